// round 2
// baseline (speedup 1.0000x reference)
#include <cuda_runtime.h>
#include <math.h>

// ---------------- problem constants ----------------
constexpr int NBAG   = 512;
constexpr int MSENT  = 8;
constexpr int TSTEPS = 64;
constexpr int IND    = 360;
constexpr int HID    = 230;
constexpr int OUTD   = 53;
constexpr int ENT    = 8;

constexpr int BB  = NBAG * MSENT;   // 4096 sequences
constexpr int H3  = 3 * HID;        // 690
constexpr int H2  = 2 * HID;        // 460
constexpr int NIH = 2 * H3;         // 1380 (fwd + rev input-gate columns)

// ---------------- device scratch (allowed: __device__ globals) ----------------
__device__ float g_Wt_ih[(size_t)IND * NIH];          // (K=360, N=1380) transposed W_ih f|r
__device__ float g_bias_ih[NIH];
__device__ float g_Wt_hh[(size_t)2 * HID * H3];       // per-dir (K=230, N=690)
__device__ float g_bias_hh[2 * H3];
__device__ float g_XG[(size_t)TSTEPS * BB * NIH];     // precomputed x@W_ih^T + b (1.45 GB)
__device__ float g_G[(size_t)2 * BB * H3];            // per-step h@W_hh^T + b_hh
__device__ float g_Hcur[(size_t)2 * BB * HID];        // current hidden, both dirs
__device__ float g_OUT[(size_t)TSTEPS * BB * H2];     // concat [hf|hr] (t,b,460)
__device__ float g_Uw[(size_t)TSTEPS * BB * H2];      // word attn pre-tanh
__device__ float g_score[TSTEPS * BB];
__device__ float g_alpha[TSTEPS * BB];
__device__ float g_wv[(size_t)BB * H2];               // word vectors
__device__ float g_U2[(size_t)BB * H2];               // sent attn pre-tanh
__device__ float g_score2[BB];

// ---------------- helpers ----------------
__device__ __forceinline__ float block_reduce_sum(float v) {
    __shared__ float s[32];
    int lane = threadIdx.x & 31, wid = threadIdx.x >> 5;
    #pragma unroll
    for (int o = 16; o; o >>= 1) v += __shfl_xor_sync(0xffffffffu, v, o);
    if (lane == 0) s[wid] = v;
    __syncthreads();
    int nw = (blockDim.x + 31) >> 5;
    v = (threadIdx.x < nw) ? s[threadIdx.x] : 0.f;
    if (wid == 0) {
        #pragma unroll
        for (int o = 16; o; o >>= 1) v += __shfl_xor_sync(0xffffffffu, v, o);
    }
    return v;  // valid on thread 0
}

__global__ void k_zero(float* p, long long n) {
    long long i = (long long)blockIdx.x * blockDim.x + threadIdx.x;
    if (i < n) p[i] = 0.f;
}

// ---------------- weight prep (transposes + bias concat) ----------------
__global__ void k_prep_ih(const float* __restrict__ Wf, const float* __restrict__ Wr,
                          const float* __restrict__ bf, const float* __restrict__ br) {
    int idx = blockIdx.x * 256 + threadIdx.x;
    if (idx < IND * NIH) {
        int k = idx / NIH, n = idx % NIH;
        g_Wt_ih[idx] = (n < H3) ? Wf[(size_t)n * IND + k] : Wr[(size_t)(n - H3) * IND + k];
    }
    if (idx < NIH) g_bias_ih[idx] = (idx < H3) ? bf[idx] : br[idx - H3];
}

__global__ void k_prep_hh(const float* __restrict__ Wf, const float* __restrict__ Wr,
                          const float* __restrict__ bf, const float* __restrict__ br) {
    int idx = blockIdx.x * 256 + threadIdx.x;
    if (idx < 2 * HID * H3) {
        int d = idx / (HID * H3);
        int r = idx % (HID * H3);
        int k = r / H3, n = r % H3;
        const float* W = d ? Wr : Wf;
        g_Wt_hh[idx] = W[(size_t)n * HID + k];
    }
    if (idx < 2 * H3) g_bias_hh[idx] = (idx < H3) ? bf[idx] : br[idx - H3];
}

// ---------------- tiled SGEMM: C = A(MxK) * B(KxN) + bias ----------------
// 128x128 tile, BK=8, 8x8 per thread, 256 threads. blockIdx.z batches via strides.
__global__ void __launch_bounds__(256, 2)
sgemm128(const float* __restrict__ A, const float* __restrict__ Bm,
         const float* __restrict__ bias, float* __restrict__ C,
         int M, int N, int K, int lda, int ldb, int ldc,
         long long sA, long long sB, long long sBias, long long sC)
{
    A    += (long long)blockIdx.z * sA;
    Bm   += (long long)blockIdx.z * sB;
    bias += (long long)blockIdx.z * sBias;
    C    += (long long)blockIdx.z * sC;

    __shared__ float As[8][132];
    __shared__ float Bs[8][128];
    int tid = threadIdx.x;
    int tx = tid & 15, ty = tid >> 4;
    int m0 = blockIdx.y * 128, n0 = blockIdx.x * 128;

    float acc[8][8];
    #pragma unroll
    for (int i = 0; i < 8; i++)
        #pragma unroll
        for (int j = 0; j < 8; j++) acc[i][j] = 0.f;

    for (int k0 = 0; k0 < K; k0 += 8) {
        #pragma unroll
        for (int l = 0; l < 4; l++) {
            int idx = tid + l * 256;
            int row = idx >> 3, col = idx & 7;
            int gm = m0 + row, gk = k0 + col;
            float v = (gm < M && gk < K) ? A[(size_t)gm * lda + gk] : 0.f;
            As[col][row] = v;
        }
        #pragma unroll
        for (int l = 0; l < 4; l++) {
            int idx = tid + l * 256;
            int row = idx >> 7, col = idx & 127;
            int gk = k0 + row, gn = n0 + col;
            float v = (gk < K && gn < N) ? Bm[(size_t)gk * ldb + gn] : 0.f;
            Bs[row][col] = v;
        }
        __syncthreads();
        #pragma unroll
        for (int kk = 0; kk < 8; kk++) {
            float a[8], b[8];
            *(float4*)&a[0] = *(const float4*)&As[kk][ty * 8];
            *(float4*)&a[4] = *(const float4*)&As[kk][ty * 8 + 4];
            *(float4*)&b[0] = *(const float4*)&Bs[kk][tx * 8];
            *(float4*)&b[4] = *(const float4*)&Bs[kk][tx * 8 + 4];
            #pragma unroll
            for (int i = 0; i < 8; i++)
                #pragma unroll
                for (int j = 0; j < 8; j++) acc[i][j] += a[i] * b[j];
        }
        __syncthreads();
    }

    #pragma unroll
    for (int i = 0; i < 8; i++) {
        int gm = m0 + ty * 8 + i;
        if (gm >= M) continue;
        #pragma unroll
        for (int j = 0; j < 8; j++) {
            int gn = n0 + tx * 8 + j;
            if (gn < N) C[(size_t)gm * ldc + gn] = acc[i][j] + bias[gn];
        }
    }
}

// Same GEMM but A is gathered from bag: row m=(t*BB+b) -> bag[b][t][k]
__global__ void __launch_bounds__(256, 2)
sgemm_bag(const float* __restrict__ bag, const float* __restrict__ Bm,
          const float* __restrict__ bias, float* __restrict__ C,
          int M, int N, int K, int ldb, int ldc)
{
    __shared__ float As[8][132];
    __shared__ float Bs[8][128];
    int tid = threadIdx.x;
    int tx = tid & 15, ty = tid >> 4;
    int m0 = blockIdx.y * 128, n0 = blockIdx.x * 128;

    float acc[8][8];
    #pragma unroll
    for (int i = 0; i < 8; i++)
        #pragma unroll
        for (int j = 0; j < 8; j++) acc[i][j] = 0.f;

    for (int k0 = 0; k0 < K; k0 += 8) {
        #pragma unroll
        for (int l = 0; l < 4; l++) {
            int idx = tid + l * 256;
            int row = idx >> 3, col = idx & 7;
            int gm = m0 + row, gk = k0 + col;
            float v = 0.f;
            if (gk < K) {
                int t = gm >> 12;           // / BB (4096)
                int b = gm & (BB - 1);
                v = bag[((size_t)b * TSTEPS + t) * IND + gk];
            }
            As[col][row] = v;
        }
        #pragma unroll
        for (int l = 0; l < 4; l++) {
            int idx = tid + l * 256;
            int row = idx >> 7, col = idx & 127;
            int gk = k0 + row, gn = n0 + col;
            float v = (gk < K && gn < N) ? Bm[(size_t)gk * ldb + gn] : 0.f;
            Bs[row][col] = v;
        }
        __syncthreads();
        #pragma unroll
        for (int kk = 0; kk < 8; kk++) {
            float a[8], b[8];
            *(float4*)&a[0] = *(const float4*)&As[kk][ty * 8];
            *(float4*)&a[4] = *(const float4*)&As[kk][ty * 8 + 4];
            *(float4*)&b[0] = *(const float4*)&Bs[kk][tx * 8];
            *(float4*)&b[4] = *(const float4*)&Bs[kk][tx * 8 + 4];
            #pragma unroll
            for (int i = 0; i < 8; i++)
                #pragma unroll
                for (int j = 0; j < 8; j++) acc[i][j] += a[i] * b[j];
        }
        __syncthreads();
    }

    #pragma unroll
    for (int i = 0; i < 8; i++) {
        int gm = m0 + ty * 8 + i;
        if (gm >= M) continue;
        #pragma unroll
        for (int j = 0; j < 8; j++) {
            int gn = n0 + tx * 8 + j;
            if (gn < N) C[(size_t)gm * ldc + gn] = acc[i][j] + bias[gn];
        }
    }
}

// ---------------- GRU gate pointwise (one step, both directions) ----------------
__global__ void k_gru_gate(int step) {
    int idx = blockIdx.x * 256 + threadIdx.x;
    if (idx >= 2 * BB * HID) return;
    int d = idx / (BB * HID);
    int r = idx % (BB * HID);
    int b = r / HID, k = r % HID;
    int t_eff = d ? (TSTEPS - 1 - step) : step;

    const float* xg = g_XG + ((size_t)t_eff * BB + b) * NIH + d * H3;
    const float* g  = g_G + ((size_t)d * BB + b) * H3;
    float hprev = g_Hcur[idx];

    float rr = 1.f / (1.f + expf(-(xg[k] + g[k])));
    float zz = 1.f / (1.f + expf(-(xg[HID + k] + g[HID + k])));
    float nn = tanhf(xg[2 * HID + k] + rr * g[2 * HID + k]);
    float h2 = (1.f - zz) * nn + zz * hprev;

    g_Hcur[idx] = h2;
    g_OUT[((size_t)t_eff * BB + b) * H2 + (size_t)d * HID + k] = h2;
}

// ---------------- score = tanh(U) . proj  (one block per row) ----------------
__global__ void k_score(const float* __restrict__ U, const float* __restrict__ proj,
                        float* __restrict__ out, int Nn) {
    long long m = blockIdx.x;
    const float* row = U + m * Nn;
    float acc = 0.f;
    for (int n = threadIdx.x; n < Nn; n += blockDim.x)
        acc += tanhf(row[n]) * proj[n];
    acc = block_reduce_sum(acc);
    if (threadIdx.x == 0) out[m] = acc;
}

// ---------------- softmax over t (axis 0), per sequence b ----------------
__global__ void k_softmax_t(const float* __restrict__ score, float* __restrict__ alpha) {
    int b = blockIdx.x;
    int t = threadIdx.x;  // 64 threads
    __shared__ float sh[64];
    float v = score[t * BB + b];
    sh[t] = v; __syncthreads();
    #pragma unroll
    for (int o = 32; o; o >>= 1) { if (t < o) sh[t] = fmaxf(sh[t], sh[t + o]); __syncthreads(); }
    float mx = sh[0]; __syncthreads();
    float e = expf(v - mx);
    sh[t] = e; __syncthreads();
    #pragma unroll
    for (int o = 32; o; o >>= 1) { if (t < o) sh[t] += sh[t + o]; __syncthreads(); }
    alpha[t * BB + b] = e / sh[0];
}

// ---------------- word_vec[b,h] = sum_t alpha[t,b] * OUT[t,b,h] ----------------
__global__ void k_word_vec(const float* __restrict__ alpha) {
    int b = blockIdx.x;
    __shared__ float a[TSTEPS];
    if (threadIdx.x < TSTEPS) a[threadIdx.x] = alpha[threadIdx.x * BB + b];
    __syncthreads();
    for (int h = threadIdx.x; h < H2; h += blockDim.x) {
        float acc = 0.f;
        #pragma unroll 8
        for (int t = 0; t < TSTEPS; t++)
            acc += a[t] * g_OUT[((size_t)t * BB + b) * H2 + h];
        g_wv[(size_t)b * H2 + h] = acc;
    }
}

// ---------------- sentence softmax + weighted sum + FC + scatter ----------------
__global__ void k_sent(const float* __restrict__ fcW, const float* __restrict__ fcb,
                       const int* __restrict__ pairs, float* __restrict__ out) {
    int nb = blockIdx.x;
    __shared__ float beta[MSENT];
    __shared__ float sv[H2];
    if (threadIdx.x == 0) {
        float v[MSENT];
        float mx = -1e30f;
        #pragma unroll
        for (int s = 0; s < MSENT; s++) { v[s] = g_score2[nb * MSENT + s]; mx = fmaxf(mx, v[s]); }
        float sum = 0.f;
        #pragma unroll
        for (int s = 0; s < MSENT; s++) { v[s] = expf(v[s] - mx); sum += v[s]; }
        #pragma unroll
        for (int s = 0; s < MSENT; s++) beta[s] = v[s] / sum;
    }
    __syncthreads();
    for (int h = threadIdx.x; h < H2; h += blockDim.x) {
        float acc = 0.f;
        #pragma unroll
        for (int s = 0; s < MSENT; s++)
            acc += beta[s] * g_wv[((size_t)(nb * MSENT + s)) * H2 + h];
        sv[h] = acc;
    }
    __syncthreads();
    const int* p = pairs + nb * 3;
    int base = ((p[0] * ENT + p[1]) * ENT + p[2]) * OUTD;
    for (int o = threadIdx.x; o < OUTD; o += blockDim.x) {
        float acc = fcb[o];
        for (int h = 0; h < H2; h++) acc += sv[h] * fcW[(size_t)o * H2 + h];
        out[base + o] = acc;
    }
}

// ---------------- launcher ----------------
extern "C" void kernel_launch(void* const* d_in, const int* in_sizes, int n_in,
                              void* d_out, int out_size) {
    const float* bag       = (const float*)d_in[0];
    const float* W_ih_f    = (const float*)d_in[1];
    const float* W_hh_f    = (const float*)d_in[2];
    const float* b_ih_f    = (const float*)d_in[3];
    const float* b_hh_f    = (const float*)d_in[4];
    const float* W_ih_r    = (const float*)d_in[5];
    const float* W_hh_r    = (const float*)d_in[6];
    const float* b_ih_r    = (const float*)d_in[7];
    const float* b_hh_r    = (const float*)d_in[8];
    const float* W_word    = (const float*)d_in[9];
    const float* b_word    = (const float*)d_in[10];
    const float* proj_word = (const float*)d_in[11];
    const float* W_sent    = (const float*)d_in[12];
    const float* b_sent    = (const float*)d_in[13];
    const float* proj_sent = (const float*)d_in[14];
    const float* fc_W      = (const float*)d_in[15];
    const float* fc_b      = (const float*)d_in[16];
    const int*   pairs     = (const int*)d_in[17];
    float* out = (float*)d_out;

    void *pWt_ih, *pBias_ih, *pWt_hh, *pBias_hh, *pXG, *pG, *pHcur, *pOUT, *pUw,
         *pScore, *pAlpha, *pWv, *pU2, *pScore2;
    cudaGetSymbolAddress(&pWt_ih, g_Wt_ih);
    cudaGetSymbolAddress(&pBias_ih, g_bias_ih);
    cudaGetSymbolAddress(&pWt_hh, g_Wt_hh);
    cudaGetSymbolAddress(&pBias_hh, g_bias_hh);
    cudaGetSymbolAddress(&pXG, g_XG);
    cudaGetSymbolAddress(&pG, g_G);
    cudaGetSymbolAddress(&pHcur, g_Hcur);
    cudaGetSymbolAddress(&pOUT, g_OUT);
    cudaGetSymbolAddress(&pUw, g_Uw);
    cudaGetSymbolAddress(&pScore, g_score);
    cudaGetSymbolAddress(&pAlpha, g_alpha);
    cudaGetSymbolAddress(&pWv, g_wv);
    cudaGetSymbolAddress(&pU2, g_U2);
    cudaGetSymbolAddress(&pScore2, g_score2);

    // 1. weight prep + zeroing
    k_prep_ih<<<(IND * NIH + 255) / 256, 256>>>(W_ih_f, W_ih_r, b_ih_f, b_ih_r);
    k_prep_hh<<<(2 * HID * H3 + 255) / 256, 256>>>(W_hh_f, W_hh_r, b_hh_f, b_hh_r);
    k_zero<<<(2 * BB * HID + 255) / 256, 256>>>((float*)pHcur, (long long)2 * BB * HID);
    k_zero<<<(out_size + 255) / 256, 256>>>(out, (long long)out_size);

    // 2. input projection for both directions: XG = x @ [W_ih_f|W_ih_r]^T + b
    {
        dim3 g((NIH + 127) / 128, (TSTEPS * BB) / 128, 1);
        sgemm_bag<<<g, 256>>>(bag, (const float*)pWt_ih, (const float*)pBias_ih,
                              (float*)pXG, TSTEPS * BB, NIH, IND, NIH, NIH);
    }

    // 3. GRU recurrence: 64 steps, both directions batched via blockIdx.z
    {
        dim3 grec((H3 + 127) / 128, BB / 128, 2);
        for (int s = 0; s < TSTEPS; s++) {
            sgemm128<<<grec, 256>>>((const float*)pHcur, (const float*)pWt_hh,
                                    (const float*)pBias_hh, (float*)pG,
                                    BB, H3, HID, HID, H3, H3,
                                    (long long)BB * HID, (long long)HID * H3,
                                    (long long)H3, (long long)BB * H3);
            k_gru_gate<<<(2 * BB * HID + 255) / 256, 256>>>(s);
        }
    }

    // 4. word attention
    {
        dim3 g((H2 + 127) / 128, (TSTEPS * BB) / 128, 1);
        sgemm128<<<g, 256>>>((const float*)pOUT, W_word, b_word, (float*)pUw,
                             TSTEPS * BB, H2, H2, H2, H2, H2, 0, 0, 0, 0);
    }
    k_score<<<TSTEPS * BB, 128>>>((const float*)pUw, proj_word, (float*)pScore, H2);
    k_softmax_t<<<BB, 64>>>((const float*)pScore, (float*)pAlpha);
    k_word_vec<<<BB, 256>>>((const float*)pAlpha);

    // 5. sentence attention + FC + scatter
    {
        dim3 g((H2 + 127) / 128, BB / 128, 1);
        sgemm128<<<g, 256>>>((const float*)pWv, W_sent, b_sent, (float*)pU2,
                             BB, H2, H2, H2, H2, H2, 0, 0, 0, 0);
    }
    k_score<<<BB, 128>>>((const float*)pU2, proj_sent, (float*)pScore2, H2);
    k_sent<<<NBAG, 256>>>(fc_W, fc_b, pairs, out);
}

// round 4
// speedup vs baseline: 2.0197x; 2.0197x over previous
#include <cuda_runtime.h>
#include <cuda_bf16.h>
#include <math.h>
#include <stdint.h>

// ---------------- problem constants ----------------
constexpr int NBAG   = 512;
constexpr int MSENT  = 8;
constexpr int TSTEPS = 64;
constexpr int IND    = 360;
constexpr int HID    = 230;
constexpr int OUTD   = 53;
constexpr int ENT    = 8;

constexpr int BB  = NBAG * MSENT;   // 4096 sequences
constexpr int H3  = 3 * HID;        // 690
constexpr int H2  = 2 * HID;        // 460
constexpr int NIH = 2 * H3;         // 1380
constexpr long long MM = (long long)TSTEPS * BB;  // 262144 rows

// padded dims (K multiple of 32, N multiple of 128)
constexpr int KPAD_IN = 384;   // 360
constexpr int NPAD_IH = 1408;  // 1380
constexpr int KPAD_H  = 256;   // 230
constexpr int NPAD_HH = 768;   // 690
constexpr int KPAD_W  = 512;   // 460
constexpr int NPAD_W  = 512;   // 460

// ---------------- device scratch ----------------
__device__ float g_bias_ih[NIH];
__device__ float g_bias_hh[2 * H3];
__device__ float g_XG[(size_t)MM * NIH];
__device__ float g_G[(size_t)2 * BB * H3];
__device__ float g_Hcur[(size_t)2 * BB * HID];
__device__ float g_OUT[(size_t)MM * H2];
__device__ float g_Uw[(size_t)MM * H2];
__device__ float g_score[TSTEPS * BB];
__device__ float g_alpha[TSTEPS * BB];
__device__ float g_wv[(size_t)BB * H2];
__device__ float g_U2[(size_t)BB * H2];
__device__ float g_score2[BB];

// bf16 hi/lo split operands (static zero-init covers pads; pads never written)
__device__ __nv_bfloat16 g_bagH[(size_t)MM * KPAD_IN];
__device__ __nv_bfloat16 g_bagL[(size_t)MM * KPAD_IN];
__device__ __nv_bfloat16 g_WihH[(size_t)NPAD_IH * KPAD_IN];
__device__ __nv_bfloat16 g_WihL[(size_t)NPAD_IH * KPAD_IN];
__device__ __nv_bfloat16 g_WhhH[(size_t)2 * NPAD_HH * KPAD_H];
__device__ __nv_bfloat16 g_WhhL[(size_t)2 * NPAD_HH * KPAD_H];
__device__ __nv_bfloat16 g_WwordH[(size_t)NPAD_W * KPAD_W];
__device__ __nv_bfloat16 g_WwordL[(size_t)NPAD_W * KPAD_W];
__device__ __nv_bfloat16 g_OUTH[(size_t)MM * KPAD_W];
__device__ __nv_bfloat16 g_OUTL[(size_t)MM * KPAD_W];
__device__ __nv_bfloat16 g_hH[(size_t)2 * BB * KPAD_H];
__device__ __nv_bfloat16 g_hL[(size_t)2 * BB * KPAD_H];

// ---------------- helpers ----------------
__device__ __forceinline__ uint32_t smem_u32(const void* p) {
    uint32_t a;
    asm("{ .reg .u64 t; cvta.to.shared.u64 t, %1; cvt.u32.u64 %0, t; }" : "=r"(a) : "l"(p));
    return a;
}

__device__ __forceinline__ void ldm_x4(uint32_t* r, uint32_t addr) {
    asm volatile("ldmatrix.sync.aligned.m8n8.x4.shared.b16 {%0,%1,%2,%3}, [%4];"
                 : "=r"(r[0]), "=r"(r[1]), "=r"(r[2]), "=r"(r[3]) : "r"(addr));
}

__device__ __forceinline__ void mma16816(float* d, const uint32_t* a, const uint32_t* b) {
    asm volatile("mma.sync.aligned.m16n8k16.row.col.f32.bf16.bf16.f32 "
                 "{%0,%1,%2,%3}, {%4,%5,%6,%7}, {%8,%9}, {%0,%1,%2,%3};"
                 : "+f"(d[0]), "+f"(d[1]), "+f"(d[2]), "+f"(d[3])
                 : "r"(a[0]), "r"(a[1]), "r"(a[2]), "r"(a[3]), "r"(b[0]), "r"(b[1]));
}

// ---------------- HMMA bf16-split GEMM ----------------
// C[M,N] = (Ah+Al)[m,k] @ (Bh+Bl)[n,k]^T + bias[n]  (Al*Bl dropped)
// A: [Mrows, Kpad] bf16, B: [Npad, Kpad] bf16 (both K-contiguous).
// 512 thr, 128x128 tile, warp grid 4x4 (warp tile 32x32), BK=32.
constexpr int TPAD = 80;                     // smem bytes per 64B row (conflict-free ldmatrix)
constexpr int TILE_SM = 128 * TPAD;          // 10240 B per tile

__global__ void __launch_bounds__(512)
gemm_bf16s(const __nv_bfloat16* __restrict__ Ah, const __nv_bfloat16* __restrict__ Al,
           const __nv_bfloat16* __restrict__ Bh, const __nv_bfloat16* __restrict__ Bl,
           const float* __restrict__ bias, float* __restrict__ C,
           int N, int ldc, int Kpad, int nit,
           long long sA, long long sB, long long sBias, long long sC)
{
    __shared__ __align__(16) unsigned char sm[4 * TILE_SM];   // Ah, Al, Bh, Bl

    int tid = threadIdx.x;
    int lane = tid & 31, wid = tid >> 5;
    int wm = wid >> 2, wn = wid & 3;

    long long z = blockIdx.z;
    Ah += z * sA;  Al += z * sA;
    Bh += z * sB;  Bl += z * sB;
    bias += z * sBias;
    C  += z * sC;

    int m0 = blockIdx.y * 128, n0 = blockIdx.x * 128;

    // loader role: tile t (0=Ah,1=Al,2=Bh,3=Bl), 128 threads per tile
    int t   = tid >> 7;
    int sub = tid & 127;
    int c4  = sub & 3;          // 16B chunk within 64B row
    int r0  = sub >> 2;         // 0..31 -> rows r0, r0+32, r0+64, r0+96
    const __nv_bfloat16* gsrc =
        (t == 0) ? Ah : (t == 1) ? Al : (t == 2) ? Bh : Bl;
    int rowbase = (t < 2) ? m0 : n0;

    uint32_t smb  = smem_u32(sm);
    uint32_t sdst = smb + t * TILE_SM + c4 * 16;

    float acc[2][4][4];
    #pragma unroll
    for (int i = 0; i < 2; i++)
        #pragma unroll
        for (int j = 0; j < 4; j++)
            #pragma unroll
            for (int q = 0; q < 4; q++) acc[i][j][q] = 0.f;

    // ldmatrix per-lane base addresses
    int arow = (lane & 7) + (((lane >> 3) & 1) << 3);
    int acolb = ((lane >> 4) & 1) * 16;
    uint32_t aBase = smb + (wm * 32 + arow) * TPAD + acolb;          // Ah tile (offset 0)
    int brow = (lane & 7) + (((lane >> 4) & 1) << 3);
    int bcolb = ((lane >> 3) & 1) * 16;
    uint32_t bBase = smb + 2 * TILE_SM + (wn * 32 + brow) * TPAD + bcolb;  // Bh tile

    uint4 pf[4];
    // prefetch chunk 0
    #pragma unroll
    for (int j = 0; j < 4; j++)
        pf[j] = *(const uint4*)(gsrc + (size_t)(rowbase + r0 + j * 32) * Kpad + c4 * 8);

    for (int kc = 0; kc < nit; kc++) {
        // store prefetched chunk to smem
        #pragma unroll
        for (int j = 0; j < 4; j++)
            *(uint4*)(sm + (sdst - smb) + (size_t)(r0 + j * 32) * TPAD) = pf[j];
        __syncthreads();

        if (kc + 1 < nit) {
            #pragma unroll
            for (int j = 0; j < 4; j++)
                pf[j] = *(const uint4*)(gsrc + (size_t)(rowbase + r0 + j * 32) * Kpad
                                        + (kc + 1) * 32 + c4 * 8);
        }

        #pragma unroll
        for (int s = 0; s < 2; s++) {
            uint32_t ah[2][4], al[2][4], bh[2][4], bl[2][4];
            #pragma unroll
            for (int i = 0; i < 2; i++) {
                ldm_x4(ah[i], aBase + i * 16 * TPAD + s * 32);
                ldm_x4(al[i], aBase + TILE_SM + i * 16 * TPAD + s * 32);
            }
            #pragma unroll
            for (int jj = 0; jj < 2; jj++) {
                ldm_x4(bh[jj], bBase + jj * 16 * TPAD + s * 32);
                ldm_x4(bl[jj], bBase + TILE_SM + jj * 16 * TPAD + s * 32);
            }
            // pass 1: Ah * Bh ; pass 2: Ah * Bl ; pass 3: Al * Bh
            #pragma unroll
            for (int i = 0; i < 2; i++)
                #pragma unroll
                for (int j = 0; j < 4; j++) {
                    const uint32_t* bfr = &bh[j >> 1][(j & 1) * 2];
                    mma16816(acc[i][j], ah[i], bfr);
                }
            #pragma unroll
            for (int i = 0; i < 2; i++)
                #pragma unroll
                for (int j = 0; j < 4; j++) {
                    const uint32_t* bfr = &bl[j >> 1][(j & 1) * 2];
                    mma16816(acc[i][j], ah[i], bfr);
                }
            #pragma unroll
            for (int i = 0; i < 2; i++)
                #pragma unroll
                for (int j = 0; j < 4; j++) {
                    const uint32_t* bfr = &bh[j >> 1][(j & 1) * 2];
                    mma16816(acc[i][j], al[i], bfr);
                }
        }
        __syncthreads();
    }

    // epilogue
    int qrow = lane >> 2, qcol = (lane & 3) * 2;
    #pragma unroll
    for (int i = 0; i < 2; i++) {
        #pragma unroll
        for (int j = 0; j < 4; j++) {
            int gc = n0 + wn * 32 + j * 8 + qcol;
            #pragma unroll
            for (int half = 0; half < 2; half++) {
                int gr = m0 + wm * 32 + i * 16 + qrow + half * 8;
                float v0 = acc[i][j][half * 2 + 0];
                float v1 = acc[i][j][half * 2 + 1];
                if (gc < N)     C[(size_t)gr * ldc + gc]     = v0 + bias[gc];
                if (gc + 1 < N) C[(size_t)gr * ldc + gc + 1] = v1 + bias[gc + 1];
            }
        }
    }
}

// ---------------- conversion / prep kernels ----------------
__global__ void k_zero(float* p, long long n) {
    long long i = (long long)blockIdx.x * blockDim.x + threadIdx.x;
    if (i < n) p[i] = 0.f;
}
__device__ __forceinline__ void split_bf16(float v, __nv_bfloat16* H, __nv_bfloat16* L, size_t i) {
    __nv_bfloat16 h = __float2bfloat16(v);
    H[i] = h;
    L[i] = __float2bfloat16(v - __bfloat162float(h));
}
__global__ void k_conv_bag(const float* __restrict__ bag) {
    size_t idx = (size_t)blockIdx.x * 256 + threadIdx.x;
    if (idx >= (size_t)MM * IND) return;
    int k = (int)(idx % IND);
    size_t m = idx / IND;
    int tt = (int)(m >> 12), b = (int)(m & 4095);
    float v = bag[((size_t)b * TSTEPS + tt) * IND + k];
    split_bf16(v, g_bagH, g_bagL, m * KPAD_IN + k);
}
__global__ void k_conv_wih(const float* __restrict__ Wf, const float* __restrict__ Wr) {
    int idx = blockIdx.x * 256 + threadIdx.x;
    if (idx >= NIH * IND) return;
    int n = idx / IND, k = idx % IND;
    float v = (n < H3) ? Wf[(size_t)n * IND + k] : Wr[(size_t)(n - H3) * IND + k];
    split_bf16(v, g_WihH, g_WihL, (size_t)n * KPAD_IN + k);
}
__global__ void k_conv_whh(const float* __restrict__ Wf, const float* __restrict__ Wr) {
    int idx = blockIdx.x * 256 + threadIdx.x;
    if (idx >= 2 * H3 * HID) return;
    int d = idx / (H3 * HID);
    int r = idx % (H3 * HID);
    int n = r / HID, k = r % HID;
    const float* W = d ? Wr : Wf;
    float v = W[(size_t)n * HID + k];
    split_bf16(v, g_WhhH, g_WhhL, ((size_t)d * NPAD_HH + n) * KPAD_H + k);
}
__global__ void k_conv_wword(const float* __restrict__ Ww) {
    int idx = blockIdx.x * 256 + threadIdx.x;
    if (idx >= H2 * H2) return;
    int n = idx / H2, k = idx % H2;
    float v = Ww[(size_t)k * H2 + n];  // transpose: B[n,k] = W[k,n]
    split_bf16(v, g_WwordH, g_WwordL, (size_t)n * KPAD_W + k);
}
__global__ void k_bias(const float* bf, const float* br, const float* hf, const float* hr) {
    int i = blockIdx.x * 256 + threadIdx.x;
    if (i < NIH) g_bias_ih[i] = (i < H3) ? bf[i] : br[i - H3];
    if (i < 2 * H3) g_bias_hh[i] = (i < H3) ? hf[i] : hr[i - H3];
}

// ---------------- GRU gate pointwise ----------------
__global__ void k_gru_gate(int step) {
    int idx = blockIdx.x * 256 + threadIdx.x;
    if (idx >= 2 * BB * HID) return;
    int d = idx / (BB * HID);
    int r = idx % (BB * HID);
    int b = r / HID, k = r % HID;
    int t_eff = d ? (TSTEPS - 1 - step) : step;

    const float* xg = g_XG + ((size_t)t_eff * BB + b) * NIH + d * H3;
    const float* g  = g_G + ((size_t)d * BB + b) * H3;
    float hprev = g_Hcur[idx];

    float rr = 1.f / (1.f + expf(-(xg[k] + g[k])));
    float zz = 1.f / (1.f + expf(-(xg[HID + k] + g[HID + k])));
    float nn = tanhf(xg[2 * HID + k] + rr * g[2 * HID + k]);
    float h2 = (1.f - zz) * nn + zz * hprev;

    g_Hcur[idx] = h2;
    size_t orow = ((size_t)t_eff * BB + b);
    g_OUT[orow * H2 + (size_t)d * HID + k] = h2;
    split_bf16(h2, g_OUTH, g_OUTL, orow * KPAD_W + (size_t)d * HID + k);
    split_bf16(h2, g_hH, g_hL, ((size_t)d * BB + b) * KPAD_H + k);
}

// ---------------- small fp32 SGEMM (sentence attn only) ----------------
__global__ void __launch_bounds__(256, 2)
sgemm128(const float* __restrict__ A, const float* __restrict__ Bm,
         const float* __restrict__ bias, float* __restrict__ C,
         int M, int N, int K, int lda, int ldb, int ldc)
{
    __shared__ float As[8][132];
    __shared__ float Bs[8][128];
    int tid = threadIdx.x;
    int tx = tid & 15, ty = tid >> 4;
    int m0 = blockIdx.y * 128, n0 = blockIdx.x * 128;
    float acc[8][8];
    #pragma unroll
    for (int i = 0; i < 8; i++)
        #pragma unroll
        for (int j = 0; j < 8; j++) acc[i][j] = 0.f;
    for (int k0 = 0; k0 < K; k0 += 8) {
        #pragma unroll
        for (int l = 0; l < 4; l++) {
            int idx = tid + l * 256, row = idx >> 3, col = idx & 7;
            int gm = m0 + row, gk = k0 + col;
            As[col][row] = (gm < M && gk < K) ? A[(size_t)gm * lda + gk] : 0.f;
        }
        #pragma unroll
        for (int l = 0; l < 4; l++) {
            int idx = tid + l * 256, row = idx >> 7, col = idx & 127;
            int gk = k0 + row, gn = n0 + col;
            Bs[row][col] = (gk < K && gn < N) ? Bm[(size_t)gk * ldb + gn] : 0.f;
        }
        __syncthreads();
        #pragma unroll
        for (int kk = 0; kk < 8; kk++) {
            float a[8], b[8];
            *(float4*)&a[0] = *(const float4*)&As[kk][ty * 8];
            *(float4*)&a[4] = *(const float4*)&As[kk][ty * 8 + 4];
            *(float4*)&b[0] = *(const float4*)&Bs[kk][tx * 8];
            *(float4*)&b[4] = *(const float4*)&Bs[kk][tx * 8 + 4];
            #pragma unroll
            for (int i = 0; i < 8; i++)
                #pragma unroll
                for (int j = 0; j < 8; j++) acc[i][j] += a[i] * b[j];
        }
        __syncthreads();
    }
    #pragma unroll
    for (int i = 0; i < 8; i++) {
        int gm = m0 + ty * 8 + i;
        if (gm >= M) continue;
        #pragma unroll
        for (int j = 0; j < 8; j++) {
            int gn = n0 + tx * 8 + j;
            if (gn < N) C[(size_t)gm * ldc + gn] = acc[i][j] + bias[gn];
        }
    }
}

// ---------------- attention tail kernels ----------------
__device__ __forceinline__ float block_reduce_sum(float v) {
    __shared__ float s[32];
    int lane = threadIdx.x & 31, wid = threadIdx.x >> 5;
    #pragma unroll
    for (int o = 16; o; o >>= 1) v += __shfl_xor_sync(0xffffffffu, v, o);
    if (lane == 0) s[wid] = v;
    __syncthreads();
    int nw = (blockDim.x + 31) >> 5;
    v = (threadIdx.x < nw) ? s[threadIdx.x] : 0.f;
    if (wid == 0) {
        #pragma unroll
        for (int o = 16; o; o >>= 1) v += __shfl_xor_sync(0xffffffffu, v, o);
    }
    return v;
}
__global__ void k_score(const float* __restrict__ U, const float* __restrict__ proj,
                        float* __restrict__ out, int Nn) {
    long long m = blockIdx.x;
    const float* row = U + m * Nn;
    float acc = 0.f;
    for (int n = threadIdx.x; n < Nn; n += blockDim.x)
        acc += tanhf(row[n]) * proj[n];
    acc = block_reduce_sum(acc);
    if (threadIdx.x == 0) out[m] = acc;
}
__global__ void k_softmax_t(const float* __restrict__ score, float* __restrict__ alpha) {
    int b = blockIdx.x, t = threadIdx.x;
    __shared__ float sh[64];
    float v = score[t * BB + b];
    sh[t] = v; __syncthreads();
    #pragma unroll
    for (int o = 32; o; o >>= 1) { if (t < o) sh[t] = fmaxf(sh[t], sh[t + o]); __syncthreads(); }
    float mx = sh[0]; __syncthreads();
    float e = expf(v - mx);
    sh[t] = e; __syncthreads();
    #pragma unroll
    for (int o = 32; o; o >>= 1) { if (t < o) sh[t] += sh[t + o]; __syncthreads(); }
    alpha[t * BB + b] = e / sh[0];
}
__global__ void k_word_vec(const float* __restrict__ alpha) {
    int b = blockIdx.x;
    __shared__ float a[TSTEPS];
    if (threadIdx.x < TSTEPS) a[threadIdx.x] = alpha[threadIdx.x * BB + b];
    __syncthreads();
    for (int h = threadIdx.x; h < H2; h += blockDim.x) {
        float acc = 0.f;
        #pragma unroll 8
        for (int t = 0; t < TSTEPS; t++)
            acc += a[t] * g_OUT[((size_t)t * BB + b) * H2 + h];
        g_wv[(size_t)b * H2 + h] = acc;
    }
}
__global__ void k_sent(const float* __restrict__ fcW, const float* __restrict__ fcb,
                       const int* __restrict__ pairs, float* __restrict__ out) {
    int nb = blockIdx.x;
    __shared__ float beta[MSENT];
    __shared__ float sv[H2];
    if (threadIdx.x == 0) {
        float v[MSENT], mx = -1e30f;
        #pragma unroll
        for (int s = 0; s < MSENT; s++) { v[s] = g_score2[nb * MSENT + s]; mx = fmaxf(mx, v[s]); }
        float sum = 0.f;
        #pragma unroll
        for (int s = 0; s < MSENT; s++) { v[s] = expf(v[s] - mx); sum += v[s]; }
        #pragma unroll
        for (int s = 0; s < MSENT; s++) beta[s] = v[s] / sum;
    }
    __syncthreads();
    for (int h = threadIdx.x; h < H2; h += blockDim.x) {
        float acc = 0.f;
        #pragma unroll
        for (int s = 0; s < MSENT; s++)
            acc += beta[s] * g_wv[((size_t)(nb * MSENT + s)) * H2 + h];
        sv[h] = acc;
    }
    __syncthreads();
    const int* p = pairs + nb * 3;
    int base = ((p[0] * ENT + p[1]) * ENT + p[2]) * OUTD;
    for (int o = threadIdx.x; o < OUTD; o += blockDim.x) {
        float acc = fcb[o];
        for (int h = 0; h < H2; h++) acc += sv[h] * fcW[(size_t)o * H2 + h];
        out[base + o] = acc;
    }
}

// ---------------- launcher ----------------
extern "C" void kernel_launch(void* const* d_in, const int* in_sizes, int n_in,
                              void* d_out, int out_size) {
    const float* bag       = (const float*)d_in[0];
    const float* W_ih_f    = (const float*)d_in[1];
    const float* W_hh_f    = (const float*)d_in[2];
    const float* b_ih_f    = (const float*)d_in[3];
    const float* b_hh_f    = (const float*)d_in[4];
    const float* W_ih_r    = (const float*)d_in[5];
    const float* W_hh_r    = (const float*)d_in[6];
    const float* b_ih_r    = (const float*)d_in[7];
    const float* b_hh_r    = (const float*)d_in[8];
    const float* W_word    = (const float*)d_in[9];
    const float* b_word    = (const float*)d_in[10];
    const float* proj_word = (const float*)d_in[11];
    const float* W_sent    = (const float*)d_in[12];
    const float* b_sent    = (const float*)d_in[13];
    const float* proj_sent = (const float*)d_in[14];
    const float* fc_W      = (const float*)d_in[15];
    const float* fc_b      = (const float*)d_in[16];
    const int*   pairs     = (const int*)d_in[17];
    float* out = (float*)d_out;

    #define SYMA(p, s) void* p; cudaGetSymbolAddress(&p, s)
    SYMA(pXG, g_XG);     SYMA(pG, g_G);       SYMA(pHcur, g_Hcur);
    SYMA(pOUT, g_OUT);   SYMA(pUw, g_Uw);     SYMA(pScore, g_score);
    SYMA(pAlpha, g_alpha); SYMA(pWv, g_wv);   SYMA(pU2, g_U2);
    SYMA(pScore2, g_score2);
    SYMA(pBih, g_bias_ih); SYMA(pBhh, g_bias_hh);
    SYMA(pBagH, g_bagH); SYMA(pBagL, g_bagL);
    SYMA(pWihH, g_WihH); SYMA(pWihL, g_WihL);
    SYMA(pWhhH, g_WhhH); SYMA(pWhhL, g_WhhL);
    SYMA(pWwH, g_WwordH); SYMA(pWwL, g_WwordL);
    SYMA(pOH, g_OUTH);   SYMA(pOL, g_OUTL);
    SYMA(phH, g_hH);     SYMA(phL, g_hL);
    #undef SYMA

    // 1. prep: biases, splits, zero state
    k_bias<<<(NIH + 255) / 256, 256>>>(b_ih_f, b_ih_r, b_hh_f, b_hh_r);
    k_conv_wih<<<(NIH * IND + 255) / 256, 256>>>(W_ih_f, W_ih_r);
    k_conv_whh<<<(2 * H3 * HID + 255) / 256, 256>>>(W_hh_f, W_hh_r);
    k_conv_wword<<<(H2 * H2 + 255) / 256, 256>>>(W_word);
    {
        long long n = MM * IND;
        k_conv_bag<<<(unsigned)((n + 255) / 256), 256>>>(bag);
    }
    k_zero<<<(2 * BB * HID + 255) / 256, 256>>>((float*)pHcur, (long long)2 * BB * HID);
    k_zero<<<(2 * BB * (KPAD_H / 2) + 255) / 256, 256>>>((float*)phH, (long long)2 * BB * (KPAD_H / 2));
    k_zero<<<(2 * BB * (KPAD_H / 2) + 255) / 256, 256>>>((float*)phL, (long long)2 * BB * (KPAD_H / 2));
    k_zero<<<(out_size + 255) / 256, 256>>>(out, (long long)out_size);

    // 2. input projection: XG = bag @ [W_ih_f|W_ih_r]^T + b
    {
        dim3 g(NPAD_IH / 128, (unsigned)(MM / 128), 1);
        gemm_bf16s<<<g, 512>>>(
            (const __nv_bfloat16*)pBagH, (const __nv_bfloat16*)pBagL,
            (const __nv_bfloat16*)pWihH, (const __nv_bfloat16*)pWihL,
            (const float*)pBih, (float*)pXG,
            NIH, NIH, KPAD_IN, KPAD_IN / 32, 0, 0, 0, 0);
    }

    // 3. GRU recurrence: 64 steps, G = h @ W_hh^T + b per direction
    {
        dim3 g(NPAD_HH / 128, BB / 128, 2);
        for (int s = 0; s < TSTEPS; s++) {
            gemm_bf16s<<<g, 512>>>(
                (const __nv_bfloat16*)phH, (const __nv_bfloat16*)phL,
                (const __nv_bfloat16*)pWhhH, (const __nv_bfloat16*)pWhhL,
                (const float*)pBhh, (float*)pG,
                H3, H3, KPAD_H, KPAD_H / 32,
                (long long)BB * KPAD_H, (long long)NPAD_HH * KPAD_H,
                (long long)H3, (long long)BB * H3);
            k_gru_gate<<<(2 * BB * HID + 255) / 256, 256>>>(s);
        }
    }

    // 4. word attention: Uw = OUT @ W_word + b  (W_word pre-transposed)
    {
        dim3 g(NPAD_W / 128, (unsigned)(MM / 128), 1);
        gemm_bf16s<<<g, 512>>>(
            (const __nv_bfloat16*)pOH, (const __nv_bfloat16*)pOL,
            (const __nv_bfloat16*)pWwH, (const __nv_bfloat16*)pWwL,
            b_word, (float*)pUw,
            H2, H2, KPAD_W, KPAD_W / 32, 0, 0, 0, 0);
    }
    k_score<<<TSTEPS * BB, 128>>>((const float*)pUw, proj_word, (float*)pScore, H2);
    k_softmax_t<<<BB, 64>>>((const float*)pScore, (float*)pAlpha);
    k_word_vec<<<BB, 256>>>((const float*)pAlpha);

    // 5. sentence attention + FC + scatter (small, fp32)
    {
        dim3 g((H2 + 127) / 128, BB / 128, 1);
        sgemm128<<<g, 256>>>((const float*)pWv, W_sent, b_sent, (float*)pU2,
                             BB, H2, H2, H2, H2, H2);
    }
    k_score<<<BB, 128>>>((const float*)pU2, proj_sent, (float*)pScore2, H2);
    k_sent<<<NBAG, 256>>>(fc_W, fc_b, pairs, out);
}

// round 5
// speedup vs baseline: 2.3903x; 1.1835x over previous
#include <cuda_runtime.h>
#include <cuda_bf16.h>
#include <math.h>
#include <stdint.h>

// ---------------- problem constants ----------------
constexpr int NBAG   = 512;
constexpr int MSENT  = 8;
constexpr int TSTEPS = 64;
constexpr int IND    = 360;
constexpr int HID    = 230;
constexpr int OUTD   = 53;
constexpr int ENT    = 8;

constexpr int BB  = NBAG * MSENT;   // 4096
constexpr int H3  = 3 * HID;        // 690
constexpr int H2  = 2 * HID;        // 460
constexpr int NIH = 2 * H3;         // 1380
constexpr long long MM = (long long)TSTEPS * BB;  // 262144

constexpr int KPAD_IN = 384;
constexpr int NPAD_IH = 1408;
constexpr int KPAD_H  = 256;
constexpr int NPAD_HH = 768;
constexpr int KPAD_W  = 512;
constexpr int NPAD_W  = 512;

// ---------------- device scratch ----------------
__device__ float g_bias_ih[NIH];
__device__ float g_bias_hh[2 * H3];
__device__ float g_XG[(size_t)MM * NIH];
__device__ float g_G[(size_t)2 * BB * H3];
__device__ float g_Uw[(size_t)MM * H2];
__device__ float g_score[TSTEPS * BB];
__device__ float g_alpha[TSTEPS * BB];
__device__ float g_wv[(size_t)BB * H2];
__device__ float g_U2[(size_t)BB * H2];
__device__ float g_score2[BB];

// bf16 hi/lo split operands (static zero-init covers pads; pads never written)
__device__ __nv_bfloat16 g_bagH[(size_t)MM * KPAD_IN];
__device__ __nv_bfloat16 g_bagL[(size_t)MM * KPAD_IN];
__device__ __nv_bfloat16 g_WihH[(size_t)NPAD_IH * KPAD_IN];
__device__ __nv_bfloat16 g_WihL[(size_t)NPAD_IH * KPAD_IN];
__device__ __nv_bfloat16 g_WhhH[(size_t)2 * NPAD_HH * KPAD_H];
__device__ __nv_bfloat16 g_WhhL[(size_t)2 * NPAD_HH * KPAD_H];
__device__ __nv_bfloat16 g_WwordH[(size_t)NPAD_W * KPAD_W];
__device__ __nv_bfloat16 g_WwordL[(size_t)NPAD_W * KPAD_W];
__device__ __nv_bfloat16 g_WsentH[(size_t)NPAD_W * KPAD_W];
__device__ __nv_bfloat16 g_WsentL[(size_t)NPAD_W * KPAD_W];
__device__ __nv_bfloat16 g_OUTH[(size_t)MM * KPAD_W];
__device__ __nv_bfloat16 g_OUTL[(size_t)MM * KPAD_W];
__device__ __nv_bfloat16 g_hH[(size_t)2 * BB * KPAD_H];
__device__ __nv_bfloat16 g_hL[(size_t)2 * BB * KPAD_H];
__device__ __nv_bfloat16 g_wvH[(size_t)BB * KPAD_W];
__device__ __nv_bfloat16 g_wvL[(size_t)BB * KPAD_W];

// ---------------- helpers ----------------
__device__ __forceinline__ uint32_t smem_u32(const void* p) {
    uint32_t a;
    asm("{ .reg .u64 t; cvta.to.shared.u64 t, %1; cvt.u32.u64 %0, t; }" : "=r"(a) : "l"(p));
    return a;
}
__device__ __forceinline__ void ldm_x4(uint32_t* r, uint32_t addr) {
    asm volatile("ldmatrix.sync.aligned.m8n8.x4.shared.b16 {%0,%1,%2,%3}, [%4];"
                 : "=r"(r[0]), "=r"(r[1]), "=r"(r[2]), "=r"(r[3]) : "r"(addr));
}
__device__ __forceinline__ void mma16816(float* d, const uint32_t* a, const uint32_t* b) {
    asm volatile("mma.sync.aligned.m16n8k16.row.col.f32.bf16.bf16.f32 "
                 "{%0,%1,%2,%3}, {%4,%5,%6,%7}, {%8,%9}, {%0,%1,%2,%3};"
                 : "+f"(d[0]), "+f"(d[1]), "+f"(d[2]), "+f"(d[3])
                 : "r"(a[0]), "r"(a[1]), "r"(a[2]), "r"(a[3]), "r"(b[0]), "r"(b[1]));
}

// ---------------- HMMA bf16-split GEMM (double-buffered) ----------------
// C[M,N] = (Ah+Al) @ (Bh+Bl)^T + bias  (Al*Bl dropped). K-contiguous operands.
// 512 thr, 128x128 tile, warp grid 4x4, BK=32. Dynamic smem: 2 buf x 4 tiles.
constexpr int TPAD    = 80;
constexpr int TILE_SM = 128 * TPAD;        // 10240
constexpr int BUFSET  = 4 * TILE_SM;       // 40960
constexpr int SMEM_GEMM = 2 * BUFSET;      // 81920

__global__ void __launch_bounds__(512)
gemm_bf16s(const __nv_bfloat16* __restrict__ Ah, const __nv_bfloat16* __restrict__ Al,
           const __nv_bfloat16* __restrict__ Bh, const __nv_bfloat16* __restrict__ Bl,
           const float* __restrict__ bias, float* __restrict__ C,
           int N, int ldc, int Kpad, int nit,
           long long sA, long long sB, long long sBias, long long sC)
{
    extern __shared__ __align__(16) unsigned char sm[];

    int tid = threadIdx.x;
    int lane = tid & 31, wid = tid >> 5;
    int wm = wid >> 2, wn = wid & 3;

    long long z = blockIdx.z;
    Ah += z * sA;  Al += z * sA;
    Bh += z * sB;  Bl += z * sB;
    bias += z * sBias;
    C  += z * sC;

    int m0 = blockIdx.y * 128, n0 = blockIdx.x * 128;

    // loader role: tile t (0=Ah,1=Al,2=Bh,3=Bl), 128 threads per tile
    int t   = tid >> 7;
    int sub = tid & 127;
    int c4  = sub & 3;
    int r0  = sub >> 2;
    const __nv_bfloat16* gsrc =
        (t == 0) ? Ah : (t == 1) ? Al : (t == 2) ? Bh : Bl;
    int rowbase = (t < 2) ? m0 : n0;

    uint32_t smb = smem_u32(sm);
    int sdstOff = t * TILE_SM + c4 * 16;    // within buffer

    float acc[2][4][4];
    #pragma unroll
    for (int i = 0; i < 2; i++)
        #pragma unroll
        for (int j = 0; j < 4; j++)
            #pragma unroll
            for (int q = 0; q < 4; q++) acc[i][j][q] = 0.f;

    int arow = (lane & 7) + (((lane >> 3) & 1) << 3);
    int acolb = ((lane >> 4) & 1) * 16;
    uint32_t aBase0 = smb + (wm * 32 + arow) * TPAD + acolb;
    int brow = (lane & 7) + (((lane >> 4) & 1) << 3);
    int bcolb = ((lane >> 3) & 1) * 16;
    uint32_t bBase0 = smb + 2 * TILE_SM + (wn * 32 + brow) * TPAD + bcolb;

    // preload chunk 0 -> buf0
    uint4 pf[4];
    #pragma unroll
    for (int j = 0; j < 4; j++)
        pf[j] = *(const uint4*)(gsrc + (size_t)(rowbase + r0 + j * 32) * Kpad + c4 * 8);
    #pragma unroll
    for (int j = 0; j < 4; j++)
        *(uint4*)(sm + sdstOff + (r0 + j * 32) * TPAD) = pf[j];
    __syncthreads();

    for (int kc = 0; kc < nit; kc++) {
        int cur = kc & 1;
        if (kc + 1 < nit) {
            #pragma unroll
            for (int j = 0; j < 4; j++)
                pf[j] = *(const uint4*)(gsrc + (size_t)(rowbase + r0 + j * 32) * Kpad
                                        + (kc + 1) * 32 + c4 * 8);
        }

        uint32_t aBase = aBase0 + cur * BUFSET;
        uint32_t bBase = bBase0 + cur * BUFSET;
        #pragma unroll
        for (int s = 0; s < 2; s++) {
            uint32_t ah[2][4], al[2][4], bh[2][4], bl[2][4];
            #pragma unroll
            for (int i = 0; i < 2; i++) {
                ldm_x4(ah[i], aBase + i * 16 * TPAD + s * 32);
                ldm_x4(al[i], aBase + TILE_SM + i * 16 * TPAD + s * 32);
            }
            #pragma unroll
            for (int jj = 0; jj < 2; jj++) {
                ldm_x4(bh[jj], bBase + jj * 16 * TPAD + s * 32);
                ldm_x4(bl[jj], bBase + TILE_SM + jj * 16 * TPAD + s * 32);
            }
            #pragma unroll
            for (int i = 0; i < 2; i++)
                #pragma unroll
                for (int j = 0; j < 4; j++)
                    mma16816(acc[i][j], ah[i], &bh[j >> 1][(j & 1) * 2]);
            #pragma unroll
            for (int i = 0; i < 2; i++)
                #pragma unroll
                for (int j = 0; j < 4; j++)
                    mma16816(acc[i][j], ah[i], &bl[j >> 1][(j & 1) * 2]);
            #pragma unroll
            for (int i = 0; i < 2; i++)
                #pragma unroll
                for (int j = 0; j < 4; j++)
                    mma16816(acc[i][j], al[i], &bh[j >> 1][(j & 1) * 2]);
        }

        if (kc + 1 < nit) {
            int nxt = cur ^ 1;
            #pragma unroll
            for (int j = 0; j < 4; j++)
                *(uint4*)(sm + nxt * BUFSET + sdstOff + (r0 + j * 32) * TPAD) = pf[j];
            __syncthreads();
        }
    }

    // epilogue
    int qrow = lane >> 2, qcol = (lane & 3) * 2;
    #pragma unroll
    for (int i = 0; i < 2; i++) {
        #pragma unroll
        for (int j = 0; j < 4; j++) {
            int gc = n0 + wn * 32 + j * 8 + qcol;
            #pragma unroll
            for (int half = 0; half < 2; half++) {
                int gr = m0 + wm * 32 + i * 16 + qrow + half * 8;
                float v0 = acc[i][j][half * 2 + 0];
                float v1 = acc[i][j][half * 2 + 1];
                if (gc < N)     C[(size_t)gr * ldc + gc]     = v0 + bias[gc];
                if (gc + 1 < N) C[(size_t)gr * ldc + gc + 1] = v1 + bias[gc + 1];
            }
        }
    }
}

// ---------------- conversion / prep kernels ----------------
__device__ __forceinline__ void split_bf16(float v, __nv_bfloat16* H, __nv_bfloat16* L, size_t i) {
    __nv_bfloat16 h = __float2bfloat16(v);
    H[i] = h;
    L[i] = __float2bfloat16(v - __bfloat162float(h));
}

__global__ void k_zero(float* p, long long n) {
    long long i = (long long)blockIdx.x * blockDim.x + threadIdx.x;
    if (i < n) p[i] = 0.f;
}
__global__ void k_zero_h(uint32_t* a, uint32_t* b, int nw) {
    int i = blockIdx.x * 256 + threadIdx.x;
    if (i < nw) { a[i] = 0u; b[i] = 0u; }
}

__global__ void k_conv_wih(const float* __restrict__ Wf, const float* __restrict__ Wr) {
    int idx = blockIdx.x * 256 + threadIdx.x;
    if (idx >= NIH * IND) return;
    int n = idx / IND, k = idx % IND;
    float v = (n < H3) ? Wf[(size_t)n * IND + k] : Wr[(size_t)(n - H3) * IND + k];
    split_bf16(v, g_WihH, g_WihL, (size_t)n * KPAD_IN + k);
}

// fused: whh (both dirs), wword^T, wsent^T, biases
constexpr int CW_WHH = 2 * H3 * HID;          // 317400
constexpr int CW_WW  = H2 * H2;               // 211600
constexpr int CW_TOT = CW_WHH + 2 * CW_WW + NIH + 2 * H3;
__global__ void k_conv_rest(const float* __restrict__ Whf, const float* __restrict__ Whr,
                            const float* __restrict__ Ww, const float* __restrict__ Ws,
                            const float* __restrict__ bif, const float* __restrict__ bir,
                            const float* __restrict__ bhf, const float* __restrict__ bhr) {
    int idx = blockIdx.x * 256 + threadIdx.x;
    if (idx < CW_WHH) {
        int d = idx / (H3 * HID), r = idx % (H3 * HID);
        int n = r / HID, k = r % HID;
        const float* W = d ? Whr : Whf;
        split_bf16(W[(size_t)n * HID + k], g_WhhH, g_WhhL,
                   ((size_t)d * NPAD_HH + n) * KPAD_H + k);
        return;
    }
    idx -= CW_WHH;
    if (idx < CW_WW) {
        int n = idx / H2, k = idx % H2;
        split_bf16(Ww[(size_t)k * H2 + n], g_WwordH, g_WwordL, (size_t)n * KPAD_W + k);
        return;
    }
    idx -= CW_WW;
    if (idx < CW_WW) {
        int n = idx / H2, k = idx % H2;
        split_bf16(Ws[(size_t)k * H2 + n], g_WsentH, g_WsentL, (size_t)n * KPAD_W + k);
        return;
    }
    idx -= CW_WW;
    if (idx < NIH) { g_bias_ih[idx] = (idx < H3) ? bif[idx] : bir[idx - H3]; return; }
    idx -= NIH;
    if (idx < 2 * H3) g_bias_hh[idx] = (idx < H3) ? bhf[idx] : bhr[idx - H3];
}

__global__ void k_conv_bag(const float* __restrict__ bag) {
    size_t idx = (size_t)blockIdx.x * 256 + threadIdx.x;     // over MM*180 (pairs)
    if (idx >= (size_t)MM * (IND / 2)) return;
    int j = (int)(idx % (IND / 2));
    size_t m = idx / (IND / 2);
    int tt = (int)(m >> 12), b = (int)(m & 4095);
    float2 v = *(const float2*)(bag + ((size_t)b * TSTEPS + tt) * IND + 2 * j);
    size_t o = m * KPAD_IN + 2 * j;
    __nv_bfloat16 h0 = __float2bfloat16(v.x), h1 = __float2bfloat16(v.y);
    __nv_bfloat162 hh; hh.x = h0; hh.y = h1;
    __nv_bfloat162 ll;
    ll.x = __float2bfloat16(v.x - __bfloat162float(h0));
    ll.y = __float2bfloat16(v.y - __bfloat162float(h1));
    *(__nv_bfloat162*)(g_bagH + o) = hh;
    *(__nv_bfloat162*)(g_bagL + o) = ll;
}

// ---------------- GRU gate pointwise (float2) ----------------
__global__ void k_gru_gate(int step) {
    int idx = blockIdx.x * 256 + threadIdx.x;    // over 2*BB*115
    if (idx >= 2 * BB * (HID / 2)) return;
    int d = idx / (BB * (HID / 2));
    int r = idx % (BB * (HID / 2));
    int b = r / (HID / 2), j = r % (HID / 2);
    int k = 2 * j;
    int t_eff = d ? (TSTEPS - 1 - step) : step;

    const float* xg = g_XG + ((size_t)t_eff * BB + b) * NIH + d * H3;
    const float* g  = g_G + ((size_t)d * BB + b) * H3;
    size_t hidx = ((size_t)d * BB + b) * KPAD_H + k;

    float2 xr = *(const float2*)(xg + k);
    float2 xz = *(const float2*)(xg + HID + k);
    float2 xn = *(const float2*)(xg + 2 * HID + k);
    float2 gr = *(const float2*)(g + k);
    float2 gz = *(const float2*)(g + HID + k);
    float2 gn = *(const float2*)(g + 2 * HID + k);

    __nv_bfloat162 hh = *(const __nv_bfloat162*)(g_hH + hidx);
    __nv_bfloat162 hl = *(const __nv_bfloat162*)(g_hL + hidx);
    float hp0 = __bfloat162float(hh.x) + __bfloat162float(hl.x);
    float hp1 = __bfloat162float(hh.y) + __bfloat162float(hl.y);

    float rr0 = 1.f / (1.f + __expf(-(xr.x + gr.x)));
    float rr1 = 1.f / (1.f + __expf(-(xr.y + gr.y)));
    float zz0 = 1.f / (1.f + __expf(-(xz.x + gz.x)));
    float zz1 = 1.f / (1.f + __expf(-(xz.y + gz.y)));
    float nn0 = tanhf(xn.x + rr0 * gn.x);
    float nn1 = tanhf(xn.y + rr1 * gn.y);
    float h0 = (1.f - zz0) * nn0 + zz0 * hp0;
    float h1 = (1.f - zz1) * nn1 + zz1 * hp1;

    __nv_bfloat16 b0 = __float2bfloat16(h0), b1 = __float2bfloat16(h1);
    __nv_bfloat162 oh; oh.x = b0; oh.y = b1;
    __nv_bfloat162 ol;
    ol.x = __float2bfloat16(h0 - __bfloat162float(b0));
    ol.y = __float2bfloat16(h1 - __bfloat162float(b1));

    *(__nv_bfloat162*)(g_hH + hidx) = oh;
    *(__nv_bfloat162*)(g_hL + hidx) = ol;
    size_t oo = ((size_t)t_eff * BB + b) * KPAD_W + (size_t)d * HID + k;
    *(__nv_bfloat162*)(g_OUTH + oo) = oh;
    *(__nv_bfloat162*)(g_OUTL + oo) = ol;
}

// ---------------- attention tail kernels ----------------
__device__ __forceinline__ float block_reduce_sum(float v) {
    __shared__ float s[32];
    int lane = threadIdx.x & 31, wid = threadIdx.x >> 5;
    #pragma unroll
    for (int o = 16; o; o >>= 1) v += __shfl_xor_sync(0xffffffffu, v, o);
    if (lane == 0) s[wid] = v;
    __syncthreads();
    int nw = (blockDim.x + 31) >> 5;
    v = (threadIdx.x < nw) ? s[threadIdx.x] : 0.f;
    if (wid == 0) {
        #pragma unroll
        for (int o = 16; o; o >>= 1) v += __shfl_xor_sync(0xffffffffu, v, o);
    }
    return v;
}
__global__ void k_score(const float* __restrict__ U, const float* __restrict__ proj,
                        float* __restrict__ out, int Nn) {
    long long m = blockIdx.x;
    const float* row = U + m * Nn;
    float acc = 0.f;
    for (int n = threadIdx.x; n < Nn; n += blockDim.x)
        acc += tanhf(row[n]) * proj[n];
    acc = block_reduce_sum(acc);
    if (threadIdx.x == 0) out[m] = acc;
}
__global__ void k_softmax_t(const float* __restrict__ score, float* __restrict__ alpha) {
    int b = blockIdx.x, t = threadIdx.x;
    __shared__ float sh[64];
    float v = score[t * BB + b];
    sh[t] = v; __syncthreads();
    #pragma unroll
    for (int o = 32; o; o >>= 1) { if (t < o) sh[t] = fmaxf(sh[t], sh[t + o]); __syncthreads(); }
    float mx = sh[0]; __syncthreads();
    float e = expf(v - mx);
    sh[t] = e; __syncthreads();
    #pragma unroll
    for (int o = 32; o; o >>= 1) { if (t < o) sh[t] += sh[t + o]; __syncthreads(); }
    alpha[t * BB + b] = e / sh[0];
}
__global__ void k_word_vec(const float* __restrict__ alpha) {
    int b = blockIdx.x;
    __shared__ float a[TSTEPS];
    if (threadIdx.x < TSTEPS) a[threadIdx.x] = alpha[threadIdx.x * BB + b];
    __syncthreads();
    for (int h = threadIdx.x; h < H2; h += blockDim.x) {
        float acc = 0.f;
        #pragma unroll 8
        for (int t = 0; t < TSTEPS; t++) {
            size_t o = ((size_t)t * BB + b) * KPAD_W + h;
            acc += a[t] * (__bfloat162float(g_OUTH[o]) + __bfloat162float(g_OUTL[o]));
        }
        g_wv[(size_t)b * H2 + h] = acc;
        split_bf16(acc, g_wvH, g_wvL, (size_t)b * KPAD_W + h);
    }
}
__global__ void k_sent(const float* __restrict__ fcW, const float* __restrict__ fcb,
                       const int* __restrict__ pairs, float* __restrict__ out) {
    int nb = blockIdx.x;
    __shared__ float beta[MSENT];
    __shared__ float sv[H2];
    if (threadIdx.x == 0) {
        float v[MSENT], mx = -1e30f;
        #pragma unroll
        for (int s = 0; s < MSENT; s++) { v[s] = g_score2[nb * MSENT + s]; mx = fmaxf(mx, v[s]); }
        float sum = 0.f;
        #pragma unroll
        for (int s = 0; s < MSENT; s++) { v[s] = expf(v[s] - mx); sum += v[s]; }
        #pragma unroll
        for (int s = 0; s < MSENT; s++) beta[s] = v[s] / sum;
    }
    __syncthreads();
    for (int h = threadIdx.x; h < H2; h += blockDim.x) {
        float acc = 0.f;
        #pragma unroll
        for (int s = 0; s < MSENT; s++)
            acc += beta[s] * g_wv[((size_t)(nb * MSENT + s)) * H2 + h];
        sv[h] = acc;
    }
    __syncthreads();
    const int* p = pairs + nb * 3;
    int base = ((p[0] * ENT + p[1]) * ENT + p[2]) * OUTD;
    for (int o = threadIdx.x; o < OUTD; o += blockDim.x) {
        float acc = fcb[o];
        for (int h = 0; h < H2; h++) acc += sv[h] * fcW[(size_t)o * H2 + h];
        out[base + o] = acc;
    }
}

// ---------------- launcher ----------------
extern "C" void kernel_launch(void* const* d_in, const int* in_sizes, int n_in,
                              void* d_out, int out_size) {
    const float* bag       = (const float*)d_in[0];
    const float* W_ih_f    = (const float*)d_in[1];
    const float* W_hh_f    = (const float*)d_in[2];
    const float* b_ih_f    = (const float*)d_in[3];
    const float* b_hh_f    = (const float*)d_in[4];
    const float* W_ih_r    = (const float*)d_in[5];
    const float* W_hh_r    = (const float*)d_in[6];
    const float* b_ih_r    = (const float*)d_in[7];
    const float* b_hh_r    = (const float*)d_in[8];
    const float* W_word    = (const float*)d_in[9];
    const float* b_word    = (const float*)d_in[10];
    const float* proj_word = (const float*)d_in[11];
    const float* W_sent    = (const float*)d_in[12];
    const float* b_sent    = (const float*)d_in[13];
    const float* proj_sent = (const float*)d_in[14];
    const float* fc_W      = (const float*)d_in[15];
    const float* fc_b      = (const float*)d_in[16];
    const int*   pairs     = (const int*)d_in[17];
    float* out = (float*)d_out;

    static bool attr_set = false;
    if (!attr_set) {
        cudaFuncSetAttribute(gemm_bf16s, cudaFuncAttributeMaxDynamicSharedMemorySize, SMEM_GEMM);
        attr_set = true;
    }

    #define SYMA(p, s) void* p; cudaGetSymbolAddress(&p, s)
    SYMA(pXG, g_XG);     SYMA(pG, g_G);
    SYMA(pUw, g_Uw);     SYMA(pScore, g_score);
    SYMA(pAlpha, g_alpha); SYMA(pWv, g_wv);   SYMA(pU2, g_U2);
    SYMA(pScore2, g_score2);
    SYMA(pBih, g_bias_ih); SYMA(pBhh, g_bias_hh);
    SYMA(pBagH, g_bagH); SYMA(pBagL, g_bagL);
    SYMA(pWihH, g_WihH); SYMA(pWihL, g_WihL);
    SYMA(pWhhH, g_WhhH); SYMA(pWhhL, g_WhhL);
    SYMA(pWwH, g_WwordH); SYMA(pWwL, g_WwordL);
    SYMA(pWsH, g_WsentH); SYMA(pWsL, g_WsentL);
    SYMA(pOH, g_OUTH);   SYMA(pOL, g_OUTL);
    SYMA(phH, g_hH);     SYMA(phL, g_hL);
    SYMA(pwvH, g_wvH);   SYMA(pwvL, g_wvL);
    #undef SYMA

    // ---- prep: exactly 5 launches so the big GEMM is launch #6 (ncu -s 5) ----
    k_conv_wih<<<(NIH * IND + 255) / 256, 256>>>(W_ih_f, W_ih_r);                       // 1
    k_conv_rest<<<(CW_TOT + 255) / 256, 256>>>(W_hh_f, W_hh_r, W_word, W_sent,          // 2
                                               b_ih_f, b_ih_r, b_hh_f, b_hh_r);
    {
        long long n = MM * (IND / 2);                                                   // 3
        k_conv_bag<<<(unsigned)((n + 255) / 256), 256>>>(bag);
    }
    {
        int nw = 2 * BB * KPAD_H / 2;  // bf16 words as uint32                          // 4
        k_zero_h<<<(nw + 255) / 256, 256>>>((uint32_t*)phH, (uint32_t*)phL, nw);
    }
    k_zero<<<(out_size + 255) / 256, 256>>>(out, (long long)out_size);                  // 5

    // ---- 2. input projection (launch #6 — ncu captures this) ----
    {
        dim3 g(NPAD_IH / 128, (unsigned)(MM / 128), 1);
        gemm_bf16s<<<g, 512, SMEM_GEMM>>>(
            (const __nv_bfloat16*)pBagH, (const __nv_bfloat16*)pBagL,
            (const __nv_bfloat16*)pWihH, (const __nv_bfloat16*)pWihL,
            (const float*)pBih, (float*)pXG,
            NIH, NIH, KPAD_IN, KPAD_IN / 32, 0, 0, 0, 0);
    }

    // ---- 3. GRU recurrence ----
    {
        dim3 g(NPAD_HH / 128, BB / 128, 2);
        for (int s = 0; s < TSTEPS; s++) {
            gemm_bf16s<<<g, 512, SMEM_GEMM>>>(
                (const __nv_bfloat16*)phH, (const __nv_bfloat16*)phL,
                (const __nv_bfloat16*)pWhhH, (const __nv_bfloat16*)pWhhL,
                (const float*)pBhh, (float*)pG,
                H3, H3, KPAD_H, KPAD_H / 32,
                (long long)BB * KPAD_H, (long long)NPAD_HH * KPAD_H,
                (long long)H3, (long long)BB * H3);
            k_gru_gate<<<(2 * BB * (HID / 2) + 255) / 256, 256>>>(s);
        }
    }

    // ---- 4. word attention ----
    {
        dim3 g(NPAD_W / 128, (unsigned)(MM / 128), 1);
        gemm_bf16s<<<g, 512, SMEM_GEMM>>>(
            (const __nv_bfloat16*)pOH, (const __nv_bfloat16*)pOL,
            (const __nv_bfloat16*)pWwH, (const __nv_bfloat16*)pWwL,
            b_word, (float*)pUw,
            H2, H2, KPAD_W, KPAD_W / 32, 0, 0, 0, 0);
    }
    k_score<<<TSTEPS * BB, 128>>>((const float*)pUw, proj_word, (float*)pScore, H2);
    k_softmax_t<<<BB, 64>>>((const float*)pScore, (float*)pAlpha);
    k_word_vec<<<BB, 256>>>((const float*)pAlpha);

    // ---- 5. sentence attention + FC + scatter ----
    {
        dim3 g(NPAD_W / 128, BB / 128, 1);
        gemm_bf16s<<<g, 512, SMEM_GEMM>>>(
            (const __nv_bfloat16*)pwvH, (const __nv_bfloat16*)pwvL,
            (const __nv_bfloat16*)pWsH, (const __nv_bfloat16*)pWsL,
            b_sent, (float*)pU2,
            H2, H2, KPAD_W, KPAD_W / 32, 0, 0, 0, 0);
    }
    k_score<<<BB, 128>>>((const float*)pU2, proj_sent, (float*)pScore2, H2);
    k_sent<<<NBAG, 256>>>(fc_W, fc_b, pairs, out);
}

// round 6
// speedup vs baseline: 2.4063x; 1.0067x over previous
#include <cuda_runtime.h>
#include <cuda_bf16.h>
#include <math.h>
#include <stdint.h>

// ---------------- problem constants ----------------
constexpr int NBAG   = 512;
constexpr int MSENT  = 8;
constexpr int TSTEPS = 64;
constexpr int IND    = 360;
constexpr int HID    = 230;
constexpr int OUTD   = 53;
constexpr int ENT    = 8;

constexpr int BB  = NBAG * MSENT;   // 4096
constexpr int H3  = 3 * HID;        // 690
constexpr int H2  = 2 * HID;        // 460
constexpr int NIH = 2 * H3;         // 1380
constexpr long long MM = (long long)TSTEPS * BB;  // 262144

constexpr int KPAD_IN = 384;
constexpr int NPAD_IH = 1408;
constexpr int KPAD_H  = 256;
constexpr int NPAD_HH = 768;
constexpr int KPAD_W  = 512;
constexpr int NPAD_W  = 512;

// ---------------- device scratch ----------------
__device__ float g_bias_ih[NIH];
__device__ float g_bias_hh[2 * H3];
__device__ float g_XG[(size_t)MM * NIH];
__device__ float g_G[(size_t)2 * BB * H3];
__device__ float g_score[TSTEPS * BB];
__device__ float g_alpha[TSTEPS * BB];
__device__ float g_wv[(size_t)BB * H2];
__device__ float g_score2[BB];

// bf16 hi/lo split operands (static zero-init covers pads; pads never written)
__device__ __nv_bfloat16 g_bagH[(size_t)MM * KPAD_IN];
__device__ __nv_bfloat16 g_bagL[(size_t)MM * KPAD_IN];
__device__ __nv_bfloat16 g_WihH[(size_t)NPAD_IH * KPAD_IN];
__device__ __nv_bfloat16 g_WihL[(size_t)NPAD_IH * KPAD_IN];
__device__ __nv_bfloat16 g_WhhH[(size_t)2 * NPAD_HH * KPAD_H];
__device__ __nv_bfloat16 g_WhhL[(size_t)2 * NPAD_HH * KPAD_H];
__device__ __nv_bfloat16 g_WwordH[(size_t)NPAD_W * KPAD_W];
__device__ __nv_bfloat16 g_WwordL[(size_t)NPAD_W * KPAD_W];
__device__ __nv_bfloat16 g_WsentH[(size_t)NPAD_W * KPAD_W];
__device__ __nv_bfloat16 g_WsentL[(size_t)NPAD_W * KPAD_W];
__device__ __nv_bfloat16 g_OUTH[(size_t)MM * KPAD_W];
__device__ __nv_bfloat16 g_OUTL[(size_t)MM * KPAD_W];
__device__ __nv_bfloat16 g_hH[(size_t)2 * BB * KPAD_H];
__device__ __nv_bfloat16 g_hL[(size_t)2 * BB * KPAD_H];
__device__ __nv_bfloat16 g_wvH[(size_t)BB * KPAD_W];
__device__ __nv_bfloat16 g_wvL[(size_t)BB * KPAD_W];

// ---------------- helpers ----------------
__device__ __forceinline__ uint32_t smem_u32(const void* p) {
    uint32_t a;
    asm("{ .reg .u64 t; cvta.to.shared.u64 t, %1; cvt.u32.u64 %0, t; }" : "=r"(a) : "l"(p));
    return a;
}
__device__ __forceinline__ void ldm_x4(uint32_t* r, uint32_t addr) {
    asm volatile("ldmatrix.sync.aligned.m8n8.x4.shared.b16 {%0,%1,%2,%3}, [%4];"
                 : "=r"(r[0]), "=r"(r[1]), "=r"(r[2]), "=r"(r[3]) : "r"(addr));
}
__device__ __forceinline__ void mma16816(float* d, const uint32_t* a, const uint32_t* b) {
    asm volatile("mma.sync.aligned.m16n8k16.row.col.f32.bf16.bf16.f32 "
                 "{%0,%1,%2,%3}, {%4,%5,%6,%7}, {%8,%9}, {%0,%1,%2,%3};"
                 : "+f"(d[0]), "+f"(d[1]), "+f"(d[2]), "+f"(d[3])
                 : "r"(a[0]), "r"(a[1]), "r"(a[2]), "r"(a[3]), "r"(b[0]), "r"(b[1]));
}

constexpr int TPAD    = 80;
constexpr int TILE_SM = 128 * TPAD;        // 10240
constexpr int BUFSET  = 4 * TILE_SM;       // 40960
constexpr int SMEM_GEMM = 2 * BUFSET;      // 81920

// ---------------- HMMA bf16-split GEMM (double-buffered, C-store) ----------------
__global__ void __launch_bounds__(512)
gemm_bf16s(const __nv_bfloat16* __restrict__ Ah, const __nv_bfloat16* __restrict__ Al,
           const __nv_bfloat16* __restrict__ Bh, const __nv_bfloat16* __restrict__ Bl,
           const float* __restrict__ bias, float* __restrict__ C,
           int N, int ldc, int Kpad, int nit,
           long long sA, long long sB, long long sBias, long long sC)
{
    extern __shared__ __align__(16) unsigned char sm[];

    int tid = threadIdx.x;
    int lane = tid & 31, wid = tid >> 5;
    int wm = wid >> 2, wn = wid & 3;

    long long z = blockIdx.z;
    Ah += z * sA;  Al += z * sA;
    Bh += z * sB;  Bl += z * sB;
    bias += z * sBias;
    C  += z * sC;

    int m0 = blockIdx.y * 128, n0 = blockIdx.x * 128;

    int t   = tid >> 7;
    int sub = tid & 127;
    int c4  = sub & 3;
    int r0  = sub >> 2;
    const __nv_bfloat16* gsrc =
        (t == 0) ? Ah : (t == 1) ? Al : (t == 2) ? Bh : Bl;
    int rowbase = (t < 2) ? m0 : n0;

    uint32_t smb = smem_u32(sm);
    int sdstOff = t * TILE_SM + c4 * 16;

    float acc[2][4][4];
    #pragma unroll
    for (int i = 0; i < 2; i++)
        #pragma unroll
        for (int j = 0; j < 4; j++)
            #pragma unroll
            for (int q = 0; q < 4; q++) acc[i][j][q] = 0.f;

    int arow = (lane & 7) + (((lane >> 3) & 1) << 3);
    int acolb = ((lane >> 4) & 1) * 16;
    uint32_t aBase0 = smb + (wm * 32 + arow) * TPAD + acolb;
    int brow = (lane & 7) + (((lane >> 4) & 1) << 3);
    int bcolb = ((lane >> 3) & 1) * 16;
    uint32_t bBase0 = smb + 2 * TILE_SM + (wn * 32 + brow) * TPAD + bcolb;

    uint4 pf[4];
    #pragma unroll
    for (int j = 0; j < 4; j++)
        pf[j] = *(const uint4*)(gsrc + (size_t)(rowbase + r0 + j * 32) * Kpad + c4 * 8);
    #pragma unroll
    for (int j = 0; j < 4; j++)
        *(uint4*)(sm + sdstOff + (r0 + j * 32) * TPAD) = pf[j];
    __syncthreads();

    for (int kc = 0; kc < nit; kc++) {
        int cur = kc & 1;
        if (kc + 1 < nit) {
            #pragma unroll
            for (int j = 0; j < 4; j++)
                pf[j] = *(const uint4*)(gsrc + (size_t)(rowbase + r0 + j * 32) * Kpad
                                        + (kc + 1) * 32 + c4 * 8);
        }

        uint32_t aBase = aBase0 + cur * BUFSET;
        uint32_t bBase = bBase0 + cur * BUFSET;
        #pragma unroll
        for (int s = 0; s < 2; s++) {
            uint32_t ah[2][4], al[2][4], bh[2][4], bl[2][4];
            #pragma unroll
            for (int i = 0; i < 2; i++) {
                ldm_x4(ah[i], aBase + i * 16 * TPAD + s * 32);
                ldm_x4(al[i], aBase + TILE_SM + i * 16 * TPAD + s * 32);
            }
            #pragma unroll
            for (int jj = 0; jj < 2; jj++) {
                ldm_x4(bh[jj], bBase + jj * 16 * TPAD + s * 32);
                ldm_x4(bl[jj], bBase + TILE_SM + jj * 16 * TPAD + s * 32);
            }
            #pragma unroll
            for (int i = 0; i < 2; i++)
                #pragma unroll
                for (int j = 0; j < 4; j++)
                    mma16816(acc[i][j], ah[i], &bh[j >> 1][(j & 1) * 2]);
            #pragma unroll
            for (int i = 0; i < 2; i++)
                #pragma unroll
                for (int j = 0; j < 4; j++)
                    mma16816(acc[i][j], ah[i], &bl[j >> 1][(j & 1) * 2]);
            #pragma unroll
            for (int i = 0; i < 2; i++)
                #pragma unroll
                for (int j = 0; j < 4; j++)
                    mma16816(acc[i][j], al[i], &bh[j >> 1][(j & 1) * 2]);
        }

        if (kc + 1 < nit) {
            int nxt = cur ^ 1;
            #pragma unroll
            for (int j = 0; j < 4; j++)
                *(uint4*)(sm + nxt * BUFSET + sdstOff + (r0 + j * 32) * TPAD) = pf[j];
            __syncthreads();
        }
    }

    int qrow = lane >> 2, qcol = (lane & 3) * 2;
    #pragma unroll
    for (int i = 0; i < 2; i++) {
        #pragma unroll
        for (int j = 0; j < 4; j++) {
            int gc = n0 + wn * 32 + j * 8 + qcol;
            #pragma unroll
            for (int half = 0; half < 2; half++) {
                int gr = m0 + wm * 32 + i * 16 + qrow + half * 8;
                float v0 = acc[i][j][half * 2 + 0];
                float v1 = acc[i][j][half * 2 + 1];
                if (gc < N)     C[(size_t)gr * ldc + gc]     = v0 + bias[gc];
                if (gc + 1 < N) C[(size_t)gr * ldc + gc + 1] = v1 + bias[gc + 1];
            }
        }
    }
}

// ---------------- HMMA bf16-split GEMM with fused score epilogue ----------------
// score[m] = sum_n tanh( (A@B^T)[m,n] + bias[n] ) * proj[n],  n < Nact.
// 1-D grid over M; loops nbt N-tiles inside the block (A-tile reuse, deterministic).
__global__ void __launch_bounds__(512)
gemm_score(const __nv_bfloat16* __restrict__ Ah, const __nv_bfloat16* __restrict__ Al,
           const __nv_bfloat16* __restrict__ Bh, const __nv_bfloat16* __restrict__ Bl,
           const float* __restrict__ bias, const float* __restrict__ proj,
           float* __restrict__ score, int Nact, int Kpad, int nit, int nbt)
{
    extern __shared__ __align__(16) unsigned char sm[];

    int tid = threadIdx.x;
    int lane = tid & 31, wid = tid >> 5;
    int wm = wid >> 2, wn = wid & 3;
    int m0 = blockIdx.x * 128;

    int t   = tid >> 7;
    int sub = tid & 127;
    int c4  = sub & 3;
    int r0  = sub >> 2;
    bool isA = (t < 2);
    const __nv_bfloat16* gsrcA = (t == 0) ? Ah : Al;
    const __nv_bfloat16* gsrcB = (t == 2) ? Bh : Bl;

    uint32_t smb = smem_u32(sm);
    int sdstOff = t * TILE_SM + c4 * 16;

    int arow = (lane & 7) + (((lane >> 3) & 1) << 3);
    int acolb = ((lane >> 4) & 1) * 16;
    uint32_t aBase0 = smb + (wm * 32 + arow) * TPAD + acolb;
    int brow = (lane & 7) + (((lane >> 4) & 1) << 3);
    int bcolb = ((lane >> 3) & 1) * 16;
    uint32_t bBase0 = smb + 2 * TILE_SM + (wn * 32 + brow) * TPAD + bcolb;

    int qrow = lane >> 2, qcol = (lane & 3) * 2;
    float sacc[2][2] = {{0.f, 0.f}, {0.f, 0.f}};

    for (int nb = 0; nb < nbt; nb++) {
        int n0 = nb * 128;
        const __nv_bfloat16* gsrc = isA ? gsrcA : gsrcB;
        int rowbase = isA ? m0 : n0;

        float acc[2][4][4];
        #pragma unroll
        for (int i = 0; i < 2; i++)
            #pragma unroll
            for (int j = 0; j < 4; j++)
                #pragma unroll
                for (int q = 0; q < 4; q++) acc[i][j][q] = 0.f;

        __syncthreads();   // smem reuse guard across nb iterations

        uint4 pf[4];
        #pragma unroll
        for (int j = 0; j < 4; j++)
            pf[j] = *(const uint4*)(gsrc + (size_t)(rowbase + r0 + j * 32) * Kpad + c4 * 8);
        #pragma unroll
        for (int j = 0; j < 4; j++)
            *(uint4*)(sm + sdstOff + (r0 + j * 32) * TPAD) = pf[j];
        __syncthreads();

        for (int kc = 0; kc < nit; kc++) {
            int cur = kc & 1;
            if (kc + 1 < nit) {
                #pragma unroll
                for (int j = 0; j < 4; j++)
                    pf[j] = *(const uint4*)(gsrc + (size_t)(rowbase + r0 + j * 32) * Kpad
                                            + (kc + 1) * 32 + c4 * 8);
            }
            uint32_t aBase = aBase0 + cur * BUFSET;
            uint32_t bBase = bBase0 + cur * BUFSET;
            #pragma unroll
            for (int s = 0; s < 2; s++) {
                uint32_t ah[2][4], al[2][4], bh[2][4], bl[2][4];
                #pragma unroll
                for (int i = 0; i < 2; i++) {
                    ldm_x4(ah[i], aBase + i * 16 * TPAD + s * 32);
                    ldm_x4(al[i], aBase + TILE_SM + i * 16 * TPAD + s * 32);
                }
                #pragma unroll
                for (int jj = 0; jj < 2; jj++) {
                    ldm_x4(bh[jj], bBase + jj * 16 * TPAD + s * 32);
                    ldm_x4(bl[jj], bBase + TILE_SM + jj * 16 * TPAD + s * 32);
                }
                #pragma unroll
                for (int i = 0; i < 2; i++)
                    #pragma unroll
                    for (int j = 0; j < 4; j++)
                        mma16816(acc[i][j], ah[i], &bh[j >> 1][(j & 1) * 2]);
                #pragma unroll
                for (int i = 0; i < 2; i++)
                    #pragma unroll
                    for (int j = 0; j < 4; j++)
                        mma16816(acc[i][j], ah[i], &bl[j >> 1][(j & 1) * 2]);
                #pragma unroll
                for (int i = 0; i < 2; i++)
                    #pragma unroll
                    for (int j = 0; j < 4; j++)
                        mma16816(acc[i][j], al[i], &bh[j >> 1][(j & 1) * 2]);
            }
            if (kc + 1 < nit) {
                int nxt = cur ^ 1;
                #pragma unroll
                for (int j = 0; j < 4; j++)
                    *(uint4*)(sm + nxt * BUFSET + sdstOff + (r0 + j * 32) * TPAD) = pf[j];
                __syncthreads();
            }
        }

        // accumulate score partial: tanh(u + bias) * proj
        #pragma unroll
        for (int i = 0; i < 2; i++) {
            #pragma unroll
            for (int j = 0; j < 4; j++) {
                int gc = n0 + wn * 32 + j * 8 + qcol;
                #pragma unroll
                for (int half = 0; half < 2; half++) {
                    if (gc < Nact)
                        sacc[i][half] += tanhf(acc[i][j][half * 2 + 0] + bias[gc]) * proj[gc];
                    if (gc + 1 < Nact)
                        sacc[i][half] += tanhf(acc[i][j][half * 2 + 1] + bias[gc + 1]) * proj[gc + 1];
                }
            }
        }
    }

    // reduce across the 4 lanes that share a row (qcol groups)
    #pragma unroll
    for (int i = 0; i < 2; i++)
        #pragma unroll
        for (int half = 0; half < 2; half++) {
            float v = sacc[i][half];
            v += __shfl_xor_sync(0xffffffffu, v, 1);
            v += __shfl_xor_sync(0xffffffffu, v, 2);
            sacc[i][half] = v;
        }

    __syncthreads();
    float* sred = (float*)sm;   // 128 rows x 4 wn
    if ((lane & 3) == 0) {
        #pragma unroll
        for (int i = 0; i < 2; i++)
            #pragma unroll
            for (int half = 0; half < 2; half++) {
                int rl = wm * 32 + i * 16 + half * 8 + qrow;
                sred[rl * 4 + wn] = sacc[i][half];
            }
    }
    __syncthreads();
    if (tid < 128) {
        float s = sred[tid * 4] + sred[tid * 4 + 1] + sred[tid * 4 + 2] + sred[tid * 4 + 3];
        score[m0 + tid] = s;
    }
}

// ---------------- conversion / prep kernels ----------------
__device__ __forceinline__ void split_bf16(float v, __nv_bfloat16* H, __nv_bfloat16* L, size_t i) {
    __nv_bfloat16 h = __float2bfloat16(v);
    H[i] = h;
    L[i] = __float2bfloat16(v - __bfloat162float(h));
}

__global__ void k_zero(float* p, long long n) {
    long long i = (long long)blockIdx.x * blockDim.x + threadIdx.x;
    if (i < n) p[i] = 0.f;
}
__global__ void k_zero_h(uint32_t* a, uint32_t* b, int nw) {
    int i = blockIdx.x * 256 + threadIdx.x;
    if (i < nw) { a[i] = 0u; b[i] = 0u; }
}

__global__ void k_conv_wih(const float* __restrict__ Wf, const float* __restrict__ Wr) {
    int idx = blockIdx.x * 256 + threadIdx.x;
    if (idx >= NIH * IND) return;
    int n = idx / IND, k = idx % IND;
    float v = (n < H3) ? Wf[(size_t)n * IND + k] : Wr[(size_t)(n - H3) * IND + k];
    split_bf16(v, g_WihH, g_WihL, (size_t)n * KPAD_IN + k);
}

constexpr int CW_WHH = 2 * H3 * HID;
constexpr int CW_WW  = H2 * H2;
constexpr int CW_TOT = CW_WHH + 2 * CW_WW + NIH + 2 * H3;
__global__ void k_conv_rest(const float* __restrict__ Whf, const float* __restrict__ Whr,
                            const float* __restrict__ Ww, const float* __restrict__ Ws,
                            const float* __restrict__ bif, const float* __restrict__ bir,
                            const float* __restrict__ bhf, const float* __restrict__ bhr) {
    int idx = blockIdx.x * 256 + threadIdx.x;
    if (idx < CW_WHH) {
        int d = idx / (H3 * HID), r = idx % (H3 * HID);
        int n = r / HID, k = r % HID;
        const float* W = d ? Whr : Whf;
        split_bf16(W[(size_t)n * HID + k], g_WhhH, g_WhhL,
                   ((size_t)d * NPAD_HH + n) * KPAD_H + k);
        return;
    }
    idx -= CW_WHH;
    if (idx < CW_WW) {
        int n = idx / H2, k = idx % H2;
        split_bf16(Ww[(size_t)k * H2 + n], g_WwordH, g_WwordL, (size_t)n * KPAD_W + k);
        return;
    }
    idx -= CW_WW;
    if (idx < CW_WW) {
        int n = idx / H2, k = idx % H2;
        split_bf16(Ws[(size_t)k * H2 + n], g_WsentH, g_WsentL, (size_t)n * KPAD_W + k);
        return;
    }
    idx -= CW_WW;
    if (idx < NIH) { g_bias_ih[idx] = (idx < H3) ? bif[idx] : bir[idx - H3]; return; }
    idx -= NIH;
    if (idx < 2 * H3) g_bias_hh[idx] = (idx < H3) ? bhf[idx] : bhr[idx - H3];
}

__global__ void k_conv_bag(const float* __restrict__ bag) {
    size_t idx = (size_t)blockIdx.x * 256 + threadIdx.x;
    if (idx >= (size_t)MM * (IND / 2)) return;
    int j = (int)(idx % (IND / 2));
    size_t m = idx / (IND / 2);
    int tt = (int)(m >> 12), b = (int)(m & 4095);
    float2 v = *(const float2*)(bag + ((size_t)b * TSTEPS + tt) * IND + 2 * j);
    size_t o = m * KPAD_IN + 2 * j;
    __nv_bfloat16 h0 = __float2bfloat16(v.x), h1 = __float2bfloat16(v.y);
    __nv_bfloat162 hh; hh.x = h0; hh.y = h1;
    __nv_bfloat162 ll;
    ll.x = __float2bfloat16(v.x - __bfloat162float(h0));
    ll.y = __float2bfloat16(v.y - __bfloat162float(h1));
    *(__nv_bfloat162*)(g_bagH + o) = hh;
    *(__nv_bfloat162*)(g_bagL + o) = ll;
}

// ---------------- GRU gate pointwise ----------------
__global__ void k_gru_gate(int step) {
    int idx = blockIdx.x * 256 + threadIdx.x;
    if (idx >= 2 * BB * (HID / 2)) return;
    int d = idx / (BB * (HID / 2));
    int r = idx % (BB * (HID / 2));
    int b = r / (HID / 2), j = r % (HID / 2);
    int k = 2 * j;
    int t_eff = d ? (TSTEPS - 1 - step) : step;

    const float* xg = g_XG + ((size_t)t_eff * BB + b) * NIH + d * H3;
    const float* g  = g_G + ((size_t)d * BB + b) * H3;
    size_t hidx = ((size_t)d * BB + b) * KPAD_H + k;

    float2 xr = *(const float2*)(xg + k);
    float2 xz = *(const float2*)(xg + HID + k);
    float2 xn = *(const float2*)(xg + 2 * HID + k);
    float2 gr = *(const float2*)(g + k);
    float2 gz = *(const float2*)(g + HID + k);
    float2 gn = *(const float2*)(g + 2 * HID + k);

    __nv_bfloat162 hh = *(const __nv_bfloat162*)(g_hH + hidx);
    __nv_bfloat162 hl = *(const __nv_bfloat162*)(g_hL + hidx);
    float hp0 = __bfloat162float(hh.x) + __bfloat162float(hl.x);
    float hp1 = __bfloat162float(hh.y) + __bfloat162float(hl.y);

    float rr0 = 1.f / (1.f + __expf(-(xr.x + gr.x)));
    float rr1 = 1.f / (1.f + __expf(-(xr.y + gr.y)));
    float zz0 = 1.f / (1.f + __expf(-(xz.x + gz.x)));
    float zz1 = 1.f / (1.f + __expf(-(xz.y + gz.y)));
    float nn0 = tanhf(xn.x + rr0 * gn.x);
    float nn1 = tanhf(xn.y + rr1 * gn.y);
    float h0 = (1.f - zz0) * nn0 + zz0 * hp0;
    float h1 = (1.f - zz1) * nn1 + zz1 * hp1;

    __nv_bfloat16 b0 = __float2bfloat16(h0), b1 = __float2bfloat16(h1);
    __nv_bfloat162 oh; oh.x = b0; oh.y = b1;
    __nv_bfloat162 ol;
    ol.x = __float2bfloat16(h0 - __bfloat162float(b0));
    ol.y = __float2bfloat16(h1 - __bfloat162float(b1));

    *(__nv_bfloat162*)(g_hH + hidx) = oh;
    *(__nv_bfloat162*)(g_hL + hidx) = ol;
    size_t oo = ((size_t)t_eff * BB + b) * KPAD_W + (size_t)d * HID + k;
    *(__nv_bfloat162*)(g_OUTH + oo) = oh;
    *(__nv_bfloat162*)(g_OUTL + oo) = ol;
}

// ---------------- attention tail kernels ----------------
__global__ void k_softmax_t(const float* __restrict__ score, float* __restrict__ alpha) {
    int b = blockIdx.x, t = threadIdx.x;
    __shared__ float sh[64];
    float v = score[t * BB + b];
    sh[t] = v; __syncthreads();
    #pragma unroll
    for (int o = 32; o; o >>= 1) { if (t < o) sh[t] = fmaxf(sh[t], sh[t + o]); __syncthreads(); }
    float mx = sh[0]; __syncthreads();
    float e = expf(v - mx);
    sh[t] = e; __syncthreads();
    #pragma unroll
    for (int o = 32; o; o >>= 1) { if (t < o) sh[t] += sh[t + o]; __syncthreads(); }
    alpha[t * BB + b] = e / sh[0];
}
__global__ void k_word_vec(const float* __restrict__ alpha) {
    int b = blockIdx.x;
    __shared__ float a[TSTEPS];
    if (threadIdx.x < TSTEPS) a[threadIdx.x] = alpha[threadIdx.x * BB + b];
    __syncthreads();
    for (int h = threadIdx.x; h < H2; h += blockDim.x) {
        float acc = 0.f;
        #pragma unroll 8
        for (int t = 0; t < TSTEPS; t++) {
            size_t o = ((size_t)t * BB + b) * KPAD_W + h;
            acc += a[t] * (__bfloat162float(g_OUTH[o]) + __bfloat162float(g_OUTL[o]));
        }
        g_wv[(size_t)b * H2 + h] = acc;
        split_bf16(acc, g_wvH, g_wvL, (size_t)b * KPAD_W + h);
    }
}
__global__ void k_sent(const float* __restrict__ fcW, const float* __restrict__ fcb,
                       const int* __restrict__ pairs, float* __restrict__ out) {
    int nb = blockIdx.x;
    __shared__ float beta[MSENT];
    __shared__ float sv[H2];
    if (threadIdx.x == 0) {
        float v[MSENT], mx = -1e30f;
        #pragma unroll
        for (int s = 0; s < MSENT; s++) { v[s] = g_score2[nb * MSENT + s]; mx = fmaxf(mx, v[s]); }
        float sum = 0.f;
        #pragma unroll
        for (int s = 0; s < MSENT; s++) { v[s] = expf(v[s] - mx); sum += v[s]; }
        #pragma unroll
        for (int s = 0; s < MSENT; s++) beta[s] = v[s] / sum;
    }
    __syncthreads();
    for (int h = threadIdx.x; h < H2; h += blockDim.x) {
        float acc = 0.f;
        #pragma unroll
        for (int s = 0; s < MSENT; s++)
            acc += beta[s] * g_wv[((size_t)(nb * MSENT + s)) * H2 + h];
        sv[h] = acc;
    }
    __syncthreads();
    const int* p = pairs + nb * 3;
    int base = ((p[0] * ENT + p[1]) * ENT + p[2]) * OUTD;
    for (int o = threadIdx.x; o < OUTD; o += blockDim.x) {
        float acc = fcb[o];
        for (int h = 0; h < H2; h++) acc += sv[h] * fcW[(size_t)o * H2 + h];
        out[base + o] = acc;
    }
}

// ---------------- launcher ----------------
extern "C" void kernel_launch(void* const* d_in, const int* in_sizes, int n_in,
                              void* d_out, int out_size) {
    const float* bag       = (const float*)d_in[0];
    const float* W_ih_f    = (const float*)d_in[1];
    const float* W_hh_f    = (const float*)d_in[2];
    const float* b_ih_f    = (const float*)d_in[3];
    const float* b_hh_f    = (const float*)d_in[4];
    const float* W_ih_r    = (const float*)d_in[5];
    const float* W_hh_r    = (const float*)d_in[6];
    const float* b_ih_r    = (const float*)d_in[7];
    const float* b_hh_r    = (const float*)d_in[8];
    const float* W_word    = (const float*)d_in[9];
    const float* b_word    = (const float*)d_in[10];
    const float* proj_word = (const float*)d_in[11];
    const float* W_sent    = (const float*)d_in[12];
    const float* b_sent    = (const float*)d_in[13];
    const float* proj_sent = (const float*)d_in[14];
    const float* fc_W      = (const float*)d_in[15];
    const float* fc_b      = (const float*)d_in[16];
    const int*   pairs     = (const int*)d_in[17];
    float* out = (float*)d_out;

    static bool attr_set = false;
    if (!attr_set) {
        cudaFuncSetAttribute(gemm_bf16s, cudaFuncAttributeMaxDynamicSharedMemorySize, SMEM_GEMM);
        cudaFuncSetAttribute(gemm_score, cudaFuncAttributeMaxDynamicSharedMemorySize, SMEM_GEMM);
        attr_set = true;
    }

    #define SYMA(p, s) void* p; cudaGetSymbolAddress(&p, s)
    SYMA(pXG, g_XG);     SYMA(pG, g_G);
    SYMA(pScore, g_score);
    SYMA(pAlpha, g_alpha); SYMA(pWv, g_wv);
    SYMA(pScore2, g_score2);
    SYMA(pBih, g_bias_ih); SYMA(pBhh, g_bias_hh);
    SYMA(pBagH, g_bagH); SYMA(pBagL, g_bagL);
    SYMA(pWihH, g_WihH); SYMA(pWihL, g_WihL);
    SYMA(pWhhH, g_WhhH); SYMA(pWhhL, g_WhhL);
    SYMA(pWwH, g_WwordH); SYMA(pWwL, g_WwordL);
    SYMA(pWsH, g_WsentH); SYMA(pWsL, g_WsentL);
    SYMA(pOH, g_OUTH);   SYMA(pOL, g_OUTL);
    SYMA(phH, g_hH);     SYMA(phL, g_hL);
    SYMA(pwvH, g_wvH);   SYMA(pwvL, g_wvL);
    #undef SYMA

    // ---- prep (3 launches), then input GEMM as launch #4 (ncu capture slot) ----
    k_conv_wih<<<(NIH * IND + 255) / 256, 256>>>(W_ih_f, W_ih_r);                       // 1
    k_conv_rest<<<(CW_TOT + 255) / 256, 256>>>(W_hh_f, W_hh_r, W_word, W_sent,          // 2
                                               b_ih_f, b_ih_r, b_hh_f, b_hh_r);
    {
        long long n = MM * (IND / 2);                                                   // 3
        k_conv_bag<<<(unsigned)((n + 255) / 256), 256>>>(bag);
    }
    {
        dim3 g(NPAD_IH / 128, (unsigned)(MM / 128), 1);                                 // 4
        gemm_bf16s<<<g, 512, SMEM_GEMM>>>(
            (const __nv_bfloat16*)pBagH, (const __nv_bfloat16*)pBagL,
            (const __nv_bfloat16*)pWihH, (const __nv_bfloat16*)pWihL,
            (const float*)pBih, (float*)pXG,
            NIH, NIH, KPAD_IN, KPAD_IN / 32, 0, 0, 0, 0);
    }
    {
        int nw = 2 * BB * KPAD_H / 2;                                                   // 5
        k_zero_h<<<(nw + 255) / 256, 256>>>((uint32_t*)phH, (uint32_t*)phL, nw);
    }
    k_zero<<<(out_size + 255) / 256, 256>>>(out, (long long)out_size);                  // 6

    // ---- GRU recurrence ----
    {
        dim3 g(NPAD_HH / 128, BB / 128, 2);
        for (int s = 0; s < TSTEPS; s++) {
            gemm_bf16s<<<g, 512, SMEM_GEMM>>>(
                (const __nv_bfloat16*)phH, (const __nv_bfloat16*)phL,
                (const __nv_bfloat16*)pWhhH, (const __nv_bfloat16*)pWhhL,
                (const float*)pBhh, (float*)pG,
                H3, H3, KPAD_H, KPAD_H / 32,
                (long long)BB * KPAD_H, (long long)NPAD_HH * KPAD_H,
                (long long)H3, (long long)BB * H3);
            k_gru_gate<<<(2 * BB * (HID / 2) + 255) / 256, 256>>>(s);
        }
    }

    // ---- word attention: fused GEMM + tanh.proj score ----
    gemm_score<<<(unsigned)(MM / 128), 512, SMEM_GEMM>>>(
        (const __nv_bfloat16*)pOH, (const __nv_bfloat16*)pOL,
        (const __nv_bfloat16*)pWwH, (const __nv_bfloat16*)pWwL,
        b_word, proj_word, (float*)pScore, H2, KPAD_W, KPAD_W / 32, NPAD_W / 128);
    k_softmax_t<<<BB, 64>>>((const float*)pScore, (float*)pAlpha);
    k_word_vec<<<BB, 256>>>((const float*)pAlpha);

    // ---- sentence attention: fused GEMM + score, then softmax+FC+scatter ----
    gemm_score<<<BB / 128, 512, SMEM_GEMM>>>(
        (const __nv_bfloat16*)pwvH, (const __nv_bfloat16*)pwvL,
        (const __nv_bfloat16*)pWsH, (const __nv_bfloat16*)pWsL,
        b_sent, proj_sent, (float*)pScore2, H2, KPAD_W, KPAD_W / 32, NPAD_W / 128);
    k_sent<<<NBAG, 256>>>(fc_W, fc_b, pairs, out);
}

// round 7
// speedup vs baseline: 2.6862x; 1.1163x over previous
#include <cuda_runtime.h>
#include <cuda_fp16.h>
#include <math.h>
#include <stdint.h>

// ---------------- problem constants ----------------
constexpr int NBAG   = 512;
constexpr int MSENT  = 8;
constexpr int TSTEPS = 64;
constexpr int IND    = 360;
constexpr int HID    = 230;
constexpr int OUTD   = 53;
constexpr int ENT    = 8;

constexpr int BB  = NBAG * MSENT;   // 4096
constexpr int H3  = 3 * HID;        // 690
constexpr int H2  = 2 * HID;        // 460
constexpr int NIH = 2 * H3;         // 1380
constexpr long long MM = (long long)TSTEPS * BB;  // 262144

constexpr int KPAD_IN = 384;
constexpr int NPAD_IH = 1408;
constexpr int KPAD_H  = 256;
constexpr int NPAD_HH = 768;
constexpr int KPAD_W  = 512;
constexpr int NPAD_W  = 512;

// ---------------- device scratch ----------------
__device__ float g_bias_ih[NIH];
__device__ float g_bias_hh[2 * H3];
__device__ float g_XG[(size_t)MM * NIH];
__device__ float g_G[(size_t)2 * BB * H3];
__device__ float g_score[TSTEPS * BB];
__device__ float g_alpha[TSTEPS * BB];
__device__ float g_wv[(size_t)BB * H2];
__device__ float g_score2[BB];

// A-side: single fp16 (error 2^-12 — dominant, within budget).
// B-side (weights): fp16 hi+lo split (error 2^-25).
__device__ __half g_bagF[(size_t)MM * KPAD_IN];
__device__ __half g_WihH[(size_t)NPAD_IH * KPAD_IN];
__device__ __half g_WihL[(size_t)NPAD_IH * KPAD_IN];
__device__ __half g_WhhH[(size_t)2 * NPAD_HH * KPAD_H];
__device__ __half g_WhhL[(size_t)2 * NPAD_HH * KPAD_H];
__device__ __half g_WwordH[(size_t)NPAD_W * KPAD_W];
__device__ __half g_WwordL[(size_t)NPAD_W * KPAD_W];
__device__ __half g_WsentH[(size_t)NPAD_W * KPAD_W];
__device__ __half g_WsentL[(size_t)NPAD_W * KPAD_W];
__device__ __half g_OUTF[(size_t)MM * KPAD_W];
__device__ __half g_hF[(size_t)2 * BB * KPAD_H];
__device__ __half g_wvF[(size_t)BB * KPAD_W];

// ---------------- helpers ----------------
__device__ __forceinline__ uint32_t smem_u32(const void* p) {
    uint32_t a;
    asm("{ .reg .u64 t; cvta.to.shared.u64 t, %1; cvt.u32.u64 %0, t; }" : "=r"(a) : "l"(p));
    return a;
}
__device__ __forceinline__ void ldm_x4(uint32_t* r, uint32_t addr) {
    asm volatile("ldmatrix.sync.aligned.m8n8.x4.shared.b16 {%0,%1,%2,%3}, [%4];"
                 : "=r"(r[0]), "=r"(r[1]), "=r"(r[2]), "=r"(r[3]) : "r"(addr));
}
__device__ __forceinline__ void mma16816(float* d, const uint32_t* a, const uint32_t* b) {
    asm volatile("mma.sync.aligned.m16n8k16.row.col.f32.f16.f16.f32 "
                 "{%0,%1,%2,%3}, {%4,%5,%6,%7}, {%8,%9}, {%0,%1,%2,%3};"
                 : "+f"(d[0]), "+f"(d[1]), "+f"(d[2]), "+f"(d[3])
                 : "r"(a[0]), "r"(a[1]), "r"(a[2]), "r"(a[3]), "r"(b[0]), "r"(b[1]));
}

constexpr int TPAD    = 80;
constexpr int TILE_SM = 128 * TPAD;        // 10240
constexpr int BUFSET  = 3 * TILE_SM;       // 30720 (Af, Bh, Bl)
constexpr int SMEM_GEMM = 2 * BUFSET;      // 61440

// ---------------- fp16 2-pass GEMM: C = Af @ (Bh+Bl)^T + bias ----------------
// A: [Mrows, Kpad] fp16, B: [Npad, Kpad] fp16 split. 512 thr, 128x128 tile,
// warp grid 4x4 (32x32 warp tile), BK=32, double-buffered smem.
__global__ void __launch_bounds__(512)
gemm_f16s(const __half* __restrict__ Af, const __half* __restrict__ Bh,
          const __half* __restrict__ Bl,
          const float* __restrict__ bias, float* __restrict__ C,
          int N, int ldc, int Kpad, int nit,
          long long sA, long long sB, long long sBias, long long sC)
{
    extern __shared__ __align__(16) unsigned char sm[];

    int tid = threadIdx.x;
    int lane = tid & 31, wid = tid >> 5;
    int wm = wid >> 2, wn = wid & 3;

    long long z = blockIdx.z;
    Af += z * sA;
    Bh += z * sB;  Bl += z * sB;
    bias += z * sBias;
    C  += z * sC;

    int m0 = blockIdx.y * 128, n0 = blockIdx.x * 128;

    // loaders: each thread fills row r0, 16B-chunk c4 of all three tiles
    int r0 = tid >> 2, c4 = tid & 3;
    const __half* srcA  = Af + (size_t)(m0 + r0) * Kpad + c4 * 8;
    const __half* srcBh = Bh + (size_t)(n0 + r0) * Kpad + c4 * 8;
    const __half* srcBl = Bl + (size_t)(n0 + r0) * Kpad + c4 * 8;
    int so = r0 * TPAD + c4 * 16;

    uint32_t smb = smem_u32(sm);

    float acc[2][4][4];
    #pragma unroll
    for (int i = 0; i < 2; i++)
        #pragma unroll
        for (int j = 0; j < 4; j++)
            #pragma unroll
            for (int q = 0; q < 4; q++) acc[i][j][q] = 0.f;

    int arow = (lane & 7) + (((lane >> 3) & 1) << 3);
    int acolb = ((lane >> 4) & 1) * 16;
    uint32_t aBase0 = smb + (wm * 32 + arow) * TPAD + acolb;
    int brow = (lane & 7) + (((lane >> 4) & 1) << 3);
    int bcolb = ((lane >> 3) & 1) * 16;
    uint32_t bhBase0 = smb + TILE_SM + (wn * 32 + brow) * TPAD + bcolb;

    uint4 p0 = *(const uint4*)srcA;
    uint4 p1 = *(const uint4*)srcBh;
    uint4 p2 = *(const uint4*)srcBl;
    *(uint4*)(sm + so) = p0;
    *(uint4*)(sm + TILE_SM + so) = p1;
    *(uint4*)(sm + 2 * TILE_SM + so) = p2;
    __syncthreads();

    for (int kc = 0; kc < nit; kc++) {
        int cur = kc & 1;
        if (kc + 1 < nit) {
            int off = (kc + 1) * 32;
            p0 = *(const uint4*)(srcA + off);
            p1 = *(const uint4*)(srcBh + off);
            p2 = *(const uint4*)(srcBl + off);
        }

        uint32_t aBase  = aBase0  + cur * BUFSET;
        uint32_t bhBase = bhBase0 + cur * BUFSET;
        #pragma unroll
        for (int s = 0; s < 2; s++) {
            uint32_t af[2][4], bh2[2][4], bl2[2][4];
            #pragma unroll
            for (int i = 0; i < 2; i++)
                ldm_x4(af[i], aBase + i * 16 * TPAD + s * 32);
            #pragma unroll
            for (int jj = 0; jj < 2; jj++) {
                ldm_x4(bh2[jj], bhBase + jj * 16 * TPAD + s * 32);
                ldm_x4(bl2[jj], bhBase + TILE_SM + jj * 16 * TPAD + s * 32);
            }
            #pragma unroll
            for (int i = 0; i < 2; i++)
                #pragma unroll
                for (int j = 0; j < 4; j++)
                    mma16816(acc[i][j], af[i], &bh2[j >> 1][(j & 1) * 2]);
            #pragma unroll
            for (int i = 0; i < 2; i++)
                #pragma unroll
                for (int j = 0; j < 4; j++)
                    mma16816(acc[i][j], af[i], &bl2[j >> 1][(j & 1) * 2]);
        }

        if (kc + 1 < nit) {
            int nxt = (cur ^ 1) * BUFSET;
            *(uint4*)(sm + nxt + so) = p0;
            *(uint4*)(sm + nxt + TILE_SM + so) = p1;
            *(uint4*)(sm + nxt + 2 * TILE_SM + so) = p2;
            __syncthreads();
        }
    }

    int qrow = lane >> 2, qcol = (lane & 3) * 2;
    #pragma unroll
    for (int i = 0; i < 2; i++) {
        #pragma unroll
        for (int j = 0; j < 4; j++) {
            int gc = n0 + wn * 32 + j * 8 + qcol;
            #pragma unroll
            for (int half = 0; half < 2; half++) {
                int gr = m0 + wm * 32 + i * 16 + qrow + half * 8;
                float v0 = acc[i][j][half * 2 + 0];
                float v1 = acc[i][j][half * 2 + 1];
                if (gc < N)     C[(size_t)gr * ldc + gc]     = v0 + bias[gc];
                if (gc + 1 < N) C[(size_t)gr * ldc + gc + 1] = v1 + bias[gc + 1];
            }
        }
    }
}

// ---------------- fp16 2-pass GEMM with fused score epilogue ----------------
// score[m] = sum_n tanh((A@B^T)[m,n] + bias[n]) * proj[n], n < Nact.
// 1-D grid over M; loops nbt N-tiles inside the block (deterministic).
__global__ void __launch_bounds__(512)
gemm_score(const __half* __restrict__ Af, const __half* __restrict__ Bh,
           const __half* __restrict__ Bl,
           const float* __restrict__ bias, const float* __restrict__ proj,
           float* __restrict__ score, int Nact, int Kpad, int nit, int nbt)
{
    extern __shared__ __align__(16) unsigned char sm[];

    int tid = threadIdx.x;
    int lane = tid & 31, wid = tid >> 5;
    int wm = wid >> 2, wn = wid & 3;
    int m0 = blockIdx.x * 128;

    int r0 = tid >> 2, c4 = tid & 3;
    const __half* srcA = Af + (size_t)(m0 + r0) * Kpad + c4 * 8;
    int so = r0 * TPAD + c4 * 16;

    uint32_t smb = smem_u32(sm);

    int arow = (lane & 7) + (((lane >> 3) & 1) << 3);
    int acolb = ((lane >> 4) & 1) * 16;
    uint32_t aBase0 = smb + (wm * 32 + arow) * TPAD + acolb;
    int brow = (lane & 7) + (((lane >> 4) & 1) << 3);
    int bcolb = ((lane >> 3) & 1) * 16;
    uint32_t bhBase0 = smb + TILE_SM + (wn * 32 + brow) * TPAD + bcolb;

    int qrow = lane >> 2, qcol = (lane & 3) * 2;
    float sacc[2][2] = {{0.f, 0.f}, {0.f, 0.f}};

    for (int nb = 0; nb < nbt; nb++) {
        int n0 = nb * 128;
        const __half* srcBh = Bh + (size_t)(n0 + r0) * Kpad + c4 * 8;
        const __half* srcBl = Bl + (size_t)(n0 + r0) * Kpad + c4 * 8;

        float acc[2][4][4];
        #pragma unroll
        for (int i = 0; i < 2; i++)
            #pragma unroll
            for (int j = 0; j < 4; j++)
                #pragma unroll
                for (int q = 0; q < 4; q++) acc[i][j][q] = 0.f;

        __syncthreads();   // smem reuse guard across nb iterations

        uint4 p0 = *(const uint4*)srcA;
        uint4 p1 = *(const uint4*)srcBh;
        uint4 p2 = *(const uint4*)srcBl;
        *(uint4*)(sm + so) = p0;
        *(uint4*)(sm + TILE_SM + so) = p1;
        *(uint4*)(sm + 2 * TILE_SM + so) = p2;
        __syncthreads();

        for (int kc = 0; kc < nit; kc++) {
            int cur = kc & 1;
            if (kc + 1 < nit) {
                int off = (kc + 1) * 32;
                p0 = *(const uint4*)(srcA + off);
                p1 = *(const uint4*)(srcBh + off);
                p2 = *(const uint4*)(srcBl + off);
            }
            uint32_t aBase  = aBase0  + cur * BUFSET;
            uint32_t bhBase = bhBase0 + cur * BUFSET;
            #pragma unroll
            for (int s = 0; s < 2; s++) {
                uint32_t af[2][4], bh2[2][4], bl2[2][4];
                #pragma unroll
                for (int i = 0; i < 2; i++)
                    ldm_x4(af[i], aBase + i * 16 * TPAD + s * 32);
                #pragma unroll
                for (int jj = 0; jj < 2; jj++) {
                    ldm_x4(bh2[jj], bhBase + jj * 16 * TPAD + s * 32);
                    ldm_x4(bl2[jj], bhBase + TILE_SM + jj * 16 * TPAD + s * 32);
                }
                #pragma unroll
                for (int i = 0; i < 2; i++)
                    #pragma unroll
                    for (int j = 0; j < 4; j++)
                        mma16816(acc[i][j], af[i], &bh2[j >> 1][(j & 1) * 2]);
                #pragma unroll
                for (int i = 0; i < 2; i++)
                    #pragma unroll
                    for (int j = 0; j < 4; j++)
                        mma16816(acc[i][j], af[i], &bl2[j >> 1][(j & 1) * 2]);
            }
            if (kc + 1 < nit) {
                int nxt = (cur ^ 1) * BUFSET;
                *(uint4*)(sm + nxt + so) = p0;
                *(uint4*)(sm + nxt + TILE_SM + so) = p1;
                *(uint4*)(sm + nxt + 2 * TILE_SM + so) = p2;
                __syncthreads();
            }
        }

        #pragma unroll
        for (int i = 0; i < 2; i++) {
            #pragma unroll
            for (int j = 0; j < 4; j++) {
                int gc = n0 + wn * 32 + j * 8 + qcol;
                #pragma unroll
                for (int half = 0; half < 2; half++) {
                    if (gc < Nact)
                        sacc[i][half] += tanhf(acc[i][j][half * 2 + 0] + bias[gc]) * proj[gc];
                    if (gc + 1 < Nact)
                        sacc[i][half] += tanhf(acc[i][j][half * 2 + 1] + bias[gc + 1]) * proj[gc + 1];
                }
            }
        }
    }

    #pragma unroll
    for (int i = 0; i < 2; i++)
        #pragma unroll
        for (int half = 0; half < 2; half++) {
            float v = sacc[i][half];
            v += __shfl_xor_sync(0xffffffffu, v, 1);
            v += __shfl_xor_sync(0xffffffffu, v, 2);
            sacc[i][half] = v;
        }

    __syncthreads();
    float* sred = (float*)sm;
    if ((lane & 3) == 0) {
        #pragma unroll
        for (int i = 0; i < 2; i++)
            #pragma unroll
            for (int half = 0; half < 2; half++) {
                int rl = wm * 32 + i * 16 + half * 8 + qrow;
                sred[rl * 4 + wn] = sacc[i][half];
            }
    }
    __syncthreads();
    if (tid < 128) {
        float s = sred[tid * 4] + sred[tid * 4 + 1] + sred[tid * 4 + 2] + sred[tid * 4 + 3];
        score[m0 + tid] = s;
    }
}

// ---------------- conversion / prep kernels ----------------
__device__ __forceinline__ void split_f16(float v, __half* H, __half* L, size_t i) {
    __half h = __float2half(v);
    H[i] = h;
    L[i] = __float2half(v - __half2float(h));
}

__global__ void k_zero(float* p, long long n) {
    long long i = (long long)blockIdx.x * blockDim.x + threadIdx.x;
    if (i < n) p[i] = 0.f;
}
__global__ void k_zero_h(uint32_t* a, int nw) {
    int i = blockIdx.x * 256 + threadIdx.x;
    if (i < nw) a[i] = 0u;
}

__global__ void k_conv_wih(const float* __restrict__ Wf, const float* __restrict__ Wr) {
    int idx = blockIdx.x * 256 + threadIdx.x;
    if (idx >= NIH * IND) return;
    int n = idx / IND, k = idx % IND;
    float v = (n < H3) ? Wf[(size_t)n * IND + k] : Wr[(size_t)(n - H3) * IND + k];
    split_f16(v, g_WihH, g_WihL, (size_t)n * KPAD_IN + k);
}

constexpr int CW_WHH = 2 * H3 * HID;
constexpr int CW_WW  = H2 * H2;
constexpr int CW_TOT = CW_WHH + 2 * CW_WW + NIH + 2 * H3;
__global__ void k_conv_rest(const float* __restrict__ Whf, const float* __restrict__ Whr,
                            const float* __restrict__ Ww, const float* __restrict__ Ws,
                            const float* __restrict__ bif, const float* __restrict__ bir,
                            const float* __restrict__ bhf, const float* __restrict__ bhr) {
    int idx = blockIdx.x * 256 + threadIdx.x;
    if (idx < CW_WHH) {
        int d = idx / (H3 * HID), r = idx % (H3 * HID);
        int n = r / HID, k = r % HID;
        const float* W = d ? Whr : Whf;
        split_f16(W[(size_t)n * HID + k], g_WhhH, g_WhhL,
                  ((size_t)d * NPAD_HH + n) * KPAD_H + k);
        return;
    }
    idx -= CW_WHH;
    if (idx < CW_WW) {
        int n = idx / H2, k = idx % H2;
        split_f16(Ww[(size_t)k * H2 + n], g_WwordH, g_WwordL, (size_t)n * KPAD_W + k);
        return;
    }
    idx -= CW_WW;
    if (idx < CW_WW) {
        int n = idx / H2, k = idx % H2;
        split_f16(Ws[(size_t)k * H2 + n], g_WsentH, g_WsentL, (size_t)n * KPAD_W + k);
        return;
    }
    idx -= CW_WW;
    if (idx < NIH) { g_bias_ih[idx] = (idx < H3) ? bif[idx] : bir[idx - H3]; return; }
    idx -= NIH;
    if (idx < 2 * H3) g_bias_hh[idx] = (idx < H3) ? bhf[idx] : bhr[idx - H3];
}

__global__ void k_conv_bag(const float* __restrict__ bag) {
    size_t idx = (size_t)blockIdx.x * 256 + threadIdx.x;
    if (idx >= (size_t)MM * (IND / 2)) return;
    int j = (int)(idx % (IND / 2));
    size_t m = idx / (IND / 2);
    int tt = (int)(m >> 12), b = (int)(m & 4095);
    float2 v = *(const float2*)(bag + ((size_t)b * TSTEPS + tt) * IND + 2 * j);
    __half2 h; h.x = __float2half(v.x); h.y = __float2half(v.y);
    *(__half2*)(g_bagF + m * KPAD_IN + 2 * j) = h;
}

// ---------------- GRU gate pointwise (fp16 state) ----------------
__global__ void k_gru_gate(int step) {
    int idx = blockIdx.x * 256 + threadIdx.x;
    if (idx >= 2 * BB * (HID / 2)) return;
    int d = idx / (BB * (HID / 2));
    int r = idx % (BB * (HID / 2));
    int b = r / (HID / 2), j = r % (HID / 2);
    int k = 2 * j;
    int t_eff = d ? (TSTEPS - 1 - step) : step;

    const float* xg = g_XG + ((size_t)t_eff * BB + b) * NIH + d * H3;
    const float* g  = g_G + ((size_t)d * BB + b) * H3;
    size_t hidx = ((size_t)d * BB + b) * KPAD_H + k;

    float2 xr = *(const float2*)(xg + k);
    float2 xz = *(const float2*)(xg + HID + k);
    float2 xn = *(const float2*)(xg + 2 * HID + k);
    float2 gr = *(const float2*)(g + k);
    float2 gz = *(const float2*)(g + HID + k);
    float2 gn = *(const float2*)(g + 2 * HID + k);

    __half2 hh = *(const __half2*)(g_hF + hidx);
    float hp0 = __half2float(hh.x);
    float hp1 = __half2float(hh.y);

    float rr0 = 1.f / (1.f + __expf(-(xr.x + gr.x)));
    float rr1 = 1.f / (1.f + __expf(-(xr.y + gr.y)));
    float zz0 = 1.f / (1.f + __expf(-(xz.x + gz.x)));
    float zz1 = 1.f / (1.f + __expf(-(xz.y + gz.y)));
    float nn0 = tanhf(xn.x + rr0 * gn.x);
    float nn1 = tanhf(xn.y + rr1 * gn.y);
    float h0 = (1.f - zz0) * nn0 + zz0 * hp0;
    float h1 = (1.f - zz1) * nn1 + zz1 * hp1;

    __half2 oh; oh.x = __float2half(h0); oh.y = __float2half(h1);
    *(__half2*)(g_hF + hidx) = oh;
    size_t oo = ((size_t)t_eff * BB + b) * KPAD_W + (size_t)d * HID + k;
    *(__half2*)(g_OUTF + oo) = oh;
}

// ---------------- attention tail kernels ----------------
__global__ void k_softmax_t(const float* __restrict__ score, float* __restrict__ alpha) {
    int b = blockIdx.x, t = threadIdx.x;
    __shared__ float sh[64];
    float v = score[t * BB + b];
    sh[t] = v; __syncthreads();
    #pragma unroll
    for (int o = 32; o; o >>= 1) { if (t < o) sh[t] = fmaxf(sh[t], sh[t + o]); __syncthreads(); }
    float mx = sh[0]; __syncthreads();
    float e = expf(v - mx);
    sh[t] = e; __syncthreads();
    #pragma unroll
    for (int o = 32; o; o >>= 1) { if (t < o) sh[t] += sh[t + o]; __syncthreads(); }
    alpha[t * BB + b] = e / sh[0];
}
__global__ void k_word_vec(const float* __restrict__ alpha) {
    int b = blockIdx.x;
    __shared__ float a[TSTEPS];
    if (threadIdx.x < TSTEPS) a[threadIdx.x] = alpha[threadIdx.x * BB + b];
    __syncthreads();
    for (int h = threadIdx.x; h < H2; h += blockDim.x) {
        float acc = 0.f;
        #pragma unroll 8
        for (int t = 0; t < TSTEPS; t++)
            acc += a[t] * __half2float(g_OUTF[((size_t)t * BB + b) * KPAD_W + h]);
        g_wv[(size_t)b * H2 + h] = acc;
        g_wvF[(size_t)b * KPAD_W + h] = __float2half(acc);
    }
}
__global__ void k_sent(const float* __restrict__ fcW, const float* __restrict__ fcb,
                       const int* __restrict__ pairs, float* __restrict__ out) {
    int nb = blockIdx.x;
    __shared__ float beta[MSENT];
    __shared__ float sv[H2];
    if (threadIdx.x == 0) {
        float v[MSENT], mx = -1e30f;
        #pragma unroll
        for (int s = 0; s < MSENT; s++) { v[s] = g_score2[nb * MSENT + s]; mx = fmaxf(mx, v[s]); }
        float sum = 0.f;
        #pragma unroll
        for (int s = 0; s < MSENT; s++) { v[s] = expf(v[s] - mx); sum += v[s]; }
        #pragma unroll
        for (int s = 0; s < MSENT; s++) beta[s] = v[s] / sum;
    }
    __syncthreads();
    for (int h = threadIdx.x; h < H2; h += blockDim.x) {
        float acc = 0.f;
        #pragma unroll
        for (int s = 0; s < MSENT; s++)
            acc += beta[s] * g_wv[((size_t)(nb * MSENT + s)) * H2 + h];
        sv[h] = acc;
    }
    __syncthreads();
    const int* p = pairs + nb * 3;
    int base = ((p[0] * ENT + p[1]) * ENT + p[2]) * OUTD;
    for (int o = threadIdx.x; o < OUTD; o += blockDim.x) {
        float acc = fcb[o];
        for (int h = 0; h < H2; h++) acc += sv[h] * fcW[(size_t)o * H2 + h];
        out[base + o] = acc;
    }
}

// ---------------- launcher ----------------
extern "C" void kernel_launch(void* const* d_in, const int* in_sizes, int n_in,
                              void* d_out, int out_size) {
    const float* bag       = (const float*)d_in[0];
    const float* W_ih_f    = (const float*)d_in[1];
    const float* W_hh_f    = (const float*)d_in[2];
    const float* b_ih_f    = (const float*)d_in[3];
    const float* b_hh_f    = (const float*)d_in[4];
    const float* W_ih_r    = (const float*)d_in[5];
    const float* W_hh_r    = (const float*)d_in[6];
    const float* b_ih_r    = (const float*)d_in[7];
    const float* b_hh_r    = (const float*)d_in[8];
    const float* W_word    = (const float*)d_in[9];
    const float* b_word    = (const float*)d_in[10];
    const float* proj_word = (const float*)d_in[11];
    const float* W_sent    = (const float*)d_in[12];
    const float* b_sent    = (const float*)d_in[13];
    const float* proj_sent = (const float*)d_in[14];
    const float* fc_W      = (const float*)d_in[15];
    const float* fc_b      = (const float*)d_in[16];
    const int*   pairs     = (const int*)d_in[17];
    float* out = (float*)d_out;

    static bool attr_set = false;
    if (!attr_set) {
        cudaFuncSetAttribute(gemm_f16s, cudaFuncAttributeMaxDynamicSharedMemorySize, SMEM_GEMM);
        cudaFuncSetAttribute(gemm_score, cudaFuncAttributeMaxDynamicSharedMemorySize, SMEM_GEMM);
        attr_set = true;
    }

    #define SYMA(p, s) void* p; cudaGetSymbolAddress(&p, s)
    SYMA(pXG, g_XG);     SYMA(pG, g_G);
    SYMA(pScore, g_score);
    SYMA(pAlpha, g_alpha); SYMA(pWv, g_wv);
    SYMA(pScore2, g_score2);
    SYMA(pBih, g_bias_ih); SYMA(pBhh, g_bias_hh);
    SYMA(pBagF, g_bagF);
    SYMA(pWihH, g_WihH); SYMA(pWihL, g_WihL);
    SYMA(pWhhH, g_WhhH); SYMA(pWhhL, g_WhhL);
    SYMA(pWwH, g_WwordH); SYMA(pWwL, g_WwordL);
    SYMA(pWsH, g_WsentH); SYMA(pWsL, g_WsentL);
    SYMA(pOF, g_OUTF);
    SYMA(phF, g_hF);
    SYMA(pwvF, g_wvF);
    #undef SYMA

    // ---- prep (3 launches), then input GEMM as launch #4 (ncu capture slot) ----
    k_conv_wih<<<(NIH * IND + 255) / 256, 256>>>(W_ih_f, W_ih_r);                       // 1
    k_conv_rest<<<(CW_TOT + 255) / 256, 256>>>(W_hh_f, W_hh_r, W_word, W_sent,          // 2
                                               b_ih_f, b_ih_r, b_hh_f, b_hh_r);
    {
        long long n = MM * (IND / 2);                                                   // 3
        k_conv_bag<<<(unsigned)((n + 255) / 256), 256>>>(bag);
    }
    {
        dim3 g(NPAD_IH / 128, (unsigned)(MM / 128), 1);                                 // 4
        gemm_f16s<<<g, 512, SMEM_GEMM>>>(
            (const __half*)pBagF,
            (const __half*)pWihH, (const __half*)pWihL,
            (const float*)pBih, (float*)pXG,
            NIH, NIH, KPAD_IN, KPAD_IN / 32, 0, 0, 0, 0);
    }
    {
        int nw = 2 * BB * KPAD_H / 2;                                                   // 5
        k_zero_h<<<(nw + 255) / 256, 256>>>((uint32_t*)phF, nw);
    }
    k_zero<<<(out_size + 255) / 256, 256>>>(out, (long long)out_size);                  // 6

    // ---- GRU recurrence ----
    {
        dim3 g(NPAD_HH / 128, BB / 128, 2);
        for (int s = 0; s < TSTEPS; s++) {
            gemm_f16s<<<g, 512, SMEM_GEMM>>>(
                (const __half*)phF,
                (const __half*)pWhhH, (const __half*)pWhhL,
                (const float*)pBhh, (float*)pG,
                H3, H3, KPAD_H, KPAD_H / 32,
                (long long)BB * KPAD_H, (long long)NPAD_HH * KPAD_H,
                (long long)H3, (long long)BB * H3);
            k_gru_gate<<<(2 * BB * (HID / 2) + 255) / 256, 256>>>(s);
        }
    }

    // ---- word attention: fused GEMM + tanh.proj score ----
    gemm_score<<<(unsigned)(MM / 128), 512, SMEM_GEMM>>>(
        (const __half*)pOF,
        (const __half*)pWwH, (const __half*)pWwL,
        b_word, proj_word, (float*)pScore, H2, KPAD_W, KPAD_W / 32, NPAD_W / 128);
    k_softmax_t<<<BB, 64>>>((const float*)pScore, (float*)pAlpha);
    k_word_vec<<<BB, 256>>>((const float*)pAlpha);

    // ---- sentence attention: fused GEMM + score, then softmax+FC+scatter ----
    gemm_score<<<BB / 128, 512, SMEM_GEMM>>>(
        (const __half*)pwvF,
        (const __half*)pWsH, (const __half*)pWsL,
        b_sent, proj_sent, (float*)pScore2, H2, KPAD_W, KPAD_W / 32, NPAD_W / 128);
    k_sent<<<NBAG, 256>>>(fc_W, fc_b, pairs, out);
}

// round 9
// speedup vs baseline: 3.3366x; 1.2421x over previous
#include <cuda_runtime.h>
#include <cuda_fp16.h>
#include <math.h>
#include <stdint.h>

// ---------------- problem constants ----------------
constexpr int NBAG   = 512;
constexpr int MSENT  = 8;
constexpr int TSTEPS = 64;
constexpr int IND    = 360;
constexpr int HID    = 230;
constexpr int OUTD   = 53;
constexpr int ENT    = 8;

constexpr int BB  = NBAG * MSENT;   // 4096
constexpr int H3  = 3 * HID;        // 690
constexpr int H2  = 2 * HID;        // 460
constexpr int NIH = 2 * H3;         // 1380
constexpr long long MM = (long long)TSTEPS * BB;  // 262144

constexpr int KPAD_IN = 384;
constexpr int NPAD_IH = 1408;
constexpr int KPAD_H  = 256;
constexpr int NPAD_HH = 768;
constexpr int KPAD_W  = 512;
constexpr int NPAD_W  = 512;

// ---------------- device scratch ----------------
__device__ float g_bias_ih[NIH];
__device__ float g_bias_hh[2 * H3];
__device__ float g_XG[(size_t)MM * NIH];
__device__ float g_G[(size_t)2 * BB * H3];
__device__ float g_score[TSTEPS * BB];
__device__ float g_alpha[TSTEPS * BB];
__device__ float g_wv[(size_t)BB * H2];
__device__ float g_score2[BB];

// A-side: single fp16 (error 2^-12). B-side (weights): fp16 hi+lo split.
__device__ __half g_bagF[(size_t)MM * KPAD_IN];
__device__ __half g_WihH[(size_t)NPAD_IH * KPAD_IN];
__device__ __half g_WihL[(size_t)NPAD_IH * KPAD_IN];
__device__ __half g_WhhH[(size_t)2 * NPAD_HH * KPAD_H];
__device__ __half g_WhhL[(size_t)2 * NPAD_HH * KPAD_H];
__device__ __half g_WwordH[(size_t)NPAD_W * KPAD_W];
__device__ __half g_WwordL[(size_t)NPAD_W * KPAD_W];
__device__ __half g_WsentH[(size_t)NPAD_W * KPAD_W];
__device__ __half g_WsentL[(size_t)NPAD_W * KPAD_W];
__device__ __half g_OUTF[(size_t)MM * KPAD_W];
__device__ __half g_hF[(size_t)2 * BB * KPAD_H];
__device__ __half g_wvF[(size_t)BB * KPAD_W];

// ---------------- helpers ----------------
__device__ __forceinline__ uint32_t smem_u32(const void* p) {
    uint32_t a;
    asm("{ .reg .u64 t; cvta.to.shared.u64 t, %1; cvt.u32.u64 %0, t; }" : "=r"(a) : "l"(p));
    return a;
}
__device__ __forceinline__ void ldm_x4(uint32_t* r, uint32_t addr) {
    asm volatile("ldmatrix.sync.aligned.m8n8.x4.shared.b16 {%0,%1,%2,%3}, [%4];"
                 : "=r"(r[0]), "=r"(r[1]), "=r"(r[2]), "=r"(r[3]) : "r"(addr));
}
__device__ __forceinline__ void mma16816(float* d, const uint32_t* a, const uint32_t* b) {
    asm volatile("mma.sync.aligned.m16n8k16.row.col.f32.f16.f16.f32 "
                 "{%0,%1,%2,%3}, {%4,%5,%6,%7}, {%8,%9}, {%0,%1,%2,%3};"
                 : "+f"(d[0]), "+f"(d[1]), "+f"(d[2]), "+f"(d[3])
                 : "r"(a[0]), "r"(a[1]), "r"(a[2]), "r"(a[3]), "r"(b[0]), "r"(b[1]));
}
__device__ __forceinline__ void cp_async16(uint32_t saddr, const void* gaddr) {
    asm volatile("cp.async.cg.shared.global [%0], [%1], 16;" :: "r"(saddr), "l"(gaddr));
}
#define CP_COMMIT() asm volatile("cp.async.commit_group;" ::: "memory")
#define CP_WAIT0()  asm volatile("cp.async.wait_group 0;" ::: "memory")

constexpr int TPAD    = 80;
constexpr int TILE_SM = 128 * TPAD;        // 10240
constexpr int BUFSET  = 3 * TILE_SM;       // 30720 (Af, Bh, Bl)
constexpr int SMEM_GEMM = 2 * BUFSET;      // 61440

// ---------------- fp16 2-pass GEMM: C = Af @ (Bh+Bl)^T + bias ----------------
// cp.async double-buffered, 512 thr, 128x128 tile, warp grid 4x4, BK=32.
__global__ void __launch_bounds__(512, 2)
gemm_f16s(const __half* __restrict__ Af, const __half* __restrict__ Bh,
          const __half* __restrict__ Bl,
          const float* __restrict__ bias, float* __restrict__ C,
          int N, int ldc, int Kpad, int nit,
          long long sA, long long sB, long long sBias, long long sC)
{
    extern __shared__ __align__(16) unsigned char sm[];

    int tid = threadIdx.x;
    int lane = tid & 31, wid = tid >> 5;
    int wm = wid >> 2, wn = wid & 3;

    long long z = blockIdx.z;
    Af += z * sA;
    Bh += z * sB;  Bl += z * sB;
    bias += z * sBias;
    C  += z * sC;

    int m0 = blockIdx.y * 128, n0 = blockIdx.x * 128;

    // loaders: thread covers row r0, 16B chunk c4 of each of the 3 tiles
    int r0 = tid >> 2, c4 = tid & 3;
    const __half* srcA  = Af + (size_t)(m0 + r0) * Kpad + c4 * 8;
    const __half* srcBh = Bh + (size_t)(n0 + r0) * Kpad + c4 * 8;
    const __half* srcBl = Bl + (size_t)(n0 + r0) * Kpad + c4 * 8;

    uint32_t smb = smem_u32(sm);
    uint32_t sdst = smb + r0 * TPAD + c4 * 16;

    float acc[2][4][4];
    #pragma unroll
    for (int i = 0; i < 2; i++)
        #pragma unroll
        for (int j = 0; j < 4; j++)
            #pragma unroll
            for (int q = 0; q < 4; q++) acc[i][j][q] = 0.f;

    int arow = (lane & 7) + (((lane >> 3) & 1) << 3);
    int acolb = ((lane >> 4) & 1) * 16;
    uint32_t aBase0 = smb + (wm * 32 + arow) * TPAD + acolb;
    int brow = (lane & 7) + (((lane >> 4) & 1) << 3);
    int bcolb = ((lane >> 3) & 1) * 16;
    uint32_t bhBase0 = smb + TILE_SM + (wn * 32 + brow) * TPAD + bcolb;

    // prologue: chunk 0 -> buf 0
    cp_async16(sdst,               srcA);
    cp_async16(sdst + TILE_SM,     srcBh);
    cp_async16(sdst + 2 * TILE_SM, srcBl);
    CP_COMMIT();

    for (int kc = 0; kc < nit; kc++) {
        int cur = kc & 1;
        CP_WAIT0();
        __syncthreads();

        if (kc + 1 < nit) {
            uint32_t d = sdst + (cur ^ 1) * BUFSET;
            int off = (kc + 1) * 32;
            cp_async16(d,               srcA + off);
            cp_async16(d + TILE_SM,     srcBh + off);
            cp_async16(d + 2 * TILE_SM, srcBl + off);
            CP_COMMIT();
        }

        uint32_t aBase  = aBase0  + cur * BUFSET;
        uint32_t bhBase = bhBase0 + cur * BUFSET;
        #pragma unroll
        for (int s = 0; s < 2; s++) {
            uint32_t af[2][4], bh2[2][4], bl2[2][4];
            #pragma unroll
            for (int i = 0; i < 2; i++)
                ldm_x4(af[i], aBase + i * 16 * TPAD + s * 32);
            #pragma unroll
            for (int jj = 0; jj < 2; jj++) {
                ldm_x4(bh2[jj], bhBase + jj * 16 * TPAD + s * 32);
                ldm_x4(bl2[jj], bhBase + TILE_SM + jj * 16 * TPAD + s * 32);
            }
            #pragma unroll
            for (int i = 0; i < 2; i++)
                #pragma unroll
                for (int j = 0; j < 4; j++)
                    mma16816(acc[i][j], af[i], &bh2[j >> 1][(j & 1) * 2]);
            #pragma unroll
            for (int i = 0; i < 2; i++)
                #pragma unroll
                for (int j = 0; j < 4; j++)
                    mma16816(acc[i][j], af[i], &bl2[j >> 1][(j & 1) * 2]);
        }
        __syncthreads();
    }

    int qrow = lane >> 2, qcol = (lane & 3) * 2;
    #pragma unroll
    for (int i = 0; i < 2; i++) {
        #pragma unroll
        for (int j = 0; j < 4; j++) {
            int gc = n0 + wn * 32 + j * 8 + qcol;
            #pragma unroll
            for (int half = 0; half < 2; half++) {
                int gr = m0 + wm * 32 + i * 16 + qrow + half * 8;
                float v0 = acc[i][j][half * 2 + 0];
                float v1 = acc[i][j][half * 2 + 1];
                if (gc < N)     C[(size_t)gr * ldc + gc]     = v0 + bias[gc];
                if (gc + 1 < N) C[(size_t)gr * ldc + gc + 1] = v1 + bias[gc + 1];
            }
        }
    }
}

// ---------------- fp16 2-pass GEMM with fused score epilogue ----------------
// score[m] = sum_n tanh((A@B^T)[m,n] + bias[n]) * proj[n], n < Nact.
__global__ void __launch_bounds__(512, 2)
gemm_score(const __half* __restrict__ Af, const __half* __restrict__ Bh,
           const __half* __restrict__ Bl,
           const float* __restrict__ bias, const float* __restrict__ proj,
           float* __restrict__ score, int Nact, int Kpad, int nit, int nbt)
{
    extern __shared__ __align__(16) unsigned char sm[];

    int tid = threadIdx.x;
    int lane = tid & 31, wid = tid >> 5;
    int wm = wid >> 2, wn = wid & 3;
    int m0 = blockIdx.x * 128;

    int r0 = tid >> 2, c4 = tid & 3;
    const __half* srcA = Af + (size_t)(m0 + r0) * Kpad + c4 * 8;

    uint32_t smb = smem_u32(sm);
    uint32_t sdst = smb + r0 * TPAD + c4 * 16;

    int arow = (lane & 7) + (((lane >> 3) & 1) << 3);
    int acolb = ((lane >> 4) & 1) * 16;
    uint32_t aBase0 = smb + (wm * 32 + arow) * TPAD + acolb;
    int brow = (lane & 7) + (((lane >> 4) & 1) << 3);
    int bcolb = ((lane >> 3) & 1) * 16;
    uint32_t bhBase0 = smb + TILE_SM + (wn * 32 + brow) * TPAD + bcolb;

    int qrow = lane >> 2, qcol = (lane & 3) * 2;
    float sacc[2][2] = {{0.f, 0.f}, {0.f, 0.f}};

    for (int nb = 0; nb < nbt; nb++) {
        int n0 = nb * 128;
        const __half* srcBh = Bh + (size_t)(n0 + r0) * Kpad + c4 * 8;
        const __half* srcBl = Bl + (size_t)(n0 + r0) * Kpad + c4 * 8;

        float acc[2][4][4];
        #pragma unroll
        for (int i = 0; i < 2; i++)
            #pragma unroll
            for (int j = 0; j < 4; j++)
                #pragma unroll
                for (int q = 0; q < 4; q++) acc[i][j][q] = 0.f;

        __syncthreads();   // smem reuse guard across nb iterations

        cp_async16(sdst,               srcA);
        cp_async16(sdst + TILE_SM,     srcBh);
        cp_async16(sdst + 2 * TILE_SM, srcBl);
        CP_COMMIT();

        for (int kc = 0; kc < nit; kc++) {
            int cur = kc & 1;
            CP_WAIT0();
            __syncthreads();

            if (kc + 1 < nit) {
                uint32_t d = sdst + (cur ^ 1) * BUFSET;
                int off = (kc + 1) * 32;
                cp_async16(d,               srcA + off);
                cp_async16(d + TILE_SM,     srcBh + off);
                cp_async16(d + 2 * TILE_SM, srcBl + off);
                CP_COMMIT();
            }

            uint32_t aBase  = aBase0  + cur * BUFSET;
            uint32_t bhBase = bhBase0 + cur * BUFSET;
            #pragma unroll
            for (int s = 0; s < 2; s++) {
                uint32_t af[2][4], bh2[2][4], bl2[2][4];
                #pragma unroll
                for (int i = 0; i < 2; i++)
                    ldm_x4(af[i], aBase + i * 16 * TPAD + s * 32);
                #pragma unroll
                for (int jj = 0; jj < 2; jj++) {
                    ldm_x4(bh2[jj], bhBase + jj * 16 * TPAD + s * 32);
                    ldm_x4(bl2[jj], bhBase + TILE_SM + jj * 16 * TPAD + s * 32);
                }
                #pragma unroll
                for (int i = 0; i < 2; i++)
                    #pragma unroll
                    for (int j = 0; j < 4; j++)
                        mma16816(acc[i][j], af[i], &bh2[j >> 1][(j & 1) * 2]);
                #pragma unroll
                for (int i = 0; i < 2; i++)
                    #pragma unroll
                    for (int j = 0; j < 4; j++)
                        mma16816(acc[i][j], af[i], &bl2[j >> 1][(j & 1) * 2]);
            }
            __syncthreads();
        }

        #pragma unroll
        for (int i = 0; i < 2; i++) {
            #pragma unroll
            for (int j = 0; j < 4; j++) {
                int gc = n0 + wn * 32 + j * 8 + qcol;
                #pragma unroll
                for (int half = 0; half < 2; half++) {
                    if (gc < Nact)
                        sacc[i][half] += tanhf(acc[i][j][half * 2 + 0] + bias[gc]) * proj[gc];
                    if (gc + 1 < Nact)
                        sacc[i][half] += tanhf(acc[i][j][half * 2 + 1] + bias[gc + 1]) * proj[gc + 1];
                }
            }
        }
    }

    #pragma unroll
    for (int i = 0; i < 2; i++)
        #pragma unroll
        for (int half = 0; half < 2; half++) {
            float v = sacc[i][half];
            v += __shfl_xor_sync(0xffffffffu, v, 1);
            v += __shfl_xor_sync(0xffffffffu, v, 2);
            sacc[i][half] = v;
        }

    __syncthreads();
    float* sred = (float*)sm;
    if ((lane & 3) == 0) {
        #pragma unroll
        for (int i = 0; i < 2; i++)
            #pragma unroll
            for (int half = 0; half < 2; half++) {
                int rl = wm * 32 + i * 16 + half * 8 + qrow;
                sred[rl * 4 + wn] = sacc[i][half];
            }
    }
    __syncthreads();
    if (tid < 128) {
        float s = sred[tid * 4] + sred[tid * 4 + 1] + sred[tid * 4 + 2] + sred[tid * 4 + 3];
        score[m0 + tid] = s;
    }
}

// ---------------- conversion / prep kernels ----------------
__device__ __forceinline__ void split_f16(float v, __half* H, __half* L, size_t i) {
    __half h = __float2half(v);
    H[i] = h;
    L[i] = __float2half(v - __half2float(h));
}

__global__ void k_zero(float* p, long long n) {
    long long i = (long long)blockIdx.x * blockDim.x + threadIdx.x;
    if (i < n) p[i] = 0.f;
}
__global__ void k_zero_h(uint32_t* a, int nw) {
    int i = blockIdx.x * 256 + threadIdx.x;
    if (i < nw) a[i] = 0u;
}

__global__ void k_conv_wih(const float* __restrict__ Wf, const float* __restrict__ Wr) {
    int idx = blockIdx.x * 256 + threadIdx.x;
    if (idx >= NIH * IND) return;
    int n = idx / IND, k = idx % IND;
    float v = (n < H3) ? Wf[(size_t)n * IND + k] : Wr[(size_t)(n - H3) * IND + k];
    split_f16(v, g_WihH, g_WihL, (size_t)n * KPAD_IN + k);
}

constexpr int CW_WHH = 2 * H3 * HID;
constexpr int CW_WW  = H2 * H2;
constexpr int CW_TOT = CW_WHH + 2 * CW_WW + NIH + 2 * H3;
__global__ void k_conv_rest(const float* __restrict__ Whf, const float* __restrict__ Whr,
                            const float* __restrict__ Ww, const float* __restrict__ Ws,
                            const float* __restrict__ bif, const float* __restrict__ bir,
                            const float* __restrict__ bhf, const float* __restrict__ bhr) {
    int idx = blockIdx.x * 256 + threadIdx.x;
    if (idx < CW_WHH) {
        int d = idx / (H3 * HID), r = idx % (H3 * HID);
        int n = r / HID, k = r % HID;
        const float* W = d ? Whr : Whf;
        split_f16(W[(size_t)n * HID + k], g_WhhH, g_WhhL,
                  ((size_t)d * NPAD_HH + n) * KPAD_H + k);
        return;
    }
    idx -= CW_WHH;
    if (idx < CW_WW) {
        int n = idx / H2, k = idx % H2;
        split_f16(Ww[(size_t)k * H2 + n], g_WwordH, g_WwordL, (size_t)n * KPAD_W + k);
        return;
    }
    idx -= CW_WW;
    if (idx < CW_WW) {
        int n = idx / H2, k = idx % H2;
        split_f16(Ws[(size_t)k * H2 + n], g_WsentH, g_WsentL, (size_t)n * KPAD_W + k);
        return;
    }
    idx -= CW_WW;
    if (idx < NIH) { g_bias_ih[idx] = (idx < H3) ? bif[idx] : bir[idx - H3]; return; }
    idx -= NIH;
    if (idx < 2 * H3) g_bias_hh[idx] = (idx < H3) ? bhf[idx] : bhr[idx - H3];
}

__global__ void k_conv_bag(const float* __restrict__ bag) {
    size_t idx = (size_t)blockIdx.x * 256 + threadIdx.x;
    if (idx >= (size_t)MM * (IND / 2)) return;
    int j = (int)(idx % (IND / 2));
    size_t m = idx / (IND / 2);
    int tt = (int)(m >> 12), b = (int)(m & 4095);
    float2 v = *(const float2*)(bag + ((size_t)b * TSTEPS + tt) * IND + 2 * j);
    __half2 h; h.x = __float2half(v.x); h.y = __float2half(v.y);
    *(__half2*)(g_bagF + m * KPAD_IN + 2 * j) = h;
}

// ---------------- GRU gate pointwise (fp16 state) ----------------
__global__ void k_gru_gate(int step) {
    int idx = blockIdx.x * 256 + threadIdx.x;
    if (idx >= 2 * BB * (HID / 2)) return;
    int d = idx / (BB * (HID / 2));
    int r = idx % (BB * (HID / 2));
    int b = r / (HID / 2), j = r % (HID / 2);
    int k = 2 * j;
    int t_eff = d ? (TSTEPS - 1 - step) : step;

    const float* xg = g_XG + ((size_t)t_eff * BB + b) * NIH + d * H3;
    const float* g  = g_G + ((size_t)d * BB + b) * H3;
    size_t hidx = ((size_t)d * BB + b) * KPAD_H + k;

    float2 xr = *(const float2*)(xg + k);
    float2 xz = *(const float2*)(xg + HID + k);
    float2 xn = *(const float2*)(xg + 2 * HID + k);
    float2 gr = *(const float2*)(g + k);
    float2 gz = *(const float2*)(g + HID + k);
    float2 gn = *(const float2*)(g + 2 * HID + k);

    __half2 hh = *(const __half2*)(g_hF + hidx);
    float hp0 = __half2float(hh.x);
    float hp1 = __half2float(hh.y);

    float rr0 = 1.f / (1.f + __expf(-(xr.x + gr.x)));
    float rr1 = 1.f / (1.f + __expf(-(xr.y + gr.y)));
    float zz0 = 1.f / (1.f + __expf(-(xz.x + gz.x)));
    float zz1 = 1.f / (1.f + __expf(-(xz.y + gz.y)));
    float nn0 = tanhf(xn.x + rr0 * gn.x);
    float nn1 = tanhf(xn.y + rr1 * gn.y);
    float h0 = (1.f - zz0) * nn0 + zz0 * hp0;
    float h1 = (1.f - zz1) * nn1 + zz1 * hp1;

    __half2 oh; oh.x = __float2half(h0); oh.y = __float2half(h1);
    *(__half2*)(g_hF + hidx) = oh;
    size_t oo = ((size_t)t_eff * BB + b) * KPAD_W + (size_t)d * HID + k;
    *(__half2*)(g_OUTF + oo) = oh;
}

// ---------------- attention tail kernels ----------------
__global__ void k_softmax_t(const float* __restrict__ score, float* __restrict__ alpha) {
    int b = blockIdx.x, t = threadIdx.x;
    __shared__ float sh[64];
    float v = score[t * BB + b];
    sh[t] = v; __syncthreads();
    #pragma unroll
    for (int o = 32; o; o >>= 1) { if (t < o) sh[t] = fmaxf(sh[t], sh[t + o]); __syncthreads(); }
    float mx = sh[0]; __syncthreads();
    float e = expf(v - mx);
    sh[t] = e; __syncthreads();
    #pragma unroll
    for (int o = 32; o; o >>= 1) { if (t < o) sh[t] += sh[t + o]; __syncthreads(); }
    alpha[t * BB + b] = e / sh[0];
}
__global__ void k_word_vec(const float* __restrict__ alpha) {
    int b = blockIdx.x;
    __shared__ float a[TSTEPS];
    if (threadIdx.x < TSTEPS) a[threadIdx.x] = alpha[threadIdx.x * BB + b];
    __syncthreads();
    for (int h = threadIdx.x; h < H2; h += blockDim.x) {
        float acc = 0.f;
        #pragma unroll 8
        for (int t = 0; t < TSTEPS; t++)
            acc += a[t] * __half2float(g_OUTF[((size_t)t * BB + b) * KPAD_W + h]);
        g_wv[(size_t)b * H2 + h] = acc;
        g_wvF[(size_t)b * KPAD_W + h] = __float2half(acc);
    }
}
__global__ void k_sent(const float* __restrict__ fcW, const float* __restrict__ fcb,
                       const int* __restrict__ pairs, float* __restrict__ out) {
    int nb = blockIdx.x;
    __shared__ float beta[MSENT];
    __shared__ float sv[H2];
    if (threadIdx.x == 0) {
        float v[MSENT], mx = -1e30f;
        #pragma unroll
        for (int s = 0; s < MSENT; s++) { v[s] = g_score2[nb * MSENT + s]; mx = fmaxf(mx, v[s]); }
        float sum = 0.f;
        #pragma unroll
        for (int s = 0; s < MSENT; s++) { v[s] = expf(v[s] - mx); sum += v[s]; }
        #pragma unroll
        for (int s = 0; s < MSENT; s++) beta[s] = v[s] / sum;
    }
    __syncthreads();
    for (int h = threadIdx.x; h < H2; h += blockDim.x) {
        float acc = 0.f;
        #pragma unroll
        for (int s = 0; s < MSENT; s++)
            acc += beta[s] * g_wv[((size_t)(nb * MSENT + s)) * H2 + h];
        sv[h] = acc;
    }
    __syncthreads();
    const int* p = pairs + nb * 3;
    int base = ((p[0] * ENT + p[1]) * ENT + p[2]) * OUTD;
    for (int o = threadIdx.x; o < OUTD; o += blockDim.x) {
        float acc = fcb[o];
        for (int h = 0; h < H2; h++) acc += sv[h] * fcW[(size_t)o * H2 + h];
        out[base + o] = acc;
    }
}

// ---------------- launcher ----------------
extern "C" void kernel_launch(void* const* d_in, const int* in_sizes, int n_in,
                              void* d_out, int out_size) {
    const float* bag       = (const float*)d_in[0];
    const float* W_ih_f    = (const float*)d_in[1];
    const float* W_hh_f    = (const float*)d_in[2];
    const float* b_ih_f    = (const float*)d_in[3];
    const float* b_hh_f    = (const float*)d_in[4];
    const float* W_ih_r    = (const float*)d_in[5];
    const float* W_hh_r    = (const float*)d_in[6];
    const float* b_ih_r    = (const float*)d_in[7];
    const float* b_hh_r    = (const float*)d_in[8];
    const float* W_word    = (const float*)d_in[9];
    const float* b_word    = (const float*)d_in[10];
    const float* proj_word = (const float*)d_in[11];
    const float* W_sent    = (const float*)d_in[12];
    const float* b_sent    = (const float*)d_in[13];
    const float* proj_sent = (const float*)d_in[14];
    const float* fc_W      = (const float*)d_in[15];
    const float* fc_b      = (const float*)d_in[16];
    const int*   pairs     = (const int*)d_in[17];
    float* out = (float*)d_out;

    static bool attr_set = false;
    if (!attr_set) {
        cudaFuncSetAttribute(gemm_f16s, cudaFuncAttributeMaxDynamicSharedMemorySize, SMEM_GEMM);
        cudaFuncSetAttribute(gemm_score, cudaFuncAttributeMaxDynamicSharedMemorySize, SMEM_GEMM);
        attr_set = true;
    }

    #define SYMA(p, s) void* p; cudaGetSymbolAddress(&p, s)
    SYMA(pXG, g_XG);     SYMA(pG, g_G);
    SYMA(pScore, g_score);
    SYMA(pAlpha, g_alpha); SYMA(pWv, g_wv);
    SYMA(pScore2, g_score2);
    SYMA(pBih, g_bias_ih); SYMA(pBhh, g_bias_hh);
    SYMA(pBagF, g_bagF);
    SYMA(pWihH, g_WihH); SYMA(pWihL, g_WihL);
    SYMA(pWhhH, g_WhhH); SYMA(pWhhL, g_WhhL);
    SYMA(pWwH, g_WwordH); SYMA(pWwL, g_WwordL);
    SYMA(pWsH, g_WsentH); SYMA(pWsL, g_WsentL);
    SYMA(pOF, g_OUTF);
    SYMA(phF, g_hF);
    SYMA(pwvF, g_wvF);
    #undef SYMA

    // ---- prep (3 launches), then input GEMM as launch #4 (ncu capture slot) ----
    k_conv_wih<<<(NIH * IND + 255) / 256, 256>>>(W_ih_f, W_ih_r);                       // 1
    k_conv_rest<<<(CW_TOT + 255) / 256, 256>>>(W_hh_f, W_hh_r, W_word, W_sent,          // 2
                                               b_ih_f, b_ih_r, b_hh_f, b_hh_r);
    {
        long long n = MM * (IND / 2);                                                   // 3
        k_conv_bag<<<(unsigned)((n + 255) / 256), 256>>>(bag);
    }
    {
        dim3 g(NPAD_IH / 128, (unsigned)(MM / 128), 1);                                 // 4
        gemm_f16s<<<g, 512, SMEM_GEMM>>>(
            (const __half*)pBagF,
            (const __half*)pWihH, (const __half*)pWihL,
            (const float*)pBih, (float*)pXG,
            NIH, NIH, KPAD_IN, KPAD_IN / 32, 0, 0, 0, 0);
    }
    {
        int nw = 2 * BB * KPAD_H / 2;                                                   // 5
        k_zero_h<<<(nw + 255) / 256, 256>>>((uint32_t*)phF, nw);
    }
    k_zero<<<(out_size + 255) / 256, 256>>>(out, (long long)out_size);                  // 6

    // ---- GRU recurrence ----
    {
        dim3 g(NPAD_HH / 128, BB / 128, 2);
        for (int s = 0; s < TSTEPS; s++) {
            gemm_f16s<<<g, 512, SMEM_GEMM>>>(
                (const __half*)phF,
                (const __half*)pWhhH, (const __half*)pWhhL,
                (const float*)pBhh, (float*)pG,
                H3, H3, KPAD_H, KPAD_H / 32,
                (long long)BB * KPAD_H, (long long)NPAD_HH * KPAD_H,
                (long long)H3, (long long)BB * H3);
            k_gru_gate<<<(2 * BB * (HID / 2) + 255) / 256, 256>>>(s);
        }
    }

    // ---- word attention: fused GEMM + tanh.proj score ----
    gemm_score<<<(unsigned)(MM / 128), 512, SMEM_GEMM>>>(
        (const __half*)pOF,
        (const __half*)pWwH, (const __half*)pWwL,
        b_word, proj_word, (float*)pScore, H2, KPAD_W, KPAD_W / 32, NPAD_W / 128);
    k_softmax_t<<<BB, 64>>>((const float*)pScore, (float*)pAlpha);
    k_word_vec<<<BB, 256>>>((const float*)pAlpha);

    // ---- sentence attention: fused GEMM + score, then softmax+FC+scatter ----
    gemm_score<<<BB / 128, 512, SMEM_GEMM>>>(
        (const __half*)pwvF,
        (const __half*)pWsH, (const __half*)pWsL,
        b_sent, proj_sent, (float*)pScore2, H2, KPAD_W, KPAD_W / 32, NPAD_W / 128);
    k_sent<<<NBAG, 256>>>(fc_W, fc_b, pairs, out);
}

// round 10
// speedup vs baseline: 3.6151x; 1.0835x over previous
#include <cuda_runtime.h>
#include <cuda_fp16.h>
#include <math.h>
#include <stdint.h>

// ---------------- problem constants ----------------
constexpr int NBAG   = 512;
constexpr int MSENT  = 8;
constexpr int TSTEPS = 64;
constexpr int IND    = 360;
constexpr int HID    = 230;
constexpr int OUTD   = 53;
constexpr int ENT    = 8;

constexpr int BB  = NBAG * MSENT;   // 4096
constexpr int H3  = 3 * HID;        // 690
constexpr int H2  = 2 * HID;        // 460
constexpr int NIH = 2 * H3;         // 1380
constexpr long long MM = (long long)TSTEPS * BB;  // 262144

constexpr int KPAD_IN = 384;
constexpr int NPAD_IH = 1408;
constexpr int KPAD_H  = 256;
constexpr int NPAD_HH = 768;
constexpr int KPAD_W  = 512;
constexpr int NPAD_W  = 512;

// ---------------- device scratch ----------------
__device__ float g_bias_ih[NIH];
__device__ float g_bias_hh[2 * H3];
__device__ __half g_XGh[(size_t)MM * NIH];        // x@W_ih^T + b, fp16
__device__ __half g_Gh[(size_t)2 * BB * H3];      // h@W_hh^T + b, fp16
__device__ float g_score[TSTEPS * BB];
__device__ float g_wv[(size_t)BB * H2];
__device__ float g_score2[BB];

// A-side: single fp16 (error 2^-12). B-side (weights): fp16 hi+lo split.
__device__ __half g_bagF[(size_t)MM * KPAD_IN];
__device__ __half g_WihH[(size_t)NPAD_IH * KPAD_IN];
__device__ __half g_WihL[(size_t)NPAD_IH * KPAD_IN];
__device__ __half g_WhhH[(size_t)2 * NPAD_HH * KPAD_H];
__device__ __half g_WhhL[(size_t)2 * NPAD_HH * KPAD_H];
__device__ __half g_WwordH[(size_t)NPAD_W * KPAD_W];
__device__ __half g_WwordL[(size_t)NPAD_W * KPAD_W];
__device__ __half g_WsentH[(size_t)NPAD_W * KPAD_W];
__device__ __half g_WsentL[(size_t)NPAD_W * KPAD_W];
__device__ __half g_OUTF[(size_t)MM * KPAD_W];
__device__ __half g_hF[(size_t)2 * BB * KPAD_H];
__device__ __half g_wvF[(size_t)BB * KPAD_W];

// ---------------- helpers ----------------
__device__ __forceinline__ uint32_t smem_u32(const void* p) {
    uint32_t a;
    asm("{ .reg .u64 t; cvta.to.shared.u64 t, %1; cvt.u32.u64 %0, t; }" : "=r"(a) : "l"(p));
    return a;
}
__device__ __forceinline__ void ldm_x4(uint32_t* r, uint32_t addr) {
    asm volatile("ldmatrix.sync.aligned.m8n8.x4.shared.b16 {%0,%1,%2,%3}, [%4];"
                 : "=r"(r[0]), "=r"(r[1]), "=r"(r[2]), "=r"(r[3]) : "r"(addr));
}
__device__ __forceinline__ void mma16816(float* d, const uint32_t* a, const uint32_t* b) {
    asm volatile("mma.sync.aligned.m16n8k16.row.col.f32.f16.f16.f32 "
                 "{%0,%1,%2,%3}, {%4,%5,%6,%7}, {%8,%9}, {%0,%1,%2,%3};"
                 : "+f"(d[0]), "+f"(d[1]), "+f"(d[2]), "+f"(d[3])
                 : "r"(a[0]), "r"(a[1]), "r"(a[2]), "r"(a[3]), "r"(b[0]), "r"(b[1]));
}
__device__ __forceinline__ void cp_async16(uint32_t saddr, const void* gaddr) {
    asm volatile("cp.async.cg.shared.global [%0], [%1], 16;" :: "r"(saddr), "l"(gaddr));
}
#define CP_COMMIT() asm volatile("cp.async.commit_group;" ::: "memory")
#define CP_WAIT1()  asm volatile("cp.async.wait_group 1;" ::: "memory")

constexpr int TPAD    = 80;
constexpr int TILE_SM = 128 * TPAD;        // 10240
constexpr int BUFSET  = 3 * TILE_SM;       // 30720 (Af, Bh, Bl)
constexpr int NBUF    = 3;
constexpr int SMEM_GEMM = NBUF * BUFSET;   // 92160 (2 CTAs -> 184 KB/SM, fits)

// ---------------- fp16 2-pass GEMM: C(half) = Af @ (Bh+Bl)^T + bias ----------------
// 3-stage cp.async pipeline, 512 thr, 128x128 tile, warp grid 4x4, BK=32.
__global__ void __launch_bounds__(512, 2)
gemm_f16s(const __half* __restrict__ Af, const __half* __restrict__ Bh,
          const __half* __restrict__ Bl,
          const float* __restrict__ bias, __half* __restrict__ C,
          int N, int ldc, int Kpad, int nit,
          long long sA, long long sB, long long sBias, long long sC)
{
    extern __shared__ __align__(16) unsigned char sm[];

    int tid = threadIdx.x;
    int lane = tid & 31, wid = tid >> 5;
    int wm = wid >> 2, wn = wid & 3;

    long long z = blockIdx.z;
    Af += z * sA;
    Bh += z * sB;  Bl += z * sB;
    bias += z * sBias;
    C  += z * sC;

    int m0 = blockIdx.y * 128, n0 = blockIdx.x * 128;

    int r0 = tid >> 2, c4 = tid & 3;
    const __half* srcA  = Af + (size_t)(m0 + r0) * Kpad + c4 * 8;
    const __half* srcBh = Bh + (size_t)(n0 + r0) * Kpad + c4 * 8;
    const __half* srcBl = Bl + (size_t)(n0 + r0) * Kpad + c4 * 8;

    uint32_t smb = smem_u32(sm);
    uint32_t sdst = smb + r0 * TPAD + c4 * 16;

    float acc[2][4][4];
    #pragma unroll
    for (int i = 0; i < 2; i++)
        #pragma unroll
        for (int j = 0; j < 4; j++)
            #pragma unroll
            for (int q = 0; q < 4; q++) acc[i][j][q] = 0.f;

    int arow = (lane & 7) + (((lane >> 3) & 1) << 3);
    int acolb = ((lane >> 4) & 1) * 16;
    uint32_t aBase0 = smb + (wm * 32 + arow) * TPAD + acolb;
    int brow = (lane & 7) + (((lane >> 4) & 1) << 3);
    int bcolb = ((lane >> 3) & 1) * 16;
    uint32_t bhBase0 = smb + TILE_SM + (wn * 32 + brow) * TPAD + bcolb;

    // prologue: chunks 0,1 -> buf 0,1   (nit >= 2 always)
    cp_async16(sdst,               srcA);
    cp_async16(sdst + TILE_SM,     srcBh);
    cp_async16(sdst + 2 * TILE_SM, srcBl);
    CP_COMMIT();
    cp_async16(sdst + BUFSET,               srcA + 32);
    cp_async16(sdst + BUFSET + TILE_SM,     srcBh + 32);
    cp_async16(sdst + BUFSET + 2 * TILE_SM, srcBl + 32);
    CP_COMMIT();

    int cur = 0;
    for (int kc = 0; kc < nit; kc++) {
        CP_WAIT1();              // chunk kc complete (<=1 newer group pending)
        __syncthreads();         // also guards smem reuse: all warps done with buf cur

        if (kc + 2 < nit) {
            int nb3 = cur + 2; if (nb3 >= NBUF) nb3 -= NBUF;
            uint32_t d = sdst + nb3 * BUFSET;
            int off = (kc + 2) * 32;
            cp_async16(d,               srcA + off);
            cp_async16(d + TILE_SM,     srcBh + off);
            cp_async16(d + 2 * TILE_SM, srcBl + off);
            CP_COMMIT();
        } else {
            CP_COMMIT();         // empty group keeps wait_group accounting valid
        }

        uint32_t aBase  = aBase0  + cur * BUFSET;
        uint32_t bhBase = bhBase0 + cur * BUFSET;
        #pragma unroll
        for (int s = 0; s < 2; s++) {
            uint32_t af[2][4], bh2[2][4], bl2[2][4];
            #pragma unroll
            for (int i = 0; i < 2; i++)
                ldm_x4(af[i], aBase + i * 16 * TPAD + s * 32);
            #pragma unroll
            for (int jj = 0; jj < 2; jj++) {
                ldm_x4(bh2[jj], bhBase + jj * 16 * TPAD + s * 32);
                ldm_x4(bl2[jj], bhBase + TILE_SM + jj * 16 * TPAD + s * 32);
            }
            #pragma unroll
            for (int i = 0; i < 2; i++)
                #pragma unroll
                for (int j = 0; j < 4; j++)
                    mma16816(acc[i][j], af[i], &bh2[j >> 1][(j & 1) * 2]);
            #pragma unroll
            for (int i = 0; i < 2; i++)
                #pragma unroll
                for (int j = 0; j < 4; j++)
                    mma16816(acc[i][j], af[i], &bl2[j >> 1][(j & 1) * 2]);
        }
        if (++cur == NBUF) cur = 0;
    }

    // epilogue: fp16 paired stores (N even, qcol even -> pair-aligned)
    int qrow = lane >> 2, qcol = (lane & 3) * 2;
    #pragma unroll
    for (int i = 0; i < 2; i++) {
        #pragma unroll
        for (int j = 0; j < 4; j++) {
            int gc = n0 + wn * 32 + j * 8 + qcol;
            #pragma unroll
            for (int half = 0; half < 2; half++) {
                int gr = m0 + wm * 32 + i * 16 + qrow + half * 8;
                if (gc + 1 < N) {
                    __half2 hv;
                    hv.x = __float2half(acc[i][j][half * 2 + 0] + bias[gc]);
                    hv.y = __float2half(acc[i][j][half * 2 + 1] + bias[gc + 1]);
                    *(__half2*)(C + (size_t)gr * ldc + gc) = hv;
                }
            }
        }
    }
}

// ---------------- fp16 2-pass GEMM with fused score epilogue ----------------
// score[m] = sum_n tanh((A@B^T)[m,n] + bias[n]) * proj[n], n < Nact.
__global__ void __launch_bounds__(512, 2)
gemm_score(const __half* __restrict__ Af, const __half* __restrict__ Bh,
           const __half* __restrict__ Bl,
           const float* __restrict__ bias, const float* __restrict__ proj,
           float* __restrict__ score, int Nact, int Kpad, int nit, int nbt)
{
    extern __shared__ __align__(16) unsigned char sm[];

    int tid = threadIdx.x;
    int lane = tid & 31, wid = tid >> 5;
    int wm = wid >> 2, wn = wid & 3;
    int m0 = blockIdx.x * 128;

    int r0 = tid >> 2, c4 = tid & 3;
    const __half* srcA = Af + (size_t)(m0 + r0) * Kpad + c4 * 8;

    uint32_t smb = smem_u32(sm);
    uint32_t sdst = smb + r0 * TPAD + c4 * 16;

    int arow = (lane & 7) + (((lane >> 3) & 1) << 3);
    int acolb = ((lane >> 4) & 1) * 16;
    uint32_t aBase0 = smb + (wm * 32 + arow) * TPAD + acolb;
    int brow = (lane & 7) + (((lane >> 4) & 1) << 3);
    int bcolb = ((lane >> 3) & 1) * 16;
    uint32_t bhBase0 = smb + TILE_SM + (wn * 32 + brow) * TPAD + bcolb;

    int qrow = lane >> 2, qcol = (lane & 3) * 2;
    float sacc[2][2] = {{0.f, 0.f}, {0.f, 0.f}};

    for (int nb = 0; nb < nbt; nb++) {
        int n0 = nb * 128;
        const __half* srcBh = Bh + (size_t)(n0 + r0) * Kpad + c4 * 8;
        const __half* srcBl = Bl + (size_t)(n0 + r0) * Kpad + c4 * 8;

        float acc[2][4][4];
        #pragma unroll
        for (int i = 0; i < 2; i++)
            #pragma unroll
            for (int j = 0; j < 4; j++)
                #pragma unroll
                for (int q = 0; q < 4; q++) acc[i][j][q] = 0.f;

        __syncthreads();   // all warps done with previous nb's smem

        cp_async16(sdst,               srcA);
        cp_async16(sdst + TILE_SM,     srcBh);
        cp_async16(sdst + 2 * TILE_SM, srcBl);
        CP_COMMIT();
        cp_async16(sdst + BUFSET,               srcA + 32);
        cp_async16(sdst + BUFSET + TILE_SM,     srcBh + 32);
        cp_async16(sdst + BUFSET + 2 * TILE_SM, srcBl + 32);
        CP_COMMIT();

        int cur = 0;
        for (int kc = 0; kc < nit; kc++) {
            CP_WAIT1();
            __syncthreads();

            if (kc + 2 < nit) {
                int nb3 = cur + 2; if (nb3 >= NBUF) nb3 -= NBUF;
                uint32_t d = sdst + nb3 * BUFSET;
                int off = (kc + 2) * 32;
                cp_async16(d,               srcA + off);
                cp_async16(d + TILE_SM,     srcBh + off);
                cp_async16(d + 2 * TILE_SM, srcBl + off);
                CP_COMMIT();
            } else {
                CP_COMMIT();
            }

            uint32_t aBase  = aBase0  + cur * BUFSET;
            uint32_t bhBase = bhBase0 + cur * BUFSET;
            #pragma unroll
            for (int s = 0; s < 2; s++) {
                uint32_t af[2][4], bh2[2][4], bl2[2][4];
                #pragma unroll
                for (int i = 0; i < 2; i++)
                    ldm_x4(af[i], aBase + i * 16 * TPAD + s * 32);
                #pragma unroll
                for (int jj = 0; jj < 2; jj++) {
                    ldm_x4(bh2[jj], bhBase + jj * 16 * TPAD + s * 32);
                    ldm_x4(bl2[jj], bhBase + TILE_SM + jj * 16 * TPAD + s * 32);
                }
                #pragma unroll
                for (int i = 0; i < 2; i++)
                    #pragma unroll
                    for (int j = 0; j < 4; j++)
                        mma16816(acc[i][j], af[i], &bh2[j >> 1][(j & 1) * 2]);
                #pragma unroll
                for (int i = 0; i < 2; i++)
                    #pragma unroll
                    for (int j = 0; j < 4; j++)
                        mma16816(acc[i][j], af[i], &bl2[j >> 1][(j & 1) * 2]);
            }
            if (++cur == NBUF) cur = 0;
        }

        #pragma unroll
        for (int i = 0; i < 2; i++) {
            #pragma unroll
            for (int j = 0; j < 4; j++) {
                int gc = n0 + wn * 32 + j * 8 + qcol;
                #pragma unroll
                for (int half = 0; half < 2; half++) {
                    if (gc < Nact)
                        sacc[i][half] += tanhf(acc[i][j][half * 2 + 0] + bias[gc]) * proj[gc];
                    if (gc + 1 < Nact)
                        sacc[i][half] += tanhf(acc[i][j][half * 2 + 1] + bias[gc + 1]) * proj[gc + 1];
                }
            }
        }
    }

    #pragma unroll
    for (int i = 0; i < 2; i++)
        #pragma unroll
        for (int half = 0; half < 2; half++) {
            float v = sacc[i][half];
            v += __shfl_xor_sync(0xffffffffu, v, 1);
            v += __shfl_xor_sync(0xffffffffu, v, 2);
            sacc[i][half] = v;
        }

    __syncthreads();
    float* sred = (float*)sm;
    if ((lane & 3) == 0) {
        #pragma unroll
        for (int i = 0; i < 2; i++)
            #pragma unroll
            for (int half = 0; half < 2; half++) {
                int rl = wm * 32 + i * 16 + half * 8 + qrow;
                sred[rl * 4 + wn] = sacc[i][half];
            }
    }
    __syncthreads();
    if (tid < 128) {
        float s = sred[tid * 4] + sred[tid * 4 + 1] + sred[tid * 4 + 2] + sred[tid * 4 + 3];
        score[m0 + tid] = s;
    }
}

// ---------------- conversion / prep kernels ----------------
__device__ __forceinline__ void split_f16(float v, __half* H, __half* L, size_t i) {
    __half h = __float2half(v);
    H[i] = h;
    L[i] = __float2half(v - __half2float(h));
}

__global__ void k_zero(float* p, long long n) {
    long long i = (long long)blockIdx.x * blockDim.x + threadIdx.x;
    if (i < n) p[i] = 0.f;
}
__global__ void k_zero_h(uint32_t* a, int nw) {
    int i = blockIdx.x * 256 + threadIdx.x;
    if (i < nw) a[i] = 0u;
}

__global__ void k_conv_wih(const float* __restrict__ Wf, const float* __restrict__ Wr) {
    int idx = blockIdx.x * 256 + threadIdx.x;
    if (idx >= NIH * IND) return;
    int n = idx / IND, k = idx % IND;
    float v = (n < H3) ? Wf[(size_t)n * IND + k] : Wr[(size_t)(n - H3) * IND + k];
    split_f16(v, g_WihH, g_WihL, (size_t)n * KPAD_IN + k);
}

constexpr int CW_WHH = 2 * H3 * HID;
constexpr int CW_WW  = H2 * H2;
constexpr int CW_TOT = CW_WHH + 2 * CW_WW + NIH + 2 * H3;
__global__ void k_conv_rest(const float* __restrict__ Whf, const float* __restrict__ Whr,
                            const float* __restrict__ Ww, const float* __restrict__ Ws,
                            const float* __restrict__ bif, const float* __restrict__ bir,
                            const float* __restrict__ bhf, const float* __restrict__ bhr) {
    int idx = blockIdx.x * 256 + threadIdx.x;
    if (idx < CW_WHH) {
        int d = idx / (H3 * HID), r = idx % (H3 * HID);
        int n = r / HID, k = r % HID;
        const float* W = d ? Whr : Whf;
        split_f16(W[(size_t)n * HID + k], g_WhhH, g_WhhL,
                  ((size_t)d * NPAD_HH + n) * KPAD_H + k);
        return;
    }
    idx -= CW_WHH;
    if (idx < CW_WW) {
        int n = idx / H2, k = idx % H2;
        split_f16(Ww[(size_t)k * H2 + n], g_WwordH, g_WwordL, (size_t)n * KPAD_W + k);
        return;
    }
    idx -= CW_WW;
    if (idx < CW_WW) {
        int n = idx / H2, k = idx % H2;
        split_f16(Ws[(size_t)k * H2 + n], g_WsentH, g_WsentL, (size_t)n * KPAD_W + k);
        return;
    }
    idx -= CW_WW;
    if (idx < NIH) { g_bias_ih[idx] = (idx < H3) ? bif[idx] : bir[idx - H3]; return; }
    idx -= NIH;
    if (idx < 2 * H3) g_bias_hh[idx] = (idx < H3) ? bhf[idx] : bhr[idx - H3];
}

__global__ void k_conv_bag(const float* __restrict__ bag) {
    size_t idx = (size_t)blockIdx.x * 256 + threadIdx.x;
    if (idx >= (size_t)MM * (IND / 2)) return;
    int j = (int)(idx % (IND / 2));
    size_t m = idx / (IND / 2);
    int tt = (int)(m >> 12), b = (int)(m & 4095);
    float2 v = *(const float2*)(bag + ((size_t)b * TSTEPS + tt) * IND + 2 * j);
    __half2 h; h.x = __float2half(v.x); h.y = __float2half(v.y);
    *(__half2*)(g_bagF + m * KPAD_IN + 2 * j) = h;
}

// ---------------- GRU gate pointwise (fp16 state + fp16 xg/g) ----------------
__global__ void k_gru_gate(int step) {
    int idx = blockIdx.x * 256 + threadIdx.x;
    if (idx >= 2 * BB * (HID / 2)) return;
    int d = idx / (BB * (HID / 2));
    int r = idx % (BB * (HID / 2));
    int b = r / (HID / 2), j = r % (HID / 2);
    int k = 2 * j;
    int t_eff = d ? (TSTEPS - 1 - step) : step;

    const __half* xg = g_XGh + ((size_t)t_eff * BB + b) * NIH + d * H3;
    const __half* g  = g_Gh + ((size_t)d * BB + b) * H3;
    size_t hidx = ((size_t)d * BB + b) * KPAD_H + k;

    float2 xr = __half22float2(*(const __half2*)(xg + k));
    float2 xz = __half22float2(*(const __half2*)(xg + HID + k));
    float2 xn = __half22float2(*(const __half2*)(xg + 2 * HID + k));
    float2 gr = __half22float2(*(const __half2*)(g + k));
    float2 gz = __half22float2(*(const __half2*)(g + HID + k));
    float2 gn = __half22float2(*(const __half2*)(g + 2 * HID + k));

    __half2 hh = *(const __half2*)(g_hF + hidx);
    float hp0 = __half2float(hh.x);
    float hp1 = __half2float(hh.y);

    float rr0 = 1.f / (1.f + __expf(-(xr.x + gr.x)));
    float rr1 = 1.f / (1.f + __expf(-(xr.y + gr.y)));
    float zz0 = 1.f / (1.f + __expf(-(xz.x + gz.x)));
    float zz1 = 1.f / (1.f + __expf(-(xz.y + gz.y)));
    float nn0 = tanhf(xn.x + rr0 * gn.x);
    float nn1 = tanhf(xn.y + rr1 * gn.y);
    float h0 = (1.f - zz0) * nn0 + zz0 * hp0;
    float h1 = (1.f - zz1) * nn1 + zz1 * hp1;

    __half2 oh; oh.x = __float2half(h0); oh.y = __float2half(h1);
    *(__half2*)(g_hF + hidx) = oh;
    size_t oo = ((size_t)t_eff * BB + b) * KPAD_W + (size_t)d * HID + k;
    *(__half2*)(g_OUTF + oo) = oh;
}

// ---------------- fused softmax-over-t + word_vec ----------------
__global__ void k_word_attn() {
    int b = blockIdx.x;
    int tid = threadIdx.x;
    __shared__ float sh[TSTEPS];
    __shared__ float al[TSTEPS];
    if (tid < TSTEPS) {
        float v = g_score[tid * BB + b];
        al[tid] = v; sh[tid] = v;
    }
    __syncthreads();
    #pragma unroll
    for (int o = 32; o; o >>= 1) {
        if (tid < o) sh[tid] = fmaxf(sh[tid], sh[tid + o]);
        __syncthreads();
    }
    float mx = sh[0];
    __syncthreads();
    if (tid < TSTEPS) {
        float e = __expf(al[tid] - mx);
        al[tid] = e; sh[tid] = e;
    }
    __syncthreads();
    #pragma unroll
    for (int o = 32; o; o >>= 1) {
        if (tid < o) sh[tid] += sh[tid + o];
        __syncthreads();
    }
    float inv = 1.f / sh[0];
    __syncthreads();
    if (tid < TSTEPS) al[tid] *= inv;
    __syncthreads();

    for (int h = tid; h < H2; h += blockDim.x) {
        float acc = 0.f;
        #pragma unroll 8
        for (int t = 0; t < TSTEPS; t++)
            acc += al[t] * __half2float(g_OUTF[((size_t)t * BB + b) * KPAD_W + h]);
        g_wv[(size_t)b * H2 + h] = acc;
        g_wvF[(size_t)b * KPAD_W + h] = __float2half(acc);
    }
}

// ---------------- sentence softmax + weighted sum + FC + scatter ----------------
__global__ void k_sent(const float* __restrict__ fcW, const float* __restrict__ fcb,
                       const int* __restrict__ pairs, float* __restrict__ out) {
    int nb = blockIdx.x;
    __shared__ float beta[MSENT];
    __shared__ float sv[H2];
    if (threadIdx.x == 0) {
        float v[MSENT], mx = -1e30f;
        #pragma unroll
        for (int s = 0; s < MSENT; s++) { v[s] = g_score2[nb * MSENT + s]; mx = fmaxf(mx, v[s]); }
        float sum = 0.f;
        #pragma unroll
        for (int s = 0; s < MSENT; s++) { v[s] = expf(v[s] - mx); sum += v[s]; }
        #pragma unroll
        for (int s = 0; s < MSENT; s++) beta[s] = v[s] / sum;
    }
    __syncthreads();
    for (int h = threadIdx.x; h < H2; h += blockDim.x) {
        float acc = 0.f;
        #pragma unroll
        for (int s = 0; s < MSENT; s++)
            acc += beta[s] * g_wv[((size_t)(nb * MSENT + s)) * H2 + h];
        sv[h] = acc;
    }
    __syncthreads();
    const int* p = pairs + nb * 3;
    int base = ((p[0] * ENT + p[1]) * ENT + p[2]) * OUTD;
    for (int o = threadIdx.x; o < OUTD; o += blockDim.x) {
        float acc = fcb[o];
        for (int h = 0; h < H2; h++) acc += sv[h] * fcW[(size_t)o * H2 + h];
        out[base + o] = acc;
    }
}

// ---------------- launcher ----------------
extern "C" void kernel_launch(void* const* d_in, const int* in_sizes, int n_in,
                              void* d_out, int out_size) {
    const float* bag       = (const float*)d_in[0];
    const float* W_ih_f    = (const float*)d_in[1];
    const float* W_hh_f    = (const float*)d_in[2];
    const float* b_ih_f    = (const float*)d_in[3];
    const float* b_hh_f    = (const float*)d_in[4];
    const float* W_ih_r    = (const float*)d_in[5];
    const float* W_hh_r    = (const float*)d_in[6];
    const float* b_ih_r    = (const float*)d_in[7];
    const float* b_hh_r    = (const float*)d_in[8];
    const float* W_word    = (const float*)d_in[9];
    const float* b_word    = (const float*)d_in[10];
    const float* proj_word = (const float*)d_in[11];
    const float* W_sent    = (const float*)d_in[12];
    const float* b_sent    = (const float*)d_in[13];
    const float* proj_sent = (const float*)d_in[14];
    const float* fc_W      = (const float*)d_in[15];
    const float* fc_b      = (const float*)d_in[16];
    const int*   pairs     = (const int*)d_in[17];
    float* out = (float*)d_out;

    static bool attr_set = false;
    if (!attr_set) {
        cudaFuncSetAttribute(gemm_f16s, cudaFuncAttributeMaxDynamicSharedMemorySize, SMEM_GEMM);
        cudaFuncSetAttribute(gemm_score, cudaFuncAttributeMaxDynamicSharedMemorySize, SMEM_GEMM);
        attr_set = true;
    }

    #define SYMA(p, s) void* p; cudaGetSymbolAddress(&p, s)
    SYMA(pXG, g_XGh);    SYMA(pG, g_Gh);
    SYMA(pScore, g_score);
    SYMA(pWv, g_wv);
    SYMA(pScore2, g_score2);
    SYMA(pBih, g_bias_ih); SYMA(pBhh, g_bias_hh);
    SYMA(pBagF, g_bagF);
    SYMA(pWihH, g_WihH); SYMA(pWihL, g_WihL);
    SYMA(pWhhH, g_WhhH); SYMA(pWhhL, g_WhhL);
    SYMA(pWwH, g_WwordH); SYMA(pWwL, g_WwordL);
    SYMA(pWsH, g_WsentH); SYMA(pWsL, g_WsentL);
    SYMA(pOF, g_OUTF);
    SYMA(phF, g_hF);
    SYMA(pwvF, g_wvF);
    #undef SYMA

    // ---- prep (3 launches), then input GEMM as launch #4 (ncu capture slot) ----
    k_conv_wih<<<(NIH * IND + 255) / 256, 256>>>(W_ih_f, W_ih_r);                       // 1
    k_conv_rest<<<(CW_TOT + 255) / 256, 256>>>(W_hh_f, W_hh_r, W_word, W_sent,          // 2
                                               b_ih_f, b_ih_r, b_hh_f, b_hh_r);
    {
        long long n = MM * (IND / 2);                                                   // 3
        k_conv_bag<<<(unsigned)((n + 255) / 256), 256>>>(bag);
    }
    {
        dim3 g(NPAD_IH / 128, (unsigned)(MM / 128), 1);                                 // 4
        gemm_f16s<<<g, 512, SMEM_GEMM>>>(
            (const __half*)pBagF,
            (const __half*)pWihH, (const __half*)pWihL,
            (const float*)pBih, (__half*)pXG,
            NIH, NIH, KPAD_IN, KPAD_IN / 32, 0, 0, 0, 0);
    }
    {
        int nw = 2 * BB * KPAD_H / 2;                                                   // 5
        k_zero_h<<<(nw + 255) / 256, 256>>>((uint32_t*)phF, nw);
    }
    k_zero<<<(out_size + 255) / 256, 256>>>(out, (long long)out_size);                  // 6

    // ---- GRU recurrence ----
    {
        dim3 g(NPAD_HH / 128, BB / 128, 2);
        for (int s = 0; s < TSTEPS; s++) {
            gemm_f16s<<<g, 512, SMEM_GEMM>>>(
                (const __half*)phF,
                (const __half*)pWhhH, (const __half*)pWhhL,
                (const float*)pBhh, (__half*)pG,
                H3, H3, KPAD_H, KPAD_H / 32,
                (long long)BB * KPAD_H, (long long)NPAD_HH * KPAD_H,
                (long long)H3, (long long)BB * H3);
            k_gru_gate<<<(2 * BB * (HID / 2) + 255) / 256, 256>>>(s);
        }
    }

    // ---- word attention: fused GEMM + tanh.proj score, fused softmax+wv ----
    gemm_score<<<(unsigned)(MM / 128), 512, SMEM_GEMM>>>(
        (const __half*)pOF,
        (const __half*)pWwH, (const __half*)pWwL,
        b_word, proj_word, (float*)pScore, H2, KPAD_W, KPAD_W / 32, NPAD_W / 128);
    k_word_attn<<<BB, 256>>>();

    // ---- sentence attention: fused GEMM + score, then softmax+FC+scatter ----
    gemm_score<<<BB / 128, 512, SMEM_GEMM>>>(
        (const __half*)pwvF,
        (const __half*)pWsH, (const __half*)pWsL,
        b_sent, proj_sent, (float*)pScore2, H2, KPAD_W, KPAD_W / 32, NPAD_W / 128);
    k_sent<<<NBAG, 256>>>(fc_W, fc_b, pairs, out);
}

// round 11
// speedup vs baseline: 3.8386x; 1.0618x over previous
#include <cuda_runtime.h>
#include <cuda_fp16.h>
#include <math.h>
#include <stdint.h>

// ---------------- problem constants ----------------
constexpr int NBAG   = 512;
constexpr int MSENT  = 8;
constexpr int TSTEPS = 64;
constexpr int IND    = 360;
constexpr int HID    = 230;
constexpr int OUTD   = 53;
constexpr int ENT    = 8;

constexpr int BB  = NBAG * MSENT;   // 4096
constexpr int H3  = 3 * HID;        // 690
constexpr int H2  = 2 * HID;        // 460
constexpr int NIH = 2 * H3;         // 1380
constexpr long long MM = (long long)TSTEPS * BB;  // 262144

constexpr int KPAD_IN = 384;
constexpr int NPAD_IH = 1408;
constexpr int KPAD_H  = 256;
constexpr int NI_GRU  = 1024;   // interleaved W_hh rows per dir: 32 groups x [r8|z8|n8|pad8]
constexpr int KPAD_W  = 512;
constexpr int NPAD_W  = 512;

// ---------------- device scratch ----------------
__device__ float g_bias_ih[NIH];
__device__ float g_bias_hh[2 * H3];
__device__ __half g_XGh[(size_t)MM * NIH];        // x@W_ih^T + b_ih, fp16
__device__ float g_score[TSTEPS * BB];
__device__ float g_wv[(size_t)BB * H2];
__device__ float g_score2[BB];

// A-side: single fp16. B-side (weights): fp16 hi+lo split.
__device__ __half g_bagF[(size_t)MM * KPAD_IN];
__device__ __half g_WihH[(size_t)NPAD_IH * KPAD_IN];
__device__ __half g_WihL[(size_t)NPAD_IH * KPAD_IN];
__device__ __half g_WhhIH[(size_t)2 * NI_GRU * KPAD_H];   // gate-interleaved
__device__ __half g_WhhIL[(size_t)2 * NI_GRU * KPAD_H];
__device__ __half g_WwordH[(size_t)NPAD_W * KPAD_W];
__device__ __half g_WwordL[(size_t)NPAD_W * KPAD_W];
__device__ __half g_WsentH[(size_t)NPAD_W * KPAD_W];
__device__ __half g_WsentL[(size_t)NPAD_W * KPAD_W];
__device__ __half g_OUTF[(size_t)MM * KPAD_W];
__device__ __half g_hA[(size_t)2 * BB * KPAD_H];          // double-buffered hidden state
__device__ __half g_hB[(size_t)2 * BB * KPAD_H];
__device__ __half g_wvF[(size_t)BB * KPAD_W];

// ---------------- helpers ----------------
__device__ __forceinline__ uint32_t smem_u32(const void* p) {
    uint32_t a;
    asm("{ .reg .u64 t; cvta.to.shared.u64 t, %1; cvt.u32.u64 %0, t; }" : "=r"(a) : "l"(p));
    return a;
}
__device__ __forceinline__ void ldm_x4(uint32_t* r, uint32_t addr) {
    asm volatile("ldmatrix.sync.aligned.m8n8.x4.shared.b16 {%0,%1,%2,%3}, [%4];"
                 : "=r"(r[0]), "=r"(r[1]), "=r"(r[2]), "=r"(r[3]) : "r"(addr));
}
__device__ __forceinline__ void mma16816(float* d, const uint32_t* a, const uint32_t* b) {
    asm volatile("mma.sync.aligned.m16n8k16.row.col.f32.f16.f16.f32 "
                 "{%0,%1,%2,%3}, {%4,%5,%6,%7}, {%8,%9}, {%0,%1,%2,%3};"
                 : "+f"(d[0]), "+f"(d[1]), "+f"(d[2]), "+f"(d[3])
                 : "r"(a[0]), "r"(a[1]), "r"(a[2]), "r"(a[3]), "r"(b[0]), "r"(b[1]));
}
__device__ __forceinline__ void cp_async16(uint32_t saddr, const void* gaddr) {
    asm volatile("cp.async.cg.shared.global [%0], [%1], 16;" :: "r"(saddr), "l"(gaddr));
}
#define CP_COMMIT() asm volatile("cp.async.commit_group;" ::: "memory")
#define CP_WAIT1()  asm volatile("cp.async.wait_group 1;" ::: "memory")

constexpr int TPAD    = 80;
constexpr int TILE_SM = 128 * TPAD;        // 10240
constexpr int BUFSET  = 3 * TILE_SM;       // 30720 (Af, Bh, Bl)
constexpr int NBUF    = 3;
constexpr int SMEM_GEMM = NBUF * BUFSET;   // 92160 (2 CTAs -> 184 KB/SM)

// ---------------- fp16 2-pass GEMM: C(half) = Af @ (Bh+Bl)^T + bias ----------------
__global__ void __launch_bounds__(512, 2)
gemm_f16s(const __half* __restrict__ Af, const __half* __restrict__ Bh,
          const __half* __restrict__ Bl,
          const float* __restrict__ bias, __half* __restrict__ C,
          int N, int ldc, int Kpad, int nit)
{
    extern __shared__ __align__(16) unsigned char sm[];

    int tid = threadIdx.x;
    int lane = tid & 31, wid = tid >> 5;
    int wm = wid >> 2, wn = wid & 3;

    int m0 = blockIdx.y * 128, n0 = blockIdx.x * 128;

    int r0 = tid >> 2, c4 = tid & 3;
    const __half* srcA  = Af + (size_t)(m0 + r0) * Kpad + c4 * 8;
    const __half* srcBh = Bh + (size_t)(n0 + r0) * Kpad + c4 * 8;
    const __half* srcBl = Bl + (size_t)(n0 + r0) * Kpad + c4 * 8;

    uint32_t smb = smem_u32(sm);
    uint32_t sdst = smb + r0 * TPAD + c4 * 16;

    float acc[2][4][4];
    #pragma unroll
    for (int i = 0; i < 2; i++)
        #pragma unroll
        for (int j = 0; j < 4; j++)
            #pragma unroll
            for (int q = 0; q < 4; q++) acc[i][j][q] = 0.f;

    int arow = (lane & 7) + (((lane >> 3) & 1) << 3);
    int acolb = ((lane >> 4) & 1) * 16;
    uint32_t aBase0 = smb + (wm * 32 + arow) * TPAD + acolb;
    int brow = (lane & 7) + (((lane >> 4) & 1) << 3);
    int bcolb = ((lane >> 3) & 1) * 16;
    uint32_t bhBase0 = smb + TILE_SM + (wn * 32 + brow) * TPAD + bcolb;

    cp_async16(sdst,               srcA);
    cp_async16(sdst + TILE_SM,     srcBh);
    cp_async16(sdst + 2 * TILE_SM, srcBl);
    CP_COMMIT();
    cp_async16(sdst + BUFSET,               srcA + 32);
    cp_async16(sdst + BUFSET + TILE_SM,     srcBh + 32);
    cp_async16(sdst + BUFSET + 2 * TILE_SM, srcBl + 32);
    CP_COMMIT();

    int cur = 0;
    for (int kc = 0; kc < nit; kc++) {
        CP_WAIT1();
        __syncthreads();

        if (kc + 2 < nit) {
            int nb3 = cur + 2; if (nb3 >= NBUF) nb3 -= NBUF;
            uint32_t d = sdst + nb3 * BUFSET;
            int off = (kc + 2) * 32;
            cp_async16(d,               srcA + off);
            cp_async16(d + TILE_SM,     srcBh + off);
            cp_async16(d + 2 * TILE_SM, srcBl + off);
            CP_COMMIT();
        } else {
            CP_COMMIT();
        }

        uint32_t aBase  = aBase0  + cur * BUFSET;
        uint32_t bhBase = bhBase0 + cur * BUFSET;
        #pragma unroll
        for (int s = 0; s < 2; s++) {
            uint32_t af[2][4], bh2[2][4], bl2[2][4];
            #pragma unroll
            for (int i = 0; i < 2; i++)
                ldm_x4(af[i], aBase + i * 16 * TPAD + s * 32);
            #pragma unroll
            for (int jj = 0; jj < 2; jj++) {
                ldm_x4(bh2[jj], bhBase + jj * 16 * TPAD + s * 32);
                ldm_x4(bl2[jj], bhBase + TILE_SM + jj * 16 * TPAD + s * 32);
            }
            #pragma unroll
            for (int i = 0; i < 2; i++)
                #pragma unroll
                for (int j = 0; j < 4; j++)
                    mma16816(acc[i][j], af[i], &bh2[j >> 1][(j & 1) * 2]);
            #pragma unroll
            for (int i = 0; i < 2; i++)
                #pragma unroll
                for (int j = 0; j < 4; j++)
                    mma16816(acc[i][j], af[i], &bl2[j >> 1][(j & 1) * 2]);
        }
        if (++cur == NBUF) cur = 0;
    }

    int qrow = lane >> 2, qcol = (lane & 3) * 2;
    #pragma unroll
    for (int i = 0; i < 2; i++) {
        #pragma unroll
        for (int j = 0; j < 4; j++) {
            int gc = n0 + wn * 32 + j * 8 + qcol;
            #pragma unroll
            for (int half = 0; half < 2; half++) {
                int gr = m0 + wm * 32 + i * 16 + qrow + half * 8;
                if (gc + 1 < N) {
                    __half2 hv;
                    hv.x = __float2half(acc[i][j][half * 2 + 0] + bias[gc]);
                    hv.y = __float2half(acc[i][j][half * 2 + 1] + bias[gc + 1]);
                    *(__half2*)(C + (size_t)gr * ldc + gc) = hv;
                }
            }
        }
    }
}

// ---------------- recurrence GEMM with fused GRU gate epilogue ----------------
// B = gate-interleaved W_hh (period 32: r8|z8|n8|pad8). jj=3 (pad) MMAs skipped.
// Thread's acc[i][0..2][q] = r,z,n pre-activations of the same (row b, hidden k).
// Epilogue: gate math in fp32, writes hOut (next state) + OUT (concat output).
__global__ void __launch_bounds__(512, 2)
gemm_gru(const __half* __restrict__ hIn, const __half* __restrict__ Bh,
         const __half* __restrict__ Bl, const float* __restrict__ bias_hh,
         const __half* __restrict__ XG, __half* __restrict__ hOut, int step)
{
    extern __shared__ __align__(16) unsigned char sm[];

    int tid = threadIdx.x;
    int lane = tid & 31, wid = tid >> 5;
    int wm = wid >> 2, wn = wid & 3;
    int d = blockIdx.z;

    const __half* Af = hIn + (size_t)d * BB * KPAD_H;
    const __half* Bhd = Bh + (size_t)d * NI_GRU * KPAD_H;
    const __half* Bld = Bl + (size_t)d * NI_GRU * KPAD_H;

    int m0 = blockIdx.y * 128, n0 = blockIdx.x * 128;

    int r0 = tid >> 2, c4 = tid & 3;
    const __half* srcA  = Af  + (size_t)(m0 + r0) * KPAD_H + c4 * 8;
    const __half* srcBh = Bhd + (size_t)(n0 + r0) * KPAD_H + c4 * 8;
    const __half* srcBl = Bld + (size_t)(n0 + r0) * KPAD_H + c4 * 8;

    uint32_t smb = smem_u32(sm);
    uint32_t sdst = smb + r0 * TPAD + c4 * 16;

    float acc[2][3][4];
    #pragma unroll
    for (int i = 0; i < 2; i++)
        #pragma unroll
        for (int j = 0; j < 3; j++)
            #pragma unroll
            for (int q = 0; q < 4; q++) acc[i][j][q] = 0.f;

    int arow = (lane & 7) + (((lane >> 3) & 1) << 3);
    int acolb = ((lane >> 4) & 1) * 16;
    uint32_t aBase0 = smb + (wm * 32 + arow) * TPAD + acolb;
    int brow = (lane & 7) + (((lane >> 4) & 1) << 3);
    int bcolb = ((lane >> 3) & 1) * 16;
    uint32_t bhBase0 = smb + TILE_SM + (wn * 32 + brow) * TPAD + bcolb;

    constexpr int nit = KPAD_H / 32;   // 8
    cp_async16(sdst,               srcA);
    cp_async16(sdst + TILE_SM,     srcBh);
    cp_async16(sdst + 2 * TILE_SM, srcBl);
    CP_COMMIT();
    cp_async16(sdst + BUFSET,               srcA + 32);
    cp_async16(sdst + BUFSET + TILE_SM,     srcBh + 32);
    cp_async16(sdst + BUFSET + 2 * TILE_SM, srcBl + 32);
    CP_COMMIT();

    int cur = 0;
    for (int kc = 0; kc < nit; kc++) {
        CP_WAIT1();
        __syncthreads();

        if (kc + 2 < nit) {
            int nb3 = cur + 2; if (nb3 >= NBUF) nb3 -= NBUF;
            uint32_t dd = sdst + nb3 * BUFSET;
            int off = (kc + 2) * 32;
            cp_async16(dd,               srcA + off);
            cp_async16(dd + TILE_SM,     srcBh + off);
            cp_async16(dd + 2 * TILE_SM, srcBl + off);
            CP_COMMIT();
        } else {
            CP_COMMIT();
        }

        uint32_t aBase  = aBase0  + cur * BUFSET;
        uint32_t bhBase = bhBase0 + cur * BUFSET;
        #pragma unroll
        for (int s = 0; s < 2; s++) {
            uint32_t af[2][4], bh2[2][4], bl2[2][4];
            #pragma unroll
            for (int i = 0; i < 2; i++)
                ldm_x4(af[i], aBase + i * 16 * TPAD + s * 32);
            #pragma unroll
            for (int jj = 0; jj < 2; jj++) {
                ldm_x4(bh2[jj], bhBase + jj * 16 * TPAD + s * 32);
                ldm_x4(bl2[jj], bhBase + TILE_SM + jj * 16 * TPAD + s * 32);
            }
            // jj = 0,1,2 only (jj=3 is the pad slot)
            #pragma unroll
            for (int i = 0; i < 2; i++)
                #pragma unroll
                for (int j = 0; j < 3; j++)
                    mma16816(acc[i][j], af[i], &bh2[j >> 1][(j & 1) * 2]);
            #pragma unroll
            for (int i = 0; i < 2; i++)
                #pragma unroll
                for (int j = 0; j < 3; j++)
                    mma16816(acc[i][j], af[i], &bl2[j >> 1][(j & 1) * 2]);
        }
        if (++cur == NBUF) cur = 0;
    }

    // ---- fused GRU gate epilogue ----
    int qrow = lane >> 2, qcol = (lane & 3) * 2;
    int kb = (blockIdx.x * 4 + wn) * 8 + qcol;   // even; kb,kb+1 both < HID iff kb < HID
    if (kb < HID) {
        int t_eff = d ? (TSTEPS - 1 - step) : step;
        const float* bh_base = bias_hh + d * H3;
        float2 bhr = *(const float2*)(bh_base + kb);
        float2 bhz = *(const float2*)(bh_base + HID + kb);
        float2 bhn = *(const float2*)(bh_base + 2 * HID + kb);

        #pragma unroll
        for (int i = 0; i < 2; i++) {
            #pragma unroll
            for (int half = 0; half < 2; half++) {
                int b = m0 + wm * 32 + i * 16 + qrow + half * 8;
                const __half* xg = g_XGh + ((size_t)t_eff * BB + b) * NIH + d * H3;
                float2 xr = __half22float2(*(const __half2*)(xg + kb));
                float2 xz = __half22float2(*(const __half2*)(xg + HID + kb));
                float2 xn = __half22float2(*(const __half2*)(xg + 2 * HID + kb));
                size_t hoff = ((size_t)d * BB + b) * KPAD_H + kb;
                float2 hp = __half22float2(*(const __half2*)(hIn + hoff));

                float gr0 = acc[i][0][half * 2 + 0] + bhr.x;
                float gr1 = acc[i][0][half * 2 + 1] + bhr.y;
                float gz0 = acc[i][1][half * 2 + 0] + bhz.x;
                float gz1 = acc[i][1][half * 2 + 1] + bhz.y;
                float gn0 = acc[i][2][half * 2 + 0] + bhn.x;
                float gn1 = acc[i][2][half * 2 + 1] + bhn.y;

                float rr0 = 1.f / (1.f + __expf(-(xr.x + gr0)));
                float rr1 = 1.f / (1.f + __expf(-(xr.y + gr1)));
                float zz0 = 1.f / (1.f + __expf(-(xz.x + gz0)));
                float zz1 = 1.f / (1.f + __expf(-(xz.y + gz1)));
                float nn0 = tanhf(xn.x + rr0 * gn0);
                float nn1 = tanhf(xn.y + rr1 * gn1);
                float h0 = (1.f - zz0) * nn0 + zz0 * hp.x;
                float h1 = (1.f - zz1) * nn1 + zz1 * hp.y;

                __half2 oh; oh.x = __float2half(h0); oh.y = __float2half(h1);
                *(__half2*)(hOut + hoff) = oh;
                size_t oo = ((size_t)t_eff * BB + b) * KPAD_W + (size_t)d * HID + kb;
                *(__half2*)(g_OUTF + oo) = oh;
            }
        }
    }
}

// ---------------- fp16 2-pass GEMM with fused score epilogue ----------------
__global__ void __launch_bounds__(512, 2)
gemm_score(const __half* __restrict__ Af, const __half* __restrict__ Bh,
           const __half* __restrict__ Bl,
           const float* __restrict__ bias, const float* __restrict__ proj,
           float* __restrict__ score, int Nact, int Kpad, int nit, int nbt)
{
    extern __shared__ __align__(16) unsigned char sm[];

    int tid = threadIdx.x;
    int lane = tid & 31, wid = tid >> 5;
    int wm = wid >> 2, wn = wid & 3;
    int m0 = blockIdx.x * 128;

    int r0 = tid >> 2, c4 = tid & 3;
    const __half* srcA = Af + (size_t)(m0 + r0) * Kpad + c4 * 8;

    uint32_t smb = smem_u32(sm);
    uint32_t sdst = smb + r0 * TPAD + c4 * 16;

    int arow = (lane & 7) + (((lane >> 3) & 1) << 3);
    int acolb = ((lane >> 4) & 1) * 16;
    uint32_t aBase0 = smb + (wm * 32 + arow) * TPAD + acolb;
    int brow = (lane & 7) + (((lane >> 4) & 1) << 3);
    int bcolb = ((lane >> 3) & 1) * 16;
    uint32_t bhBase0 = smb + TILE_SM + (wn * 32 + brow) * TPAD + bcolb;

    int qrow = lane >> 2, qcol = (lane & 3) * 2;
    float sacc[2][2] = {{0.f, 0.f}, {0.f, 0.f}};

    for (int nb = 0; nb < nbt; nb++) {
        int n0 = nb * 128;
        const __half* srcBh = Bh + (size_t)(n0 + r0) * Kpad + c4 * 8;
        const __half* srcBl = Bl + (size_t)(n0 + r0) * Kpad + c4 * 8;

        float acc[2][4][4];
        #pragma unroll
        for (int i = 0; i < 2; i++)
            #pragma unroll
            for (int j = 0; j < 4; j++)
                #pragma unroll
                for (int q = 0; q < 4; q++) acc[i][j][q] = 0.f;

        __syncthreads();

        cp_async16(sdst,               srcA);
        cp_async16(sdst + TILE_SM,     srcBh);
        cp_async16(sdst + 2 * TILE_SM, srcBl);
        CP_COMMIT();
        cp_async16(sdst + BUFSET,               srcA + 32);
        cp_async16(sdst + BUFSET + TILE_SM,     srcBh + 32);
        cp_async16(sdst + BUFSET + 2 * TILE_SM, srcBl + 32);
        CP_COMMIT();

        int cur = 0;
        for (int kc = 0; kc < nit; kc++) {
            CP_WAIT1();
            __syncthreads();

            if (kc + 2 < nit) {
                int nb3 = cur + 2; if (nb3 >= NBUF) nb3 -= NBUF;
                uint32_t d = sdst + nb3 * BUFSET;
                int off = (kc + 2) * 32;
                cp_async16(d,               srcA + off);
                cp_async16(d + TILE_SM,     srcBh + off);
                cp_async16(d + 2 * TILE_SM, srcBl + off);
                CP_COMMIT();
            } else {
                CP_COMMIT();
            }

            uint32_t aBase  = aBase0  + cur * BUFSET;
            uint32_t bhBase = bhBase0 + cur * BUFSET;
            #pragma unroll
            for (int s = 0; s < 2; s++) {
                uint32_t af[2][4], bh2[2][4], bl2[2][4];
                #pragma unroll
                for (int i = 0; i < 2; i++)
                    ldm_x4(af[i], aBase + i * 16 * TPAD + s * 32);
                #pragma unroll
                for (int jj = 0; jj < 2; jj++) {
                    ldm_x4(bh2[jj], bhBase + jj * 16 * TPAD + s * 32);
                    ldm_x4(bl2[jj], bhBase + TILE_SM + jj * 16 * TPAD + s * 32);
                }
                #pragma unroll
                for (int i = 0; i < 2; i++)
                    #pragma unroll
                    for (int j = 0; j < 4; j++)
                        mma16816(acc[i][j], af[i], &bh2[j >> 1][(j & 1) * 2]);
                #pragma unroll
                for (int i = 0; i < 2; i++)
                    #pragma unroll
                    for (int j = 0; j < 4; j++)
                        mma16816(acc[i][j], af[i], &bl2[j >> 1][(j & 1) * 2]);
            }
            if (++cur == NBUF) cur = 0;
        }

        #pragma unroll
        for (int i = 0; i < 2; i++) {
            #pragma unroll
            for (int j = 0; j < 4; j++) {
                int gc = n0 + wn * 32 + j * 8 + qcol;
                #pragma unroll
                for (int half = 0; half < 2; half++) {
                    if (gc < Nact)
                        sacc[i][half] += tanhf(acc[i][j][half * 2 + 0] + bias[gc]) * proj[gc];
                    if (gc + 1 < Nact)
                        sacc[i][half] += tanhf(acc[i][j][half * 2 + 1] + bias[gc + 1]) * proj[gc + 1];
                }
            }
        }
    }

    #pragma unroll
    for (int i = 0; i < 2; i++)
        #pragma unroll
        for (int half = 0; half < 2; half++) {
            float v = sacc[i][half];
            v += __shfl_xor_sync(0xffffffffu, v, 1);
            v += __shfl_xor_sync(0xffffffffu, v, 2);
            sacc[i][half] = v;
        }

    __syncthreads();
    float* sred = (float*)sm;
    if ((lane & 3) == 0) {
        #pragma unroll
        for (int i = 0; i < 2; i++)
            #pragma unroll
            for (int half = 0; half < 2; half++) {
                int rl = wm * 32 + i * 16 + half * 8 + qrow;
                sred[rl * 4 + wn] = sacc[i][half];
            }
    }
    __syncthreads();
    if (tid < 128) {
        float s = sred[tid * 4] + sred[tid * 4 + 1] + sred[tid * 4 + 2] + sred[tid * 4 + 3];
        score[m0 + tid] = s;
    }
}

// ---------------- conversion / prep kernels ----------------
__device__ __forceinline__ void split_f16(float v, __half* H, __half* L, size_t i) {
    __half h = __float2half(v);
    H[i] = h;
    L[i] = __float2half(v - __half2float(h));
}

__global__ void k_zero(float* p, long long n) {
    long long i = (long long)blockIdx.x * blockDim.x + threadIdx.x;
    if (i < n) p[i] = 0.f;
}
__global__ void k_zero_h2(uint32_t* a, uint32_t* b, int nw) {
    int i = blockIdx.x * 256 + threadIdx.x;
    if (i < nw) { a[i] = 0u; b[i] = 0u; }
}

__global__ void k_conv_wih(const float* __restrict__ Wf, const float* __restrict__ Wr) {
    int idx = blockIdx.x * 256 + threadIdx.x;
    if (idx >= NIH * IND) return;
    int n = idx / IND, k = idx % IND;
    float v = (n < H3) ? Wf[(size_t)n * IND + k] : Wr[(size_t)(n - H3) * IND + k];
    split_f16(v, g_WihH, g_WihL, (size_t)n * KPAD_IN + k);
}

constexpr int CW_WHH = 2 * H3 * HID;
constexpr int CW_WW  = H2 * H2;
constexpr int CW_TOT = CW_WHH + 2 * CW_WW + NIH + 2 * H3;
__global__ void k_conv_rest(const float* __restrict__ Whf, const float* __restrict__ Whr,
                            const float* __restrict__ Ww, const float* __restrict__ Ws,
                            const float* __restrict__ bif, const float* __restrict__ bir,
                            const float* __restrict__ bhf, const float* __restrict__ bhr) {
    int idx = blockIdx.x * 256 + threadIdx.x;
    if (idx < CW_WHH) {
        int d = idx / (H3 * HID), r = idx % (H3 * HID);
        int n = r / HID, k = r % HID;       // n = gate*HID + kk
        int gate = n / HID == 0 ? 0 : 0;    // placeholder (n < H3)
        gate = n / HID;                      // 0,1,2
        int kk = n % HID;
        // interleaved dest row: group = kk/8, slot = gate*8 + kk%8
        int c = (kk >> 3) * 32 + gate * 8 + (kk & 7);
        const float* W = d ? Whr : Whf;
        split_f16(W[(size_t)n * HID + k], g_WhhIH, g_WhhIL,
                  ((size_t)d * NI_GRU + c) * KPAD_H + k);
        return;
    }
    idx -= CW_WHH;
    if (idx < CW_WW) {
        int n = idx / H2, k = idx % H2;
        split_f16(Ww[(size_t)k * H2 + n], g_WwordH, g_WwordL, (size_t)n * KPAD_W + k);
        return;
    }
    idx -= CW_WW;
    if (idx < CW_WW) {
        int n = idx / H2, k = idx % H2;
        split_f16(Ws[(size_t)k * H2 + n], g_WsentH, g_WsentL, (size_t)n * KPAD_W + k);
        return;
    }
    idx -= CW_WW;
    if (idx < NIH) { g_bias_ih[idx] = (idx < H3) ? bif[idx] : bir[idx - H3]; return; }
    idx -= NIH;
    if (idx < 2 * H3) g_bias_hh[idx] = (idx < H3) ? bhf[idx] : bhr[idx - H3];
}

__global__ void k_conv_bag(const float* __restrict__ bag) {
    size_t idx = (size_t)blockIdx.x * 256 + threadIdx.x;
    if (idx >= (size_t)MM * (IND / 2)) return;
    int j = (int)(idx % (IND / 2));
    size_t m = idx / (IND / 2);
    int tt = (int)(m >> 12), b = (int)(m & 4095);
    float2 v = *(const float2*)(bag + ((size_t)b * TSTEPS + tt) * IND + 2 * j);
    __half2 h; h.x = __float2half(v.x); h.y = __float2half(v.y);
    *(__half2*)(g_bagF + m * KPAD_IN + 2 * j) = h;
}

// ---------------- fused softmax-over-t + word_vec ----------------
__global__ void k_word_attn() {
    int b = blockIdx.x;
    int tid = threadIdx.x;
    __shared__ float sh[TSTEPS];
    __shared__ float al[TSTEPS];
    if (tid < TSTEPS) {
        float v = g_score[tid * BB + b];
        al[tid] = v; sh[tid] = v;
    }
    __syncthreads();
    #pragma unroll
    for (int o = 32; o; o >>= 1) {
        if (tid < o) sh[tid] = fmaxf(sh[tid], sh[tid + o]);
        __syncthreads();
    }
    float mx = sh[0];
    __syncthreads();
    if (tid < TSTEPS) {
        float e = __expf(al[tid] - mx);
        al[tid] = e; sh[tid] = e;
    }
    __syncthreads();
    #pragma unroll
    for (int o = 32; o; o >>= 1) {
        if (tid < o) sh[tid] += sh[tid + o];
        __syncthreads();
    }
    float inv = 1.f / sh[0];
    __syncthreads();
    if (tid < TSTEPS) al[tid] *= inv;
    __syncthreads();

    for (int h = tid; h < H2; h += blockDim.x) {
        float acc = 0.f;
        #pragma unroll 8
        for (int t = 0; t < TSTEPS; t++)
            acc += al[t] * __half2float(g_OUTF[((size_t)t * BB + b) * KPAD_W + h]);
        g_wv[(size_t)b * H2 + h] = acc;
        g_wvF[(size_t)b * KPAD_W + h] = __float2half(acc);
    }
}

// ---------------- sentence softmax + weighted sum + FC + scatter ----------------
__global__ void k_sent(const float* __restrict__ fcW, const float* __restrict__ fcb,
                       const int* __restrict__ pairs, float* __restrict__ out) {
    int nb = blockIdx.x;
    __shared__ float beta[MSENT];
    __shared__ float sv[H2];
    if (threadIdx.x == 0) {
        float v[MSENT], mx = -1e30f;
        #pragma unroll
        for (int s = 0; s < MSENT; s++) { v[s] = g_score2[nb * MSENT + s]; mx = fmaxf(mx, v[s]); }
        float sum = 0.f;
        #pragma unroll
        for (int s = 0; s < MSENT; s++) { v[s] = expf(v[s] - mx); sum += v[s]; }
        #pragma unroll
        for (int s = 0; s < MSENT; s++) beta[s] = v[s] / sum;
    }
    __syncthreads();
    for (int h = threadIdx.x; h < H2; h += blockDim.x) {
        float acc = 0.f;
        #pragma unroll
        for (int s = 0; s < MSENT; s++)
            acc += beta[s] * g_wv[((size_t)(nb * MSENT + s)) * H2 + h];
        sv[h] = acc;
    }
    __syncthreads();
    const int* p = pairs + nb * 3;
    int base = ((p[0] * ENT + p[1]) * ENT + p[2]) * OUTD;
    for (int o = threadIdx.x; o < OUTD; o += blockDim.x) {
        float acc = fcb[o];
        for (int h = 0; h < H2; h++) acc += sv[h] * fcW[(size_t)o * H2 + h];
        out[base + o] = acc;
    }
}

// ---------------- launcher ----------------
extern "C" void kernel_launch(void* const* d_in, const int* in_sizes, int n_in,
                              void* d_out, int out_size) {
    const float* bag       = (const float*)d_in[0];
    const float* W_ih_f    = (const float*)d_in[1];
    const float* W_hh_f    = (const float*)d_in[2];
    const float* b_ih_f    = (const float*)d_in[3];
    const float* b_hh_f    = (const float*)d_in[4];
    const float* W_ih_r    = (const float*)d_in[5];
    const float* W_hh_r    = (const float*)d_in[6];
    const float* b_ih_r    = (const float*)d_in[7];
    const float* b_hh_r    = (const float*)d_in[8];
    const float* W_word    = (const float*)d_in[9];
    const float* b_word    = (const float*)d_in[10];
    const float* proj_word = (const float*)d_in[11];
    const float* W_sent    = (const float*)d_in[12];
    const float* b_sent    = (const float*)d_in[13];
    const float* proj_sent = (const float*)d_in[14];
    const float* fc_W      = (const float*)d_in[15];
    const float* fc_b      = (const float*)d_in[16];
    const int*   pairs     = (const int*)d_in[17];
    float* out = (float*)d_out;

    static bool attr_set = false;
    if (!attr_set) {
        cudaFuncSetAttribute(gemm_f16s, cudaFuncAttributeMaxDynamicSharedMemorySize, SMEM_GEMM);
        cudaFuncSetAttribute(gemm_gru, cudaFuncAttributeMaxDynamicSharedMemorySize, SMEM_GEMM);
        cudaFuncSetAttribute(gemm_score, cudaFuncAttributeMaxDynamicSharedMemorySize, SMEM_GEMM);
        attr_set = true;
    }

    #define SYMA(p, s) void* p; cudaGetSymbolAddress(&p, s)
    SYMA(pXG, g_XGh);
    SYMA(pScore, g_score);
    SYMA(pWv, g_wv);
    SYMA(pScore2, g_score2);
    SYMA(pBih, g_bias_ih); SYMA(pBhh, g_bias_hh);
    SYMA(pBagF, g_bagF);
    SYMA(pWihH, g_WihH); SYMA(pWihL, g_WihL);
    SYMA(pWhhIH, g_WhhIH); SYMA(pWhhIL, g_WhhIL);
    SYMA(pWwH, g_WwordH); SYMA(pWwL, g_WwordL);
    SYMA(pWsH, g_WsentH); SYMA(pWsL, g_WsentL);
    SYMA(pOF, g_OUTF);
    SYMA(phA, g_hA); SYMA(phB, g_hB);
    SYMA(pwvF, g_wvF);
    #undef SYMA

    // ---- prep (3 launches), then input GEMM as launch #4 (ncu capture slot) ----
    k_conv_wih<<<(NIH * IND + 255) / 256, 256>>>(W_ih_f, W_ih_r);                       // 1
    k_conv_rest<<<(CW_TOT + 255) / 256, 256>>>(W_hh_f, W_hh_r, W_word, W_sent,          // 2
                                               b_ih_f, b_ih_r, b_hh_f, b_hh_r);
    {
        long long n = MM * (IND / 2);                                                   // 3
        k_conv_bag<<<(unsigned)((n + 255) / 256), 256>>>(bag);
    }
    {
        dim3 g(NPAD_IH / 128, (unsigned)(MM / 128), 1);                                 // 4
        gemm_f16s<<<g, 512, SMEM_GEMM>>>(
            (const __half*)pBagF,
            (const __half*)pWihH, (const __half*)pWihL,
            (const float*)pBih, (__half*)pXG,
            NIH, NIH, KPAD_IN, KPAD_IN / 32);
    }
    {
        int nw = 2 * BB * KPAD_H / 2;                                                   // 5
        k_zero_h2<<<(nw + 255) / 256, 256>>>((uint32_t*)phA, (uint32_t*)phB, nw);
    }
    k_zero<<<(out_size + 255) / 256, 256>>>(out, (long long)out_size);                  // 6

    // ---- GRU recurrence: one fused launch per step ----
    {
        dim3 g(NI_GRU / 128, BB / 128, 2);   // (8, 32, 2) = 512 blocks
        const __half* hbuf[2] = {(const __half*)phA, (const __half*)phB};
        for (int s = 0; s < TSTEPS; s++) {
            gemm_gru<<<g, 512, SMEM_GEMM>>>(
                hbuf[s & 1],
                (const __half*)pWhhIH, (const __half*)pWhhIL,
                (const float*)pBhh, (const __half*)pXG,
                (__half*)(s & 1 ? phA : phB), s);
        }
    }

    // ---- word attention: fused GEMM + tanh.proj score, fused softmax+wv ----
    gemm_score<<<(unsigned)(MM / 128), 512, SMEM_GEMM>>>(
        (const __half*)pOF,
        (const __half*)pWwH, (const __half*)pWwL,
        b_word, proj_word, (float*)pScore, H2, KPAD_W, KPAD_W / 32, NPAD_W / 128);
    k_word_attn<<<BB, 256>>>();

    // ---- sentence attention: fused GEMM + score, then softmax+FC+scatter ----
    gemm_score<<<BB / 128, 512, SMEM_GEMM>>>(
        (const __half*)pwvF,
        (const __half*)pWsH, (const __half*)pWsL,
        b_sent, proj_sent, (float*)pScore2, H2, KPAD_W, KPAD_W / 32, NPAD_W / 128);
    k_sent<<<NBAG, 256>>>(fc_W, fc_b, pairs, out);
}

// round 13
// speedup vs baseline: 3.8653x; 1.0070x over previous
#include <cuda_runtime.h>
#include <cuda_fp16.h>
#include <math.h>
#include <stdint.h>

// ---------------- problem constants ----------------
constexpr int NBAG   = 512;
constexpr int MSENT  = 8;
constexpr int TSTEPS = 64;
constexpr int IND    = 360;
constexpr int HID    = 230;
constexpr int OUTD   = 53;
constexpr int ENT    = 8;

constexpr int BB  = NBAG * MSENT;   // 4096
constexpr int H3  = 3 * HID;        // 690
constexpr int H2  = 2 * HID;        // 460
constexpr int NIH = 2 * H3;         // 1380
constexpr long long MM = (long long)TSTEPS * BB;  // 262144

constexpr int KPAD_IN = 384;
constexpr int NPAD_IH = 1408;
constexpr int KPAD_H  = 256;
constexpr int NI_GRU  = 1024;   // interleaved W_hh rows per dir: 32 groups x [r8|z8|n8|pad8]
constexpr int KPAD_W  = 512;
constexpr int NPAD_W  = 512;

// ---------------- device scratch ----------------
__device__ float g_bias_ih[NIH];
__device__ float g_bias_hh[2 * H3];
__device__ __half g_XGh[(size_t)MM * NIH];        // x@W_ih^T + b_ih, fp16
__device__ float g_score[TSTEPS * BB];
__device__ float g_wv[(size_t)BB * H2];
__device__ float g_score2[BB];

// A-side: single fp16. B-side (weights): fp16 hi+lo split.
__device__ __half g_bagF[(size_t)MM * KPAD_IN];
__device__ __half g_WihH[(size_t)NPAD_IH * KPAD_IN];
__device__ __half g_WihL[(size_t)NPAD_IH * KPAD_IN];
__device__ __half g_WhhIH[(size_t)2 * NI_GRU * KPAD_H];   // gate-interleaved
__device__ __half g_WhhIL[(size_t)2 * NI_GRU * KPAD_H];
__device__ __half g_WwordH[(size_t)NPAD_W * KPAD_W];
__device__ __half g_WwordL[(size_t)NPAD_W * KPAD_W];
__device__ __half g_WsentH[(size_t)NPAD_W * KPAD_W];
__device__ __half g_WsentL[(size_t)NPAD_W * KPAD_W];
__device__ __half g_OUTF[(size_t)MM * KPAD_W];
__device__ __half g_hA[(size_t)2 * BB * KPAD_H];          // double-buffered hidden state
__device__ __half g_hB[(size_t)2 * BB * KPAD_H];
__device__ __half g_wvF[(size_t)BB * KPAD_W];

// ---------------- helpers ----------------
__device__ __forceinline__ uint32_t smem_u32(const void* p) {
    uint32_t a;
    asm("{ .reg .u64 t; cvta.to.shared.u64 t, %1; cvt.u32.u64 %0, t; }" : "=r"(a) : "l"(p));
    return a;
}
__device__ __forceinline__ void ldm_x4(uint32_t* r, uint32_t addr) {
    asm volatile("ldmatrix.sync.aligned.m8n8.x4.shared.b16 {%0,%1,%2,%3}, [%4];"
                 : "=r"(r[0]), "=r"(r[1]), "=r"(r[2]), "=r"(r[3]) : "r"(addr));
}
__device__ __forceinline__ void mma16816(float* d, const uint32_t* a, const uint32_t* b) {
    asm volatile("mma.sync.aligned.m16n8k16.row.col.f32.f16.f16.f32 "
                 "{%0,%1,%2,%3}, {%4,%5,%6,%7}, {%8,%9}, {%0,%1,%2,%3};"
                 : "+f"(d[0]), "+f"(d[1]), "+f"(d[2]), "+f"(d[3])
                 : "r"(a[0]), "r"(a[1]), "r"(a[2]), "r"(a[3]), "r"(b[0]), "r"(b[1]));
}
__device__ __forceinline__ void cp_async16(uint32_t saddr, const void* gaddr) {
    asm volatile("cp.async.cg.shared.global [%0], [%1], 16;" :: "r"(saddr), "l"(gaddr));
}
#define CP_COMMIT() asm volatile("cp.async.commit_group;" ::: "memory")
#define CP_WAIT0()  asm volatile("cp.async.wait_group 0;" ::: "memory")

// BK = 64: rows of 128B data padded to 144B (bank-stride 36 mod 32 = 4 -> the
// 8 ldmatrix rows cover all 32 banks; conflict-free like the old 80B pad).
constexpr int TPAD    = 144;
constexpr int TILE_SM = 128 * TPAD;        // 18432
constexpr int BUFSET  = 3 * TILE_SM;       // 55296 (Af, Bh, Bl)
constexpr int SMEM_GEMM = 2 * BUFSET;      // 110592 -> 2 CTAs = 221 KB <= 228 KB

// load one BK=64 chunk (128B per row) of all 3 tiles into buffer `dst`
#define LOAD_CHUNK(dst, off)                                        \
    do {                                                            \
        cp_async16((dst),                    srcA  + (off));        \
        cp_async16((dst) + 64,               srcA  + (off) + 32);   \
        cp_async16((dst) + TILE_SM,          srcBh + (off));        \
        cp_async16((dst) + TILE_SM + 64,     srcBh + (off) + 32);   \
        cp_async16((dst) + 2 * TILE_SM,      srcBl + (off));        \
        cp_async16((dst) + 2 * TILE_SM + 64, srcBl + (off) + 32);   \
    } while (0)

// ---------------- fp16 2-pass GEMM: C(half) = Af @ (Bh+Bl)^T + bias ----------------
// BK=64 double-buffered cp.async, 512 thr, 128x128 tile, warp grid 4x4.
__global__ void __launch_bounds__(512, 2)
gemm_f16s(const __half* __restrict__ Af, const __half* __restrict__ Bh,
          const __half* __restrict__ Bl,
          const float* __restrict__ bias, __half* __restrict__ C,
          int N, int ldc, int Kpad, int nit)
{
    extern __shared__ __align__(16) unsigned char sm[];

    int tid = threadIdx.x;
    int lane = tid & 31, wid = tid >> 5;
    int wm = wid >> 2, wn = wid & 3;

    int m0 = blockIdx.y * 128, n0 = blockIdx.x * 128;

    int r0 = tid >> 2, c4 = tid & 3;
    const __half* srcA  = Af + (size_t)(m0 + r0) * Kpad + c4 * 8;
    const __half* srcBh = Bh + (size_t)(n0 + r0) * Kpad + c4 * 8;
    const __half* srcBl = Bl + (size_t)(n0 + r0) * Kpad + c4 * 8;

    uint32_t smb = smem_u32(sm);
    uint32_t sdst = smb + r0 * TPAD + c4 * 16;

    float acc[2][4][4];
    #pragma unroll
    for (int i = 0; i < 2; i++)
        #pragma unroll
        for (int j = 0; j < 4; j++)
            #pragma unroll
            for (int q = 0; q < 4; q++) acc[i][j][q] = 0.f;

    int arow = (lane & 7) + (((lane >> 3) & 1) << 3);
    int acolb = ((lane >> 4) & 1) * 16;
    uint32_t aBase0 = smb + (wm * 32 + arow) * TPAD + acolb;
    int brow = (lane & 7) + (((lane >> 4) & 1) << 3);
    int bcolb = ((lane >> 3) & 1) * 16;
    uint32_t bhBase0 = smb + TILE_SM + (wn * 32 + brow) * TPAD + bcolb;

    LOAD_CHUNK(sdst, 0);
    CP_COMMIT();

    int cur = 0;
    for (int kc = 0; kc < nit; kc++) {
        CP_WAIT0();
        __syncthreads();

        if (kc + 1 < nit) {
            LOAD_CHUNK(sdst + (cur ^ 1) * BUFSET, (kc + 1) * 64);
            CP_COMMIT();
        }

        uint32_t aBase  = aBase0  + cur * BUFSET;
        uint32_t bhBase = bhBase0 + cur * BUFSET;
        #pragma unroll
        for (int s = 0; s < 4; s++) {
            uint32_t af[2][4], bh2[2][4], bl2[2][4];
            #pragma unroll
            for (int i = 0; i < 2; i++)
                ldm_x4(af[i], aBase + i * 16 * TPAD + s * 32);
            #pragma unroll
            for (int jj = 0; jj < 2; jj++) {
                ldm_x4(bh2[jj], bhBase + jj * 16 * TPAD + s * 32);
                ldm_x4(bl2[jj], bhBase + TILE_SM + jj * 16 * TPAD + s * 32);
            }
            #pragma unroll
            for (int i = 0; i < 2; i++)
                #pragma unroll
                for (int j = 0; j < 4; j++)
                    mma16816(acc[i][j], af[i], &bh2[j >> 1][(j & 1) * 2]);
            #pragma unroll
            for (int i = 0; i < 2; i++)
                #pragma unroll
                for (int j = 0; j < 4; j++)
                    mma16816(acc[i][j], af[i], &bl2[j >> 1][(j & 1) * 2]);
        }
        cur ^= 1;
    }

    int qrow = lane >> 2, qcol = (lane & 3) * 2;
    #pragma unroll
    for (int i = 0; i < 2; i++) {
        #pragma unroll
        for (int j = 0; j < 4; j++) {
            int gc = n0 + wn * 32 + j * 8 + qcol;
            #pragma unroll
            for (int half = 0; half < 2; half++) {
                int gr = m0 + wm * 32 + i * 16 + qrow + half * 8;
                if (gc + 1 < N) {
                    __half2 hv;
                    hv.x = __float2half(acc[i][j][half * 2 + 0] + bias[gc]);
                    hv.y = __float2half(acc[i][j][half * 2 + 1] + bias[gc + 1]);
                    *(__half2*)(C + (size_t)gr * ldc + gc) = hv;
                }
            }
        }
    }
}

// ---------------- recurrence GEMM with fused GRU gate epilogue ----------------
// B = gate-interleaved W_hh (period 32: r8|z8|n8|pad8). jj=3 (pad) MMAs skipped.
__global__ void __launch_bounds__(512, 2)
gemm_gru(const __half* __restrict__ hIn, const __half* __restrict__ Bhw,
         const __half* __restrict__ Blw, const float* __restrict__ bias_hh,
         __half* __restrict__ hOut, int step)
{
    extern __shared__ __align__(16) unsigned char sm[];

    int tid = threadIdx.x;
    int lane = tid & 31, wid = tid >> 5;
    int wm = wid >> 2, wn = wid & 3;
    int d = blockIdx.z;

    const __half* Af  = hIn + (size_t)d * BB * KPAD_H;
    const __half* Bhd = Bhw + (size_t)d * NI_GRU * KPAD_H;
    const __half* Bld = Blw + (size_t)d * NI_GRU * KPAD_H;

    int m0 = blockIdx.y * 128, n0 = blockIdx.x * 128;

    int r0 = tid >> 2, c4 = tid & 3;
    const __half* srcA  = Af  + (size_t)(m0 + r0) * KPAD_H + c4 * 8;
    const __half* srcBh = Bhd + (size_t)(n0 + r0) * KPAD_H + c4 * 8;
    const __half* srcBl = Bld + (size_t)(n0 + r0) * KPAD_H + c4 * 8;

    uint32_t smb = smem_u32(sm);
    uint32_t sdst = smb + r0 * TPAD + c4 * 16;

    float acc[2][3][4];
    #pragma unroll
    for (int i = 0; i < 2; i++)
        #pragma unroll
        for (int j = 0; j < 3; j++)
            #pragma unroll
            for (int q = 0; q < 4; q++) acc[i][j][q] = 0.f;

    int arow = (lane & 7) + (((lane >> 3) & 1) << 3);
    int acolb = ((lane >> 4) & 1) * 16;
    uint32_t aBase0 = smb + (wm * 32 + arow) * TPAD + acolb;
    int brow = (lane & 7) + (((lane >> 4) & 1) << 3);
    int bcolb = ((lane >> 3) & 1) * 16;
    uint32_t bhBase0 = smb + TILE_SM + (wn * 32 + brow) * TPAD + bcolb;

    constexpr int nit = KPAD_H / 64;   // 4
    LOAD_CHUNK(sdst, 0);
    CP_COMMIT();

    int cur = 0;
    for (int kc = 0; kc < nit; kc++) {
        CP_WAIT0();
        __syncthreads();

        if (kc + 1 < nit) {
            LOAD_CHUNK(sdst + (cur ^ 1) * BUFSET, (kc + 1) * 64);
            CP_COMMIT();
        }

        uint32_t aBase  = aBase0  + cur * BUFSET;
        uint32_t bhBase = bhBase0 + cur * BUFSET;
        #pragma unroll
        for (int s = 0; s < 4; s++) {
            uint32_t af[2][4], bh2[2][4], bl2[2][4];
            #pragma unroll
            for (int i = 0; i < 2; i++)
                ldm_x4(af[i], aBase + i * 16 * TPAD + s * 32);
            #pragma unroll
            for (int jj = 0; jj < 2; jj++) {
                ldm_x4(bh2[jj], bhBase + jj * 16 * TPAD + s * 32);
                ldm_x4(bl2[jj], bhBase + TILE_SM + jj * 16 * TPAD + s * 32);
            }
            // jj slots 0..2 only (3 = pad)
            #pragma unroll
            for (int i = 0; i < 2; i++)
                #pragma unroll
                for (int j = 0; j < 3; j++)
                    mma16816(acc[i][j], af[i], &bh2[j >> 1][(j & 1) * 2]);
            #pragma unroll
            for (int i = 0; i < 2; i++)
                #pragma unroll
                for (int j = 0; j < 3; j++)
                    mma16816(acc[i][j], af[i], &bl2[j >> 1][(j & 1) * 2]);
        }
        cur ^= 1;
    }

    // ---- fused GRU gate epilogue ----
    int qrow = lane >> 2, qcol = (lane & 3) * 2;
    int kb = (blockIdx.x * 4 + wn) * 8 + qcol;
    if (kb < HID) {
        int t_eff = d ? (TSTEPS - 1 - step) : step;
        const float* bh_base = bias_hh + d * H3;
        float2 bhr = *(const float2*)(bh_base + kb);
        float2 bhz = *(const float2*)(bh_base + HID + kb);
        float2 bhn = *(const float2*)(bh_base + 2 * HID + kb);

        #pragma unroll
        for (int i = 0; i < 2; i++) {
            #pragma unroll
            for (int half = 0; half < 2; half++) {
                int b = m0 + wm * 32 + i * 16 + qrow + half * 8;
                const __half* xg = g_XGh + ((size_t)t_eff * BB + b) * NIH + d * H3;
                float2 xr = __half22float2(*(const __half2*)(xg + kb));
                float2 xz = __half22float2(*(const __half2*)(xg + HID + kb));
                float2 xn = __half22float2(*(const __half2*)(xg + 2 * HID + kb));
                size_t hoff = ((size_t)d * BB + b) * KPAD_H + kb;
                float2 hp = __half22float2(*(const __half2*)(hIn + hoff));

                float gr0 = acc[i][0][half * 2 + 0] + bhr.x;
                float gr1 = acc[i][0][half * 2 + 1] + bhr.y;
                float gz0 = acc[i][1][half * 2 + 0] + bhz.x;
                float gz1 = acc[i][1][half * 2 + 1] + bhz.y;
                float gn0 = acc[i][2][half * 2 + 0] + bhn.x;
                float gn1 = acc[i][2][half * 2 + 1] + bhn.y;

                float rr0 = 1.f / (1.f + __expf(-(xr.x + gr0)));
                float rr1 = 1.f / (1.f + __expf(-(xr.y + gr1)));
                float zz0 = 1.f / (1.f + __expf(-(xz.x + gz0)));
                float zz1 = 1.f / (1.f + __expf(-(xz.y + gz1)));
                float nn0 = tanhf(xn.x + rr0 * gn0);
                float nn1 = tanhf(xn.y + rr1 * gn1);
                float h0 = (1.f - zz0) * nn0 + zz0 * hp.x;
                float h1 = (1.f - zz1) * nn1 + zz1 * hp.y;

                __half2 oh; oh.x = __float2half(h0); oh.y = __float2half(h1);
                *(__half2*)(hOut + hoff) = oh;
                size_t oo = ((size_t)t_eff * BB + b) * KPAD_W + (size_t)d * HID + kb;
                *(__half2*)(g_OUTF + oo) = oh;
            }
        }
    }
}

// ---------------- fp16 2-pass GEMM with fused score epilogue ----------------
__global__ void __launch_bounds__(512, 2)
gemm_score(const __half* __restrict__ Af, const __half* __restrict__ Bh,
           const __half* __restrict__ Bl,
           const float* __restrict__ bias, const float* __restrict__ proj,
           float* __restrict__ score, int Nact, int Kpad, int nit, int nbt)
{
    extern __shared__ __align__(16) unsigned char sm[];

    int tid = threadIdx.x;
    int lane = tid & 31, wid = tid >> 5;
    int wm = wid >> 2, wn = wid & 3;
    int m0 = blockIdx.x * 128;

    int r0 = tid >> 2, c4 = tid & 3;
    const __half* srcA = Af + (size_t)(m0 + r0) * Kpad + c4 * 8;

    uint32_t smb = smem_u32(sm);
    uint32_t sdst = smb + r0 * TPAD + c4 * 16;

    int arow = (lane & 7) + (((lane >> 3) & 1) << 3);
    int acolb = ((lane >> 4) & 1) * 16;
    uint32_t aBase0 = smb + (wm * 32 + arow) * TPAD + acolb;
    int brow = (lane & 7) + (((lane >> 4) & 1) << 3);
    int bcolb = ((lane >> 3) & 1) * 16;
    uint32_t bhBase0 = smb + TILE_SM + (wn * 32 + brow) * TPAD + bcolb;

    int qrow = lane >> 2, qcol = (lane & 3) * 2;
    float sacc[2][2] = {{0.f, 0.f}, {0.f, 0.f}};

    for (int nb = 0; nb < nbt; nb++) {
        int n0 = nb * 128;
        const __half* srcBh = Bh + (size_t)(n0 + r0) * Kpad + c4 * 8;
        const __half* srcBl = Bl + (size_t)(n0 + r0) * Kpad + c4 * 8;

        float acc[2][4][4];
        #pragma unroll
        for (int i = 0; i < 2; i++)
            #pragma unroll
            for (int j = 0; j < 4; j++)
                #pragma unroll
                for (int q = 0; q < 4; q++) acc[i][j][q] = 0.f;

        __syncthreads();   // all warps done with previous nb's smem

        LOAD_CHUNK(sdst, 0);
        CP_COMMIT();

        int cur = 0;
        for (int kc = 0; kc < nit; kc++) {
            CP_WAIT0();
            __syncthreads();

            if (kc + 1 < nit) {
                LOAD_CHUNK(sdst + (cur ^ 1) * BUFSET, (kc + 1) * 64);
                CP_COMMIT();
            }

            uint32_t aBase  = aBase0  + cur * BUFSET;
            uint32_t bhBase = bhBase0 + cur * BUFSET;
            #pragma unroll
            for (int s = 0; s < 4; s++) {
                uint32_t af[2][4], bh2[2][4], bl2[2][4];
                #pragma unroll
                for (int i = 0; i < 2; i++)
                    ldm_x4(af[i], aBase + i * 16 * TPAD + s * 32);
                #pragma unroll
                for (int jj = 0; jj < 2; jj++) {
                    ldm_x4(bh2[jj], bhBase + jj * 16 * TPAD + s * 32);
                    ldm_x4(bl2[jj], bhBase + TILE_SM + jj * 16 * TPAD + s * 32);
                }
                #pragma unroll
                for (int i = 0; i < 2; i++)
                    #pragma unroll
                    for (int j = 0; j < 4; j++)
                        mma16816(acc[i][j], af[i], &bh2[j >> 1][(j & 1) * 2]);
                #pragma unroll
                for (int i = 0; i < 2; i++)
                    #pragma unroll
                    for (int j = 0; j < 4; j++)
                        mma16816(acc[i][j], af[i], &bl2[j >> 1][(j & 1) * 2]);
            }
            cur ^= 1;
        }

        #pragma unroll
        for (int i = 0; i < 2; i++) {
            #pragma unroll
            for (int j = 0; j < 4; j++) {
                int gc = n0 + wn * 32 + j * 8 + qcol;
                #pragma unroll
                for (int half = 0; half < 2; half++) {
                    if (gc < Nact)
                        sacc[i][half] += tanhf(acc[i][j][half * 2 + 0] + bias[gc]) * proj[gc];
                    if (gc + 1 < Nact)
                        sacc[i][half] += tanhf(acc[i][j][half * 2 + 1] + bias[gc + 1]) * proj[gc + 1];
                }
            }
        }
    }

    #pragma unroll
    for (int i = 0; i < 2; i++)
        #pragma unroll
        for (int half = 0; half < 2; half++) {
            float v = sacc[i][half];
            v += __shfl_xor_sync(0xffffffffu, v, 1);
            v += __shfl_xor_sync(0xffffffffu, v, 2);
            sacc[i][half] = v;
        }

    __syncthreads();
    float* sred = (float*)sm;
    if ((lane & 3) == 0) {
        #pragma unroll
        for (int i = 0; i < 2; i++)
            #pragma unroll
            for (int half = 0; half < 2; half++) {
                int rl = wm * 32 + i * 16 + half * 8 + qrow;
                sred[rl * 4 + wn] = sacc[i][half];
            }
    }
    __syncthreads();
    if (tid < 128) {
        float s = sred[tid * 4] + sred[tid * 4 + 1] + sred[tid * 4 + 2] + sred[tid * 4 + 3];
        score[m0 + tid] = s;
    }
}

// ---------------- conversion / prep kernels ----------------
__device__ __forceinline__ void split_f16(float v, __half* H, __half* L, size_t i) {
    __half h = __float2half(v);
    H[i] = h;
    L[i] = __float2half(v - __half2float(h));
}

__global__ void k_zero(float* p, long long n) {
    long long i = (long long)blockIdx.x * blockDim.x + threadIdx.x;
    if (i < n) p[i] = 0.f;
}
__global__ void k_zero_h2(uint32_t* a, uint32_t* b, int nw) {
    int i = blockIdx.x * 256 + threadIdx.x;
    if (i < nw) { a[i] = 0u; b[i] = 0u; }
}

__global__ void k_conv_wih(const float* __restrict__ Wf, const float* __restrict__ Wr) {
    int idx = blockIdx.x * 256 + threadIdx.x;
    if (idx >= NIH * IND) return;
    int n = idx / IND, k = idx % IND;
    float v = (n < H3) ? Wf[(size_t)n * IND + k] : Wr[(size_t)(n - H3) * IND + k];
    split_f16(v, g_WihH, g_WihL, (size_t)n * KPAD_IN + k);
}

constexpr int CW_WHH = 2 * H3 * HID;
constexpr int CW_WW  = H2 * H2;
constexpr int CW_TOT = CW_WHH + 2 * CW_WW + NIH + 2 * H3;
__global__ void k_conv_rest(const float* __restrict__ Whf, const float* __restrict__ Whr,
                            const float* __restrict__ Ww, const float* __restrict__ Ws,
                            const float* __restrict__ bif, const float* __restrict__ bir,
                            const float* __restrict__ bhf, const float* __restrict__ bhr) {
    int idx = blockIdx.x * 256 + threadIdx.x;
    if (idx < CW_WHH) {
        int d = idx / (H3 * HID), r = idx % (H3 * HID);
        int n = r / HID, k = r % HID;       // n = gate*HID + kk
        int gate = n / HID;                  // 0,1,2
        int kk = n % HID;
        int c = (kk >> 3) * 32 + gate * 8 + (kk & 7);   // interleaved row
        const float* W = d ? Whr : Whf;
        split_f16(W[(size_t)n * HID + k], g_WhhIH, g_WhhIL,
                  ((size_t)d * NI_GRU + c) * KPAD_H + k);
        return;
    }
    idx -= CW_WHH;
    if (idx < CW_WW) {
        int n = idx / H2, k = idx % H2;
        split_f16(Ww[(size_t)k * H2 + n], g_WwordH, g_WwordL, (size_t)n * KPAD_W + k);
        return;
    }
    idx -= CW_WW;
    if (idx < CW_WW) {
        int n = idx / H2, k = idx % H2;
        split_f16(Ws[(size_t)k * H2 + n], g_WsentH, g_WsentL, (size_t)n * KPAD_W + k);
        return;
    }
    idx -= CW_WW;
    if (idx < NIH) { g_bias_ih[idx] = (idx < H3) ? bif[idx] : bir[idx - H3]; return; }
    idx -= NIH;
    if (idx < 2 * H3) g_bias_hh[idx] = (idx < H3) ? bhf[idx] : bhr[idx - H3];
}

__global__ void k_conv_bag(const float* __restrict__ bag) {
    size_t idx = (size_t)blockIdx.x * 256 + threadIdx.x;
    if (idx >= (size_t)MM * (IND / 2)) return;
    int j = (int)(idx % (IND / 2));
    size_t m = idx / (IND / 2);
    int tt = (int)(m >> 12), b = (int)(m & 4095);
    float2 v = *(const float2*)(bag + ((size_t)b * TSTEPS + tt) * IND + 2 * j);
    __half2 h; h.x = __float2half(v.x); h.y = __float2half(v.y);
    *(__half2*)(g_bagF + m * KPAD_IN + 2 * j) = h;
}

// ---------------- fused softmax-over-t + word_vec ----------------
__global__ void k_word_attn() {
    int b = blockIdx.x;
    int tid = threadIdx.x;
    __shared__ float sh[TSTEPS];
    __shared__ float al[TSTEPS];
    if (tid < TSTEPS) {
        float v = g_score[tid * BB + b];
        al[tid] = v; sh[tid] = v;
    }
    __syncthreads();
    #pragma unroll
    for (int o = 32; o; o >>= 1) {
        if (tid < o) sh[tid] = fmaxf(sh[tid], sh[tid + o]);
        __syncthreads();
    }
    float mx = sh[0];
    __syncthreads();
    if (tid < TSTEPS) {
        float e = __expf(al[tid] - mx);
        al[tid] = e; sh[tid] = e;
    }
    __syncthreads();
    #pragma unroll
    for (int o = 32; o; o >>= 1) {
        if (tid < o) sh[tid] += sh[tid + o];
        __syncthreads();
    }
    float inv = 1.f / sh[0];
    __syncthreads();
    if (tid < TSTEPS) al[tid] *= inv;
    __syncthreads();

    for (int h = tid; h < H2; h += blockDim.x) {
        float acc = 0.f;
        #pragma unroll 8
        for (int t = 0; t < TSTEPS; t++)
            acc += al[t] * __half2float(g_OUTF[((size_t)t * BB + b) * KPAD_W + h]);
        g_wv[(size_t)b * H2 + h] = acc;
        g_wvF[(size_t)b * KPAD_W + h] = __float2half(acc);
    }
}

// ---------------- sentence softmax + weighted sum + FC + scatter ----------------
__global__ void k_sent(const float* __restrict__ fcW, const float* __restrict__ fcb,
                       const int* __restrict__ pairs, float* __restrict__ out) {
    int nb = blockIdx.x;
    __shared__ float beta[MSENT];
    __shared__ float sv[H2];
    if (threadIdx.x == 0) {
        float v[MSENT], mx = -1e30f;
        #pragma unroll
        for (int s = 0; s < MSENT; s++) { v[s] = g_score2[nb * MSENT + s]; mx = fmaxf(mx, v[s]); }
        float sum = 0.f;
        #pragma unroll
        for (int s = 0; s < MSENT; s++) { v[s] = expf(v[s] - mx); sum += v[s]; }
        #pragma unroll
        for (int s = 0; s < MSENT; s++) beta[s] = v[s] / sum;
    }
    __syncthreads();
    for (int h = threadIdx.x; h < H2; h += blockDim.x) {
        float acc = 0.f;
        #pragma unroll
        for (int s = 0; s < MSENT; s++)
            acc += beta[s] * g_wv[((size_t)(nb * MSENT + s)) * H2 + h];
        sv[h] = acc;
    }
    __syncthreads();
    const int* p = pairs + nb * 3;
    int base = ((p[0] * ENT + p[1]) * ENT + p[2]) * OUTD;
    for (int o = threadIdx.x; o < OUTD; o += blockDim.x) {
        float acc = fcb[o];
        for (int h = 0; h < H2; h++) acc += sv[h] * fcW[(size_t)o * H2 + h];
        out[base + o] = acc;
    }
}

// ---------------- launcher ----------------
extern "C" void kernel_launch(void* const* d_in, const int* in_sizes, int n_in,
                              void* d_out, int out_size) {
    const float* bag       = (const float*)d_in[0];
    const float* W_ih_f    = (const float*)d_in[1];
    const float* W_hh_f    = (const float*)d_in[2];
    const float* b_ih_f    = (const float*)d_in[3];
    const float* b_hh_f    = (const float*)d_in[4];
    const float* W_ih_r    = (const float*)d_in[5];
    const float* W_hh_r    = (const float*)d_in[6];
    const float* b_ih_r    = (const float*)d_in[7];
    const float* b_hh_r    = (const float*)d_in[8];
    const float* W_word    = (const float*)d_in[9];
    const float* b_word    = (const float*)d_in[10];
    const float* proj_word = (const float*)d_in[11];
    const float* W_sent    = (const float*)d_in[12];
    const float* b_sent    = (const float*)d_in[13];
    const float* proj_sent = (const float*)d_in[14];
    const float* fc_W      = (const float*)d_in[15];
    const float* fc_b      = (const float*)d_in[16];
    const int*   pairs     = (const int*)d_in[17];
    float* out = (float*)d_out;

    static bool attr_set = false;
    if (!attr_set) {
        cudaFuncSetAttribute(gemm_f16s, cudaFuncAttributeMaxDynamicSharedMemorySize, SMEM_GEMM);
        cudaFuncSetAttribute(gemm_gru, cudaFuncAttributeMaxDynamicSharedMemorySize, SMEM_GEMM);
        cudaFuncSetAttribute(gemm_score, cudaFuncAttributeMaxDynamicSharedMemorySize, SMEM_GEMM);
        attr_set = true;
    }

    #define SYMA(p, s) void* p; cudaGetSymbolAddress(&p, s)
    SYMA(pXG, g_XGh);
    SYMA(pScore, g_score);
    SYMA(pWv, g_wv);
    SYMA(pScore2, g_score2);
    SYMA(pBih, g_bias_ih); SYMA(pBhh, g_bias_hh);
    SYMA(pBagF, g_bagF);
    SYMA(pWihH, g_WihH); SYMA(pWihL, g_WihL);
    SYMA(pWhhIH, g_WhhIH); SYMA(pWhhIL, g_WhhIL);
    SYMA(pWwH, g_WwordH); SYMA(pWwL, g_WwordL);
    SYMA(pWsH, g_WsentH); SYMA(pWsL, g_WsentL);
    SYMA(pOF, g_OUTF);
    SYMA(phA, g_hA); SYMA(phB, g_hB);
    SYMA(pwvF, g_wvF);
    #undef SYMA

    // ---- prep (3 launches), then input GEMM as launch #4 (ncu capture slot) ----
    k_conv_wih<<<(NIH * IND + 255) / 256, 256>>>(W_ih_f, W_ih_r);                       // 1
    k_conv_rest<<<(CW_TOT + 255) / 256, 256>>>(W_hh_f, W_hh_r, W_word, W_sent,          // 2
                                               b_ih_f, b_ih_r, b_hh_f, b_hh_r);
    {
        long long n = MM * (IND / 2);                                                   // 3
        k_conv_bag<<<(unsigned)((n + 255) / 256), 256>>>(bag);
    }
    {
        dim3 g(NPAD_IH / 128, (unsigned)(MM / 128), 1);                                 // 4
        gemm_f16s<<<g, 512, SMEM_GEMM>>>(
            (const __half*)pBagF,
            (const __half*)pWihH, (const __half*)pWihL,
            (const float*)pBih, (__half*)pXG,
            NIH, NIH, KPAD_IN, KPAD_IN / 64);
    }
    {
        int nw = 2 * BB * KPAD_H / 2;                                                   // 5
        k_zero_h2<<<(nw + 255) / 256, 256>>>((uint32_t*)phA, (uint32_t*)phB, nw);
    }
    k_zero<<<(out_size + 255) / 256, 256>>>(out, (long long)out_size);                  // 6

    // ---- GRU recurrence: one fused launch per step ----
    {
        dim3 g(NI_GRU / 128, BB / 128, 2);   // (8, 32, 2) = 512 blocks
        const __half* hbuf[2] = {(const __half*)phA, (const __half*)phB};
        for (int s = 0; s < TSTEPS; s++) {
            gemm_gru<<<g, 512, SMEM_GEMM>>>(
                hbuf[s & 1],
                (const __half*)pWhhIH, (const __half*)pWhhIL,
                (const float*)pBhh,
                (__half*)(s & 1 ? phA : phB), s);
        }
    }

    // ---- word attention: fused GEMM + tanh.proj score, fused softmax+wv ----
    gemm_score<<<(unsigned)(MM / 128), 512, SMEM_GEMM>>>(
        (const __half*)pOF,
        (const __half*)pWwH, (const __half*)pWwL,
        b_word, proj_word, (float*)pScore, H2, KPAD_W, KPAD_W / 64, NPAD_W / 128);
    k_word_attn<<<BB, 256>>>();

    // ---- sentence attention: fused GEMM + score, then softmax+FC+scatter ----
    gemm_score<<<BB / 128, 512, SMEM_GEMM>>>(
        (const __half*)pwvF,
        (const __half*)pWsH, (const __half*)pWsL,
        b_sent, proj_sent, (float*)pScore2, H2, KPAD_W, KPAD_W / 64, NPAD_W / 128);
    k_sent<<<NBAG, 256>>>(fc_W, fc_b, pairs, out);
}

// round 14
// speedup vs baseline: 4.4891x; 1.1614x over previous
#include <cuda_runtime.h>
#include <cuda_fp16.h>
#include <math.h>
#include <stdint.h>

// ---------------- problem constants ----------------
constexpr int NBAG   = 512;
constexpr int MSENT  = 8;
constexpr int TSTEPS = 64;
constexpr int IND    = 360;
constexpr int HID    = 230;
constexpr int OUTD   = 53;
constexpr int ENT    = 8;

constexpr int BB  = NBAG * MSENT;   // 4096
constexpr int H3  = 3 * HID;        // 690
constexpr int H2  = 2 * HID;        // 460
constexpr int NIH = 2 * H3;         // 1380
constexpr long long MM = (long long)TSTEPS * BB;  // 262144

constexpr int KPAD_IN = 384;
constexpr int NPAD_IH = 1408;
constexpr int KPAD_H  = 256;
constexpr int NI_GRU  = 1024;   // interleaved W_hh rows per dir: 32 groups x [r8|z8|n8|pad8]
constexpr int KPAD_W  = 512;
constexpr int NPAD_W  = 512;

// ---------------- device scratch ----------------
__device__ float g_bias_ih[NIH];
__device__ float g_bias_hh[2 * H3];
__device__ __half g_XGh[(size_t)MM * NIH];        // x@W_ih^T + b_ih, fp16
__device__ float g_score[TSTEPS * BB];
__device__ float g_wv[(size_t)BB * H2];
__device__ float g_score2[BB];

// A-side: single fp16. Recurrence/attn weights: fp16 hi+lo split.
// Input-proj weights: single fp16 (one-shot error, outside the recurrence chain).
__device__ __half g_bagF[(size_t)MM * KPAD_IN];
__device__ __half g_WihH[(size_t)NPAD_IH * KPAD_IN];
__device__ __half g_WhhIH[(size_t)2 * NI_GRU * KPAD_H];   // gate-interleaved
__device__ __half g_WhhIL[(size_t)2 * NI_GRU * KPAD_H];
__device__ __half g_WwordH[(size_t)NPAD_W * KPAD_W];
__device__ __half g_WwordL[(size_t)NPAD_W * KPAD_W];
__device__ __half g_WsentH[(size_t)NPAD_W * KPAD_W];
__device__ __half g_WsentL[(size_t)NPAD_W * KPAD_W];
__device__ __half g_OUTF[(size_t)MM * KPAD_W];
__device__ __half g_hA[(size_t)2 * BB * KPAD_H];          // double-buffered hidden state
__device__ __half g_hB[(size_t)2 * BB * KPAD_H];
__device__ __half g_wvF[(size_t)BB * KPAD_W];

// ---------------- helpers ----------------
__device__ __forceinline__ uint32_t smem_u32(const void* p) {
    uint32_t a;
    asm("{ .reg .u64 t; cvta.to.shared.u64 t, %1; cvt.u32.u64 %0, t; }" : "=r"(a) : "l"(p));
    return a;
}
__device__ __forceinline__ void ldm_x4(uint32_t* r, uint32_t addr) {
    asm volatile("ldmatrix.sync.aligned.m8n8.x4.shared.b16 {%0,%1,%2,%3}, [%4];"
                 : "=r"(r[0]), "=r"(r[1]), "=r"(r[2]), "=r"(r[3]) : "r"(addr));
}
__device__ __forceinline__ void mma16816(float* d, const uint32_t* a, const uint32_t* b) {
    asm volatile("mma.sync.aligned.m16n8k16.row.col.f32.f16.f16.f32 "
                 "{%0,%1,%2,%3}, {%4,%5,%6,%7}, {%8,%9}, {%0,%1,%2,%3};"
                 : "+f"(d[0]), "+f"(d[1]), "+f"(d[2]), "+f"(d[3])
                 : "r"(a[0]), "r"(a[1]), "r"(a[2]), "r"(a[3]), "r"(b[0]), "r"(b[1]));
}
__device__ __forceinline__ void cp_async16(uint32_t saddr, const void* gaddr) {
    asm volatile("cp.async.cg.shared.global [%0], [%1], 16;" :: "r"(saddr), "l"(gaddr));
}
#define CP_COMMIT() asm volatile("cp.async.commit_group;" ::: "memory")
#define CP_WAIT0()  asm volatile("cp.async.wait_group 0;" ::: "memory")

// BK = 64: rows of 128B data padded to 144B (bank-stride 36 mod 32 = 4 -> conflict-free).
constexpr int TPAD    = 144;
constexpr int TILE_SM = 128 * TPAD;        // 18432
constexpr int BUFSET  = 3 * TILE_SM;       // 55296 (Af, Bh, Bl) for 2-pass kernels
constexpr int SMEM_GEMM = 2 * BUFSET;      // 110592 -> 2 CTAs = 221 KB
constexpr int BUFSET1 = 2 * TILE_SM;       // 36864 (Af, Bh) single-pass
constexpr int SMEM_GEMM1 = 2 * BUFSET1;    // 73728

// load one BK=64 chunk of the 3 tiles (2-pass kernels)
#define LOAD_CHUNK(dst, off)                                        \
    do {                                                            \
        cp_async16((dst),                    srcA  + (off));        \
        cp_async16((dst) + 64,               srcA  + (off) + 32);   \
        cp_async16((dst) + TILE_SM,          srcBh + (off));        \
        cp_async16((dst) + TILE_SM + 64,     srcBh + (off) + 32);   \
        cp_async16((dst) + 2 * TILE_SM,      srcBl + (off));        \
        cp_async16((dst) + 2 * TILE_SM + 64, srcBl + (off) + 32);   \
    } while (0)

// load one BK=64 chunk of 2 tiles (single-pass kernel)
#define LOAD_CHUNK1(dst, off)                                       \
    do {                                                            \
        cp_async16((dst),                    srcA  + (off));        \
        cp_async16((dst) + 64,               srcA  + (off) + 32);   \
        cp_async16((dst) + TILE_SM,          srcBh + (off));        \
        cp_async16((dst) + TILE_SM + 64,     srcBh + (off) + 32);   \
    } while (0)

// ---------------- single-pass fp16 GEMM: C(half) = Af @ Bh^T + bias ----------------
// Used for the input projection only (one-shot precision, outside recurrence chain).
__global__ void __launch_bounds__(512, 2)
gemm_f16s(const __half* __restrict__ Af, const __half* __restrict__ Bh,
          const float* __restrict__ bias, __half* __restrict__ C,
          int N, int ldc, int Kpad, int nit)
{
    extern __shared__ __align__(16) unsigned char sm[];

    int tid = threadIdx.x;
    int lane = tid & 31, wid = tid >> 5;
    int wm = wid >> 2, wn = wid & 3;

    int m0 = blockIdx.y * 128, n0 = blockIdx.x * 128;

    int r0 = tid >> 2, c4 = tid & 3;
    const __half* srcA  = Af + (size_t)(m0 + r0) * Kpad + c4 * 8;
    const __half* srcBh = Bh + (size_t)(n0 + r0) * Kpad + c4 * 8;

    uint32_t smb = smem_u32(sm);
    uint32_t sdst = smb + r0 * TPAD + c4 * 16;

    float acc[2][4][4];
    #pragma unroll
    for (int i = 0; i < 2; i++)
        #pragma unroll
        for (int j = 0; j < 4; j++)
            #pragma unroll
            for (int q = 0; q < 4; q++) acc[i][j][q] = 0.f;

    int arow = (lane & 7) + (((lane >> 3) & 1) << 3);
    int acolb = ((lane >> 4) & 1) * 16;
    uint32_t aBase0 = smb + (wm * 32 + arow) * TPAD + acolb;
    int brow = (lane & 7) + (((lane >> 4) & 1) << 3);
    int bcolb = ((lane >> 3) & 1) * 16;
    uint32_t bhBase0 = smb + TILE_SM + (wn * 32 + brow) * TPAD + bcolb;

    LOAD_CHUNK1(sdst, 0);
    CP_COMMIT();

    int cur = 0;
    for (int kc = 0; kc < nit; kc++) {
        CP_WAIT0();
        __syncthreads();

        if (kc + 1 < nit) {
            LOAD_CHUNK1(sdst + (cur ^ 1) * BUFSET1, (kc + 1) * 64);
            CP_COMMIT();
        }

        uint32_t aBase  = aBase0  + cur * BUFSET1;
        uint32_t bhBase = bhBase0 + cur * BUFSET1;
        #pragma unroll
        for (int s = 0; s < 4; s++) {
            uint32_t af[2][4], bh2[2][4];
            #pragma unroll
            for (int i = 0; i < 2; i++)
                ldm_x4(af[i], aBase + i * 16 * TPAD + s * 32);
            #pragma unroll
            for (int jj = 0; jj < 2; jj++)
                ldm_x4(bh2[jj], bhBase + jj * 16 * TPAD + s * 32);
            #pragma unroll
            for (int i = 0; i < 2; i++)
                #pragma unroll
                for (int j = 0; j < 4; j++)
                    mma16816(acc[i][j], af[i], &bh2[j >> 1][(j & 1) * 2]);
        }
        cur ^= 1;
    }

    int qrow = lane >> 2, qcol = (lane & 3) * 2;
    #pragma unroll
    for (int i = 0; i < 2; i++) {
        #pragma unroll
        for (int j = 0; j < 4; j++) {
            int gc = n0 + wn * 32 + j * 8 + qcol;
            #pragma unroll
            for (int half = 0; half < 2; half++) {
                int gr = m0 + wm * 32 + i * 16 + qrow + half * 8;
                if (gc + 1 < N) {
                    __half2 hv;
                    hv.x = __float2half(acc[i][j][half * 2 + 0] + bias[gc]);
                    hv.y = __float2half(acc[i][j][half * 2 + 1] + bias[gc + 1]);
                    *(__half2*)(C + (size_t)gr * ldc + gc) = hv;
                }
            }
        }
    }
}

// ---------------- recurrence GEMM with fused GRU gate epilogue (2-pass) ----------------
// B = gate-interleaved W_hh (period 32: r8|z8|n8|pad8). jj=3 (pad) MMAs skipped.
__global__ void __launch_bounds__(512, 2)
gemm_gru(const __half* __restrict__ hIn, const __half* __restrict__ Bhw,
         const __half* __restrict__ Blw, const float* __restrict__ bias_hh,
         __half* __restrict__ hOut, int step)
{
    extern __shared__ __align__(16) unsigned char sm[];

    int tid = threadIdx.x;
    int lane = tid & 31, wid = tid >> 5;
    int wm = wid >> 2, wn = wid & 3;
    int d = blockIdx.z;

    const __half* Af  = hIn + (size_t)d * BB * KPAD_H;
    const __half* Bhd = Bhw + (size_t)d * NI_GRU * KPAD_H;
    const __half* Bld = Blw + (size_t)d * NI_GRU * KPAD_H;

    int m0 = blockIdx.y * 128, n0 = blockIdx.x * 128;

    int r0 = tid >> 2, c4 = tid & 3;
    const __half* srcA  = Af  + (size_t)(m0 + r0) * KPAD_H + c4 * 8;
    const __half* srcBh = Bhd + (size_t)(n0 + r0) * KPAD_H + c4 * 8;
    const __half* srcBl = Bld + (size_t)(n0 + r0) * KPAD_H + c4 * 8;

    uint32_t smb = smem_u32(sm);
    uint32_t sdst = smb + r0 * TPAD + c4 * 16;

    float acc[2][3][4];
    #pragma unroll
    for (int i = 0; i < 2; i++)
        #pragma unroll
        for (int j = 0; j < 3; j++)
            #pragma unroll
            for (int q = 0; q < 4; q++) acc[i][j][q] = 0.f;

    int arow = (lane & 7) + (((lane >> 3) & 1) << 3);
    int acolb = ((lane >> 4) & 1) * 16;
    uint32_t aBase0 = smb + (wm * 32 + arow) * TPAD + acolb;
    int brow = (lane & 7) + (((lane >> 4) & 1) << 3);
    int bcolb = ((lane >> 3) & 1) * 16;
    uint32_t bhBase0 = smb + TILE_SM + (wn * 32 + brow) * TPAD + bcolb;

    constexpr int nit = KPAD_H / 64;   // 4
    LOAD_CHUNK(sdst, 0);
    CP_COMMIT();

    int cur = 0;
    for (int kc = 0; kc < nit; kc++) {
        CP_WAIT0();
        __syncthreads();

        if (kc + 1 < nit) {
            LOAD_CHUNK(sdst + (cur ^ 1) * BUFSET, (kc + 1) * 64);
            CP_COMMIT();
        }

        uint32_t aBase  = aBase0  + cur * BUFSET;
        uint32_t bhBase = bhBase0 + cur * BUFSET;
        #pragma unroll
        for (int s = 0; s < 4; s++) {
            uint32_t af[2][4], bh2[2][4], bl2[2][4];
            #pragma unroll
            for (int i = 0; i < 2; i++)
                ldm_x4(af[i], aBase + i * 16 * TPAD + s * 32);
            #pragma unroll
            for (int jj = 0; jj < 2; jj++) {
                ldm_x4(bh2[jj], bhBase + jj * 16 * TPAD + s * 32);
                ldm_x4(bl2[jj], bhBase + TILE_SM + jj * 16 * TPAD + s * 32);
            }
            // jj slots 0..2 only (3 = pad)
            #pragma unroll
            for (int i = 0; i < 2; i++)
                #pragma unroll
                for (int j = 0; j < 3; j++)
                    mma16816(acc[i][j], af[i], &bh2[j >> 1][(j & 1) * 2]);
            #pragma unroll
            for (int i = 0; i < 2; i++)
                #pragma unroll
                for (int j = 0; j < 3; j++)
                    mma16816(acc[i][j], af[i], &bl2[j >> 1][(j & 1) * 2]);
        }
        cur ^= 1;
    }

    // ---- fused GRU gate epilogue ----
    int qrow = lane >> 2, qcol = (lane & 3) * 2;
    int kb = (blockIdx.x * 4 + wn) * 8 + qcol;
    if (kb < HID) {
        int t_eff = d ? (TSTEPS - 1 - step) : step;
        const float* bh_base = bias_hh + d * H3;
        float2 bhr = *(const float2*)(bh_base + kb);
        float2 bhz = *(const float2*)(bh_base + HID + kb);
        float2 bhn = *(const float2*)(bh_base + 2 * HID + kb);

        #pragma unroll
        for (int i = 0; i < 2; i++) {
            #pragma unroll
            for (int half = 0; half < 2; half++) {
                int b = m0 + wm * 32 + i * 16 + qrow + half * 8;
                const __half* xg = g_XGh + ((size_t)t_eff * BB + b) * NIH + d * H3;
                float2 xr = __half22float2(*(const __half2*)(xg + kb));
                float2 xz = __half22float2(*(const __half2*)(xg + HID + kb));
                float2 xn = __half22float2(*(const __half2*)(xg + 2 * HID + kb));
                size_t hoff = ((size_t)d * BB + b) * KPAD_H + kb;
                float2 hp = __half22float2(*(const __half2*)(hIn + hoff));

                float gr0 = acc[i][0][half * 2 + 0] + bhr.x;
                float gr1 = acc[i][0][half * 2 + 1] + bhr.y;
                float gz0 = acc[i][1][half * 2 + 0] + bhz.x;
                float gz1 = acc[i][1][half * 2 + 1] + bhz.y;
                float gn0 = acc[i][2][half * 2 + 0] + bhn.x;
                float gn1 = acc[i][2][half * 2 + 1] + bhn.y;

                float rr0 = 1.f / (1.f + __expf(-(xr.x + gr0)));
                float rr1 = 1.f / (1.f + __expf(-(xr.y + gr1)));
                float zz0 = 1.f / (1.f + __expf(-(xz.x + gz0)));
                float zz1 = 1.f / (1.f + __expf(-(xz.y + gz1)));
                float nn0 = tanhf(xn.x + rr0 * gn0);
                float nn1 = tanhf(xn.y + rr1 * gn1);
                float h0 = (1.f - zz0) * nn0 + zz0 * hp.x;
                float h1 = (1.f - zz1) * nn1 + zz1 * hp.y;

                __half2 oh; oh.x = __float2half(h0); oh.y = __float2half(h1);
                *(__half2*)(hOut + hoff) = oh;
                size_t oo = ((size_t)t_eff * BB + b) * KPAD_W + (size_t)d * HID + kb;
                *(__half2*)(g_OUTF + oo) = oh;
            }
        }
    }
}

// ---------------- fp16 2-pass GEMM with fused score epilogue ----------------
__global__ void __launch_bounds__(512, 2)
gemm_score(const __half* __restrict__ Af, const __half* __restrict__ Bh,
           const __half* __restrict__ Bl,
           const float* __restrict__ bias, const float* __restrict__ proj,
           float* __restrict__ score, int Nact, int Kpad, int nit, int nbt)
{
    extern __shared__ __align__(16) unsigned char sm[];

    int tid = threadIdx.x;
    int lane = tid & 31, wid = tid >> 5;
    int wm = wid >> 2, wn = wid & 3;
    int m0 = blockIdx.x * 128;

    int r0 = tid >> 2, c4 = tid & 3;
    const __half* srcA = Af + (size_t)(m0 + r0) * Kpad + c4 * 8;

    uint32_t smb = smem_u32(sm);
    uint32_t sdst = smb + r0 * TPAD + c4 * 16;

    int arow = (lane & 7) + (((lane >> 3) & 1) << 3);
    int acolb = ((lane >> 4) & 1) * 16;
    uint32_t aBase0 = smb + (wm * 32 + arow) * TPAD + acolb;
    int brow = (lane & 7) + (((lane >> 4) & 1) << 3);
    int bcolb = ((lane >> 3) & 1) * 16;
    uint32_t bhBase0 = smb + TILE_SM + (wn * 32 + brow) * TPAD + bcolb;

    int qrow = lane >> 2, qcol = (lane & 3) * 2;
    float sacc[2][2] = {{0.f, 0.f}, {0.f, 0.f}};

    for (int nb = 0; nb < nbt; nb++) {
        int n0 = nb * 128;
        const __half* srcBh = Bh + (size_t)(n0 + r0) * Kpad + c4 * 8;
        const __half* srcBl = Bl + (size_t)(n0 + r0) * Kpad + c4 * 8;

        float acc[2][4][4];
        #pragma unroll
        for (int i = 0; i < 2; i++)
            #pragma unroll
            for (int j = 0; j < 4; j++)
                #pragma unroll
                for (int q = 0; q < 4; q++) acc[i][j][q] = 0.f;

        __syncthreads();   // all warps done with previous nb's smem

        LOAD_CHUNK(sdst, 0);
        CP_COMMIT();

        int cur = 0;
        for (int kc = 0; kc < nit; kc++) {
            CP_WAIT0();
            __syncthreads();

            if (kc + 1 < nit) {
                LOAD_CHUNK(sdst + (cur ^ 1) * BUFSET, (kc + 1) * 64);
                CP_COMMIT();
            }

            uint32_t aBase  = aBase0  + cur * BUFSET;
            uint32_t bhBase = bhBase0 + cur * BUFSET;
            #pragma unroll
            for (int s = 0; s < 4; s++) {
                uint32_t af[2][4], bh2[2][4], bl2[2][4];
                #pragma unroll
                for (int i = 0; i < 2; i++)
                    ldm_x4(af[i], aBase + i * 16 * TPAD + s * 32);
                #pragma unroll
                for (int jj = 0; jj < 2; jj++) {
                    ldm_x4(bh2[jj], bhBase + jj * 16 * TPAD + s * 32);
                    ldm_x4(bl2[jj], bhBase + TILE_SM + jj * 16 * TPAD + s * 32);
                }
                #pragma unroll
                for (int i = 0; i < 2; i++)
                    #pragma unroll
                    for (int j = 0; j < 4; j++)
                        mma16816(acc[i][j], af[i], &bh2[j >> 1][(j & 1) * 2]);
                #pragma unroll
                for (int i = 0; i < 2; i++)
                    #pragma unroll
                    for (int j = 0; j < 4; j++)
                        mma16816(acc[i][j], af[i], &bl2[j >> 1][(j & 1) * 2]);
            }
            cur ^= 1;
        }

        #pragma unroll
        for (int i = 0; i < 2; i++) {
            #pragma unroll
            for (int j = 0; j < 4; j++) {
                int gc = n0 + wn * 32 + j * 8 + qcol;
                #pragma unroll
                for (int half = 0; half < 2; half++) {
                    if (gc < Nact)
                        sacc[i][half] += tanhf(acc[i][j][half * 2 + 0] + bias[gc]) * proj[gc];
                    if (gc + 1 < Nact)
                        sacc[i][half] += tanhf(acc[i][j][half * 2 + 1] + bias[gc + 1]) * proj[gc + 1];
                }
            }
        }
    }

    #pragma unroll
    for (int i = 0; i < 2; i++)
        #pragma unroll
        for (int half = 0; half < 2; half++) {
            float v = sacc[i][half];
            v += __shfl_xor_sync(0xffffffffu, v, 1);
            v += __shfl_xor_sync(0xffffffffu, v, 2);
            sacc[i][half] = v;
        }

    __syncthreads();
    float* sred = (float*)sm;
    if ((lane & 3) == 0) {
        #pragma unroll
        for (int i = 0; i < 2; i++)
            #pragma unroll
            for (int half = 0; half < 2; half++) {
                int rl = wm * 32 + i * 16 + half * 8 + qrow;
                sred[rl * 4 + wn] = sacc[i][half];
            }
    }
    __syncthreads();
    if (tid < 128) {
        float s = sred[tid * 4] + sred[tid * 4 + 1] + sred[tid * 4 + 2] + sred[tid * 4 + 3];
        score[m0 + tid] = s;
    }
}

// ---------------- conversion / prep kernels ----------------
__device__ __forceinline__ void split_f16(float v, __half* H, __half* L, size_t i) {
    __half h = __float2half(v);
    H[i] = h;
    L[i] = __float2half(v - __half2float(h));
}

__global__ void k_zero(float* p, long long n) {
    long long i = (long long)blockIdx.x * blockDim.x + threadIdx.x;
    if (i < n) p[i] = 0.f;
}
__global__ void k_zero_h2(uint32_t* a, uint32_t* b, int nw) {
    int i = blockIdx.x * 256 + threadIdx.x;
    if (i < nw) { a[i] = 0u; b[i] = 0u; }
}

__global__ void k_conv_wih(const float* __restrict__ Wf, const float* __restrict__ Wr) {
    int idx = blockIdx.x * 256 + threadIdx.x;
    if (idx >= NIH * IND) return;
    int n = idx / IND, k = idx % IND;
    float v = (n < H3) ? Wf[(size_t)n * IND + k] : Wr[(size_t)(n - H3) * IND + k];
    g_WihH[(size_t)n * KPAD_IN + k] = __float2half(v);
}

constexpr int CW_WHH = 2 * H3 * HID;
constexpr int CW_WW  = H2 * H2;
constexpr int CW_TOT = CW_WHH + 2 * CW_WW + NIH + 2 * H3;
__global__ void k_conv_rest(const float* __restrict__ Whf, const float* __restrict__ Whr,
                            const float* __restrict__ Ww, const float* __restrict__ Ws,
                            const float* __restrict__ bif, const float* __restrict__ bir,
                            const float* __restrict__ bhf, const float* __restrict__ bhr) {
    int idx = blockIdx.x * 256 + threadIdx.x;
    if (idx < CW_WHH) {
        int d = idx / (H3 * HID), r = idx % (H3 * HID);
        int n = r / HID, k = r % HID;       // n = gate*HID + kk
        int gate = n / HID;                  // 0,1,2
        int kk = n % HID;
        int c = (kk >> 3) * 32 + gate * 8 + (kk & 7);   // interleaved row
        const float* W = d ? Whr : Whf;
        split_f16(W[(size_t)n * HID + k], g_WhhIH, g_WhhIL,
                  ((size_t)d * NI_GRU + c) * KPAD_H + k);
        return;
    }
    idx -= CW_WHH;
    if (idx < CW_WW) {
        int n = idx / H2, k = idx % H2;
        split_f16(Ww[(size_t)k * H2 + n], g_WwordH, g_WwordL, (size_t)n * KPAD_W + k);
        return;
    }
    idx -= CW_WW;
    if (idx < CW_WW) {
        int n = idx / H2, k = idx % H2;
        split_f16(Ws[(size_t)k * H2 + n], g_WsentH, g_WsentL, (size_t)n * KPAD_W + k);
        return;
    }
    idx -= CW_WW;
    if (idx < NIH) { g_bias_ih[idx] = (idx < H3) ? bif[idx] : bir[idx - H3]; return; }
    idx -= NIH;
    if (idx < 2 * H3) g_bias_hh[idx] = (idx < H3) ? bhf[idx] : bhr[idx - H3];
}

__global__ void k_conv_bag(const float* __restrict__ bag) {
    size_t idx = (size_t)blockIdx.x * 256 + threadIdx.x;
    if (idx >= (size_t)MM * (IND / 2)) return;
    int j = (int)(idx % (IND / 2));
    size_t m = idx / (IND / 2);
    int tt = (int)(m >> 12), b = (int)(m & 4095);
    float2 v = *(const float2*)(bag + ((size_t)b * TSTEPS + tt) * IND + 2 * j);
    __half2 h; h.x = __float2half(v.x); h.y = __float2half(v.y);
    *(__half2*)(g_bagF + m * KPAD_IN + 2 * j) = h;
}

// ---------------- fused softmax-over-t + word_vec ----------------
__global__ void k_word_attn() {
    int b = blockIdx.x;
    int tid = threadIdx.x;
    __shared__ float sh[TSTEPS];
    __shared__ float al[TSTEPS];
    if (tid < TSTEPS) {
        float v = g_score[tid * BB + b];
        al[tid] = v; sh[tid] = v;
    }
    __syncthreads();
    #pragma unroll
    for (int o = 32; o; o >>= 1) {
        if (tid < o) sh[tid] = fmaxf(sh[tid], sh[tid + o]);
        __syncthreads();
    }
    float mx = sh[0];
    __syncthreads();
    if (tid < TSTEPS) {
        float e = __expf(al[tid] - mx);
        al[tid] = e; sh[tid] = e;
    }
    __syncthreads();
    #pragma unroll
    for (int o = 32; o; o >>= 1) {
        if (tid < o) sh[tid] += sh[tid + o];
        __syncthreads();
    }
    float inv = 1.f / sh[0];
    __syncthreads();
    if (tid < TSTEPS) al[tid] *= inv;
    __syncthreads();

    for (int h = tid; h < H2; h += blockDim.x) {
        float acc = 0.f;
        #pragma unroll 8
        for (int t = 0; t < TSTEPS; t++)
            acc += al[t] * __half2float(g_OUTF[((size_t)t * BB + b) * KPAD_W + h]);
        g_wv[(size_t)b * H2 + h] = acc;
        g_wvF[(size_t)b * KPAD_W + h] = __float2half(acc);
    }
}

// ---------------- sentence softmax + weighted sum + FC + scatter ----------------
__global__ void k_sent(const float* __restrict__ fcW, const float* __restrict__ fcb,
                       const int* __restrict__ pairs, float* __restrict__ out) {
    int nb = blockIdx.x;
    __shared__ float beta[MSENT];
    __shared__ float sv[H2];
    if (threadIdx.x == 0) {
        float v[MSENT], mx = -1e30f;
        #pragma unroll
        for (int s = 0; s < MSENT; s++) { v[s] = g_score2[nb * MSENT + s]; mx = fmaxf(mx, v[s]); }
        float sum = 0.f;
        #pragma unroll
        for (int s = 0; s < MSENT; s++) { v[s] = expf(v[s] - mx); sum += v[s]; }
        #pragma unroll
        for (int s = 0; s < MSENT; s++) beta[s] = v[s] / sum;
    }
    __syncthreads();
    for (int h = threadIdx.x; h < H2; h += blockDim.x) {
        float acc = 0.f;
        #pragma unroll
        for (int s = 0; s < MSENT; s++)
            acc += beta[s] * g_wv[((size_t)(nb * MSENT + s)) * H2 + h];
        sv[h] = acc;
    }
    __syncthreads();
    const int* p = pairs + nb * 3;
    int base = ((p[0] * ENT + p[1]) * ENT + p[2]) * OUTD;
    for (int o = threadIdx.x; o < OUTD; o += blockDim.x) {
        float acc = fcb[o];
        for (int h = 0; h < H2; h++) acc += sv[h] * fcW[(size_t)o * H2 + h];
        out[base + o] = acc;
    }
}

// ---------------- launcher ----------------
extern "C" void kernel_launch(void* const* d_in, const int* in_sizes, int n_in,
                              void* d_out, int out_size) {
    const float* bag       = (const float*)d_in[0];
    const float* W_ih_f    = (const float*)d_in[1];
    const float* W_hh_f    = (const float*)d_in[2];
    const float* b_ih_f    = (const float*)d_in[3];
    const float* b_hh_f    = (const float*)d_in[4];
    const float* W_ih_r    = (const float*)d_in[5];
    const float* W_hh_r    = (const float*)d_in[6];
    const float* b_ih_r    = (const float*)d_in[7];
    const float* b_hh_r    = (const float*)d_in[8];
    const float* W_word    = (const float*)d_in[9];
    const float* b_word    = (const float*)d_in[10];
    const float* proj_word = (const float*)d_in[11];
    const float* W_sent    = (const float*)d_in[12];
    const float* b_sent    = (const float*)d_in[13];
    const float* proj_sent = (const float*)d_in[14];
    const float* fc_W      = (const float*)d_in[15];
    const float* fc_b      = (const float*)d_in[16];
    const int*   pairs     = (const int*)d_in[17];
    float* out = (float*)d_out;

    static bool attr_set = false;
    if (!attr_set) {
        cudaFuncSetAttribute(gemm_f16s, cudaFuncAttributeMaxDynamicSharedMemorySize, SMEM_GEMM1);
        cudaFuncSetAttribute(gemm_gru, cudaFuncAttributeMaxDynamicSharedMemorySize, SMEM_GEMM);
        cudaFuncSetAttribute(gemm_score, cudaFuncAttributeMaxDynamicSharedMemorySize, SMEM_GEMM);
        attr_set = true;
    }

    #define SYMA(p, s) void* p; cudaGetSymbolAddress(&p, s)
    SYMA(pXG, g_XGh);
    SYMA(pScore, g_score);
    SYMA(pWv, g_wv);
    SYMA(pScore2, g_score2);
    SYMA(pBih, g_bias_ih); SYMA(pBhh, g_bias_hh);
    SYMA(pBagF, g_bagF);
    SYMA(pWihH, g_WihH);
    SYMA(pWhhIH, g_WhhIH); SYMA(pWhhIL, g_WhhIL);
    SYMA(pWwH, g_WwordH); SYMA(pWwL, g_WwordL);
    SYMA(pWsH, g_WsentH); SYMA(pWsL, g_WsentL);
    SYMA(pOF, g_OUTF);
    SYMA(phA, g_hA); SYMA(phB, g_hB);
    SYMA(pwvF, g_wvF);
    #undef SYMA

    // ---- prep (3 launches), then input GEMM as launch #4 (ncu capture slot) ----
    k_conv_wih<<<(NIH * IND + 255) / 256, 256>>>(W_ih_f, W_ih_r);                       // 1
    k_conv_rest<<<(CW_TOT + 255) / 256, 256>>>(W_hh_f, W_hh_r, W_word, W_sent,          // 2
                                               b_ih_f, b_ih_r, b_hh_f, b_hh_r);
    {
        long long n = MM * (IND / 2);                                                   // 3
        k_conv_bag<<<(unsigned)((n + 255) / 256), 256>>>(bag);
    }
    {
        dim3 g(NPAD_IH / 128, (unsigned)(MM / 128), 1);                                 // 4
        gemm_f16s<<<g, 512, SMEM_GEMM1>>>(
            (const __half*)pBagF, (const __half*)pWihH,
            (const float*)pBih, (__half*)pXG,
            NIH, NIH, KPAD_IN, KPAD_IN / 64);
    }
    {
        int nw = 2 * BB * KPAD_H / 2;                                                   // 5
        k_zero_h2<<<(nw + 255) / 256, 256>>>((uint32_t*)phA, (uint32_t*)phB, nw);
    }
    k_zero<<<(out_size + 255) / 256, 256>>>(out, (long long)out_size);                  // 6

    // ---- GRU recurrence: one fused launch per step ----
    {
        dim3 g(NI_GRU / 128, BB / 128, 2);   // (8, 32, 2) = 512 blocks
        const __half* hbuf[2] = {(const __half*)phA, (const __half*)phB};
        for (int s = 0; s < TSTEPS; s++) {
            gemm_gru<<<g, 512, SMEM_GEMM>>>(
                hbuf[s & 1],
                (const __half*)pWhhIH, (const __half*)pWhhIL,
                (const float*)pBhh,
                (__half*)(s & 1 ? phA : phB), s);
        }
    }

    // ---- word attention: fused GEMM + tanh.proj score, fused softmax+wv ----
    gemm_score<<<(unsigned)(MM / 128), 512, SMEM_GEMM>>>(
        (const __half*)pOF,
        (const __half*)pWwH, (const __half*)pWwL,
        b_word, proj_word, (float*)pScore, H2, KPAD_W, KPAD_W / 64, NPAD_W / 128);
    k_word_attn<<<BB, 256>>>();

    // ---- sentence attention: fused GEMM + score, then softmax+FC+scatter ----
    gemm_score<<<BB / 128, 512, SMEM_GEMM>>>(
        (const __half*)pwvF,
        (const __half*)pWsH, (const __half*)pWsL,
        b_sent, proj_sent, (float*)pScore2, H2, KPAD_W, KPAD_W / 64, NPAD_W / 128);
    k_sent<<<NBAG, 256>>>(fc_W, fc_b, pairs, out);
}

// round 15
// speedup vs baseline: 4.9571x; 1.1043x over previous
#include <cuda_runtime.h>
#include <cuda_fp16.h>
#include <math.h>
#include <stdint.h>

// ---------------- problem constants ----------------
constexpr int NBAG   = 512;
constexpr int MSENT  = 8;
constexpr int TSTEPS = 64;
constexpr int IND    = 360;
constexpr int HID    = 230;
constexpr int OUTD   = 53;
constexpr int ENT    = 8;

constexpr int BB  = NBAG * MSENT;   // 4096
constexpr int H3  = 3 * HID;        // 690
constexpr int H2  = 2 * HID;        // 460
constexpr int NIH = 2 * H3;         // 1380
constexpr long long MM = (long long)TSTEPS * BB;  // 262144

constexpr int KPAD_IN = 384;
constexpr int NPAD_IH = 1408;
constexpr int KPAD_H  = 256;
constexpr int NI_GRU  = 1024;   // interleaved W_hh rows per dir: 32 groups x [r8|z8|n8|pad8]
constexpr int KPAD_W  = 512;
constexpr int NPAD_W  = 512;

// ---------------- device scratch ----------------
__device__ float g_bias_ih[NIH];
__device__ float g_bias_hh[2 * H3];
__device__ __half g_XGh[(size_t)MM * NIH];        // x@W_ih^T + b_ih, fp16
__device__ float g_score[TSTEPS * BB];
__device__ float g_wv[(size_t)BB * H2];
__device__ float g_score2[BB];

// A-side fp16 everywhere. Recurrence weights: fp16 hi+lo split (compounding chain).
// One-shot weights (input proj, word, sent): single fp16.
__device__ __half g_bagF[(size_t)MM * KPAD_IN];
__device__ __half g_WihH[(size_t)NPAD_IH * KPAD_IN];
__device__ __half g_WhhIH[(size_t)2 * NI_GRU * KPAD_H];   // gate-interleaved
__device__ __half g_WhhIL[(size_t)2 * NI_GRU * KPAD_H];
__device__ __half g_WwordH[(size_t)NPAD_W * KPAD_W];
__device__ __half g_WsentH[(size_t)NPAD_W * KPAD_W];
__device__ __half g_OUTF[(size_t)MM * KPAD_W];
__device__ __half g_hA[(size_t)2 * BB * KPAD_H];          // double-buffered hidden state
__device__ __half g_hB[(size_t)2 * BB * KPAD_H];
__device__ __half g_wvF[(size_t)BB * KPAD_W];

// ---------------- helpers ----------------
__device__ __forceinline__ uint32_t smem_u32(const void* p) {
    uint32_t a;
    asm("{ .reg .u64 t; cvta.to.shared.u64 t, %1; cvt.u32.u64 %0, t; }" : "=r"(a) : "l"(p));
    return a;
}
__device__ __forceinline__ void ldm_x4(uint32_t* r, uint32_t addr) {
    asm volatile("ldmatrix.sync.aligned.m8n8.x4.shared.b16 {%0,%1,%2,%3}, [%4];"
                 : "=r"(r[0]), "=r"(r[1]), "=r"(r[2]), "=r"(r[3]) : "r"(addr));
}
__device__ __forceinline__ void mma16816(float* d, const uint32_t* a, const uint32_t* b) {
    asm volatile("mma.sync.aligned.m16n8k16.row.col.f32.f16.f16.f32 "
                 "{%0,%1,%2,%3}, {%4,%5,%6,%7}, {%8,%9}, {%0,%1,%2,%3};"
                 : "+f"(d[0]), "+f"(d[1]), "+f"(d[2]), "+f"(d[3])
                 : "r"(a[0]), "r"(a[1]), "r"(a[2]), "r"(a[3]), "r"(b[0]), "r"(b[1]));
}
__device__ __forceinline__ void cp_async16(uint32_t saddr, const void* gaddr) {
    asm volatile("cp.async.cg.shared.global [%0], [%1], 16;" :: "r"(saddr), "l"(gaddr));
}
#define CP_COMMIT() asm volatile("cp.async.commit_group;" ::: "memory")
#define CP_WAIT0()  asm volatile("cp.async.wait_group 0;" ::: "memory")

// BK = 64: rows of 128B data padded to 144B (bank-stride 36 mod 32 = 4 -> conflict-free).
constexpr int TPAD    = 144;
constexpr int TILE_SM = 128 * TPAD;        // 18432
constexpr int BUFSET  = 3 * TILE_SM;       // 55296 (Af, Bh, Bl) 2-pass (recurrence)
constexpr int SMEM_GEMM = 2 * BUFSET;      // 110592 -> 2 CTAs = 221 KB
constexpr int BUFSET1 = 2 * TILE_SM;       // 36864 (Af, Bh) single-pass
constexpr int SMEM_GEMM1 = 2 * BUFSET1;    // 73728

// load one BK=64 chunk of the 3 tiles (2-pass kernels)
#define LOAD_CHUNK(dst, off)                                        \
    do {                                                            \
        cp_async16((dst),                    srcA  + (off));        \
        cp_async16((dst) + 64,               srcA  + (off) + 32);   \
        cp_async16((dst) + TILE_SM,          srcBh + (off));        \
        cp_async16((dst) + TILE_SM + 64,     srcBh + (off) + 32);   \
        cp_async16((dst) + 2 * TILE_SM,      srcBl + (off));        \
        cp_async16((dst) + 2 * TILE_SM + 64, srcBl + (off) + 32);   \
    } while (0)

// load one BK=64 chunk of 2 tiles (single-pass kernels)
#define LOAD_CHUNK1(dst, off)                                       \
    do {                                                            \
        cp_async16((dst),                    srcA  + (off));        \
        cp_async16((dst) + 64,               srcA  + (off) + 32);   \
        cp_async16((dst) + TILE_SM,          srcBh + (off));        \
        cp_async16((dst) + TILE_SM + 64,     srcBh + (off) + 32);   \
    } while (0)

// ---------------- single-pass fp16 GEMM: C(half) = Af @ Bh^T + bias ----------------
__global__ void __launch_bounds__(512, 2)
gemm_f16s(const __half* __restrict__ Af, const __half* __restrict__ Bh,
          const float* __restrict__ bias, __half* __restrict__ C,
          int N, int ldc, int Kpad, int nit)
{
    extern __shared__ __align__(16) unsigned char sm[];

    int tid = threadIdx.x;
    int lane = tid & 31, wid = tid >> 5;
    int wm = wid >> 2, wn = wid & 3;

    int m0 = blockIdx.y * 128, n0 = blockIdx.x * 128;

    int r0 = tid >> 2, c4 = tid & 3;
    const __half* srcA  = Af + (size_t)(m0 + r0) * Kpad + c4 * 8;
    const __half* srcBh = Bh + (size_t)(n0 + r0) * Kpad + c4 * 8;

    uint32_t smb = smem_u32(sm);
    uint32_t sdst = smb + r0 * TPAD + c4 * 16;

    float acc[2][4][4];
    #pragma unroll
    for (int i = 0; i < 2; i++)
        #pragma unroll
        for (int j = 0; j < 4; j++)
            #pragma unroll
            for (int q = 0; q < 4; q++) acc[i][j][q] = 0.f;

    int arow = (lane & 7) + (((lane >> 3) & 1) << 3);
    int acolb = ((lane >> 4) & 1) * 16;
    uint32_t aBase0 = smb + (wm * 32 + arow) * TPAD + acolb;
    int brow = (lane & 7) + (((lane >> 4) & 1) << 3);
    int bcolb = ((lane >> 3) & 1) * 16;
    uint32_t bhBase0 = smb + TILE_SM + (wn * 32 + brow) * TPAD + bcolb;

    LOAD_CHUNK1(sdst, 0);
    CP_COMMIT();

    int cur = 0;
    for (int kc = 0; kc < nit; kc++) {
        CP_WAIT0();
        __syncthreads();

        if (kc + 1 < nit) {
            LOAD_CHUNK1(sdst + (cur ^ 1) * BUFSET1, (kc + 1) * 64);
            CP_COMMIT();
        }

        uint32_t aBase  = aBase0  + cur * BUFSET1;
        uint32_t bhBase = bhBase0 + cur * BUFSET1;
        #pragma unroll
        for (int s = 0; s < 4; s++) {
            uint32_t af[2][4], bh2[2][4];
            #pragma unroll
            for (int i = 0; i < 2; i++)
                ldm_x4(af[i], aBase + i * 16 * TPAD + s * 32);
            #pragma unroll
            for (int jj = 0; jj < 2; jj++)
                ldm_x4(bh2[jj], bhBase + jj * 16 * TPAD + s * 32);
            #pragma unroll
            for (int i = 0; i < 2; i++)
                #pragma unroll
                for (int j = 0; j < 4; j++)
                    mma16816(acc[i][j], af[i], &bh2[j >> 1][(j & 1) * 2]);
        }
        cur ^= 1;
    }

    int qrow = lane >> 2, qcol = (lane & 3) * 2;
    #pragma unroll
    for (int i = 0; i < 2; i++) {
        #pragma unroll
        for (int j = 0; j < 4; j++) {
            int gc = n0 + wn * 32 + j * 8 + qcol;
            #pragma unroll
            for (int half = 0; half < 2; half++) {
                int gr = m0 + wm * 32 + i * 16 + qrow + half * 8;
                if (gc + 1 < N) {
                    __half2 hv;
                    hv.x = __float2half(acc[i][j][half * 2 + 0] + bias[gc]);
                    hv.y = __float2half(acc[i][j][half * 2 + 1] + bias[gc + 1]);
                    *(__half2*)(C + (size_t)gr * ldc + gc) = hv;
                }
            }
        }
    }
}

// ---------------- recurrence GEMM with fused GRU gate epilogue (2-pass) ----------------
// B = gate-interleaved W_hh (period 32: r8|z8|n8|pad8). jj=3 (pad) MMAs skipped.
__global__ void __launch_bounds__(512, 2)
gemm_gru(const __half* __restrict__ hIn, const __half* __restrict__ Bhw,
         const __half* __restrict__ Blw, const float* __restrict__ bias_hh,
         __half* __restrict__ hOut, int step)
{
    extern __shared__ __align__(16) unsigned char sm[];

    int tid = threadIdx.x;
    int lane = tid & 31, wid = tid >> 5;
    int wm = wid >> 2, wn = wid & 3;
    int d = blockIdx.z;

    const __half* Af  = hIn + (size_t)d * BB * KPAD_H;
    const __half* Bhd = Bhw + (size_t)d * NI_GRU * KPAD_H;
    const __half* Bld = Blw + (size_t)d * NI_GRU * KPAD_H;

    int m0 = blockIdx.y * 128, n0 = blockIdx.x * 128;

    int r0 = tid >> 2, c4 = tid & 3;
    const __half* srcA  = Af  + (size_t)(m0 + r0) * KPAD_H + c4 * 8;
    const __half* srcBh = Bhd + (size_t)(n0 + r0) * KPAD_H + c4 * 8;
    const __half* srcBl = Bld + (size_t)(n0 + r0) * KPAD_H + c4 * 8;

    uint32_t smb = smem_u32(sm);
    uint32_t sdst = smb + r0 * TPAD + c4 * 16;

    float acc[2][3][4];
    #pragma unroll
    for (int i = 0; i < 2; i++)
        #pragma unroll
        for (int j = 0; j < 3; j++)
            #pragma unroll
            for (int q = 0; q < 4; q++) acc[i][j][q] = 0.f;

    int arow = (lane & 7) + (((lane >> 3) & 1) << 3);
    int acolb = ((lane >> 4) & 1) * 16;
    uint32_t aBase0 = smb + (wm * 32 + arow) * TPAD + acolb;
    int brow = (lane & 7) + (((lane >> 4) & 1) << 3);
    int bcolb = ((lane >> 3) & 1) * 16;
    uint32_t bhBase0 = smb + TILE_SM + (wn * 32 + brow) * TPAD + bcolb;

    constexpr int nit = KPAD_H / 64;   // 4
    LOAD_CHUNK(sdst, 0);
    CP_COMMIT();

    int cur = 0;
    for (int kc = 0; kc < nit; kc++) {
        CP_WAIT0();
        __syncthreads();

        if (kc + 1 < nit) {
            LOAD_CHUNK(sdst + (cur ^ 1) * BUFSET, (kc + 1) * 64);
            CP_COMMIT();
        }

        uint32_t aBase  = aBase0  + cur * BUFSET;
        uint32_t bhBase = bhBase0 + cur * BUFSET;
        #pragma unroll
        for (int s = 0; s < 4; s++) {
            uint32_t af[2][4], bh2[2][4], bl2[2][4];
            #pragma unroll
            for (int i = 0; i < 2; i++)
                ldm_x4(af[i], aBase + i * 16 * TPAD + s * 32);
            #pragma unroll
            for (int jj = 0; jj < 2; jj++) {
                ldm_x4(bh2[jj], bhBase + jj * 16 * TPAD + s * 32);
                ldm_x4(bl2[jj], bhBase + TILE_SM + jj * 16 * TPAD + s * 32);
            }
            // jj slots 0..2 only (3 = pad)
            #pragma unroll
            for (int i = 0; i < 2; i++)
                #pragma unroll
                for (int j = 0; j < 3; j++)
                    mma16816(acc[i][j], af[i], &bh2[j >> 1][(j & 1) * 2]);
            #pragma unroll
            for (int i = 0; i < 2; i++)
                #pragma unroll
                for (int j = 0; j < 3; j++)
                    mma16816(acc[i][j], af[i], &bl2[j >> 1][(j & 1) * 2]);
        }
        cur ^= 1;
    }

    // ---- fused GRU gate epilogue ----
    int qrow = lane >> 2, qcol = (lane & 3) * 2;
    int kb = (blockIdx.x * 4 + wn) * 8 + qcol;
    if (kb < HID) {
        int t_eff = d ? (TSTEPS - 1 - step) : step;
        const float* bh_base = bias_hh + d * H3;
        float2 bhr = *(const float2*)(bh_base + kb);
        float2 bhz = *(const float2*)(bh_base + HID + kb);
        float2 bhn = *(const float2*)(bh_base + 2 * HID + kb);

        #pragma unroll
        for (int i = 0; i < 2; i++) {
            #pragma unroll
            for (int half = 0; half < 2; half++) {
                int b = m0 + wm * 32 + i * 16 + qrow + half * 8;
                const __half* xg = g_XGh + ((size_t)t_eff * BB + b) * NIH + d * H3;
                float2 xr = __half22float2(*(const __half2*)(xg + kb));
                float2 xz = __half22float2(*(const __half2*)(xg + HID + kb));
                float2 xn = __half22float2(*(const __half2*)(xg + 2 * HID + kb));
                size_t hoff = ((size_t)d * BB + b) * KPAD_H + kb;
                float2 hp = __half22float2(*(const __half2*)(hIn + hoff));

                float gr0 = acc[i][0][half * 2 + 0] + bhr.x;
                float gr1 = acc[i][0][half * 2 + 1] + bhr.y;
                float gz0 = acc[i][1][half * 2 + 0] + bhz.x;
                float gz1 = acc[i][1][half * 2 + 1] + bhz.y;
                float gn0 = acc[i][2][half * 2 + 0] + bhn.x;
                float gn1 = acc[i][2][half * 2 + 1] + bhn.y;

                float rr0 = 1.f / (1.f + __expf(-(xr.x + gr0)));
                float rr1 = 1.f / (1.f + __expf(-(xr.y + gr1)));
                float zz0 = 1.f / (1.f + __expf(-(xz.x + gz0)));
                float zz1 = 1.f / (1.f + __expf(-(xz.y + gz1)));
                float nn0 = tanhf(xn.x + rr0 * gn0);
                float nn1 = tanhf(xn.y + rr1 * gn1);
                float h0 = (1.f - zz0) * nn0 + zz0 * hp.x;
                float h1 = (1.f - zz1) * nn1 + zz1 * hp.y;

                __half2 oh; oh.x = __float2half(h0); oh.y = __float2half(h1);
                *(__half2*)(hOut + hoff) = oh;
                size_t oo = ((size_t)t_eff * BB + b) * KPAD_W + (size_t)d * HID + kb;
                *(__half2*)(g_OUTF + oo) = oh;
            }
        }
    }
}

// ---------------- single-pass fp16 GEMM with fused score epilogue ----------------
// score[m] = sum_n tanh((A@Bh^T)[m,n] + bias[n]) * proj[n], n < Nact.
__global__ void __launch_bounds__(512, 2)
gemm_score(const __half* __restrict__ Af, const __half* __restrict__ Bh,
           const float* __restrict__ bias, const float* __restrict__ proj,
           float* __restrict__ score, int Nact, int Kpad, int nit, int nbt)
{
    extern __shared__ __align__(16) unsigned char sm[];

    int tid = threadIdx.x;
    int lane = tid & 31, wid = tid >> 5;
    int wm = wid >> 2, wn = wid & 3;
    int m0 = blockIdx.x * 128;

    int r0 = tid >> 2, c4 = tid & 3;
    const __half* srcA = Af + (size_t)(m0 + r0) * Kpad + c4 * 8;

    uint32_t smb = smem_u32(sm);
    uint32_t sdst = smb + r0 * TPAD + c4 * 16;

    int arow = (lane & 7) + (((lane >> 3) & 1) << 3);
    int acolb = ((lane >> 4) & 1) * 16;
    uint32_t aBase0 = smb + (wm * 32 + arow) * TPAD + acolb;
    int brow = (lane & 7) + (((lane >> 4) & 1) << 3);
    int bcolb = ((lane >> 3) & 1) * 16;
    uint32_t bhBase0 = smb + TILE_SM + (wn * 32 + brow) * TPAD + bcolb;

    int qrow = lane >> 2, qcol = (lane & 3) * 2;
    float sacc[2][2] = {{0.f, 0.f}, {0.f, 0.f}};

    for (int nb = 0; nb < nbt; nb++) {
        int n0 = nb * 128;
        const __half* srcBh = Bh + (size_t)(n0 + r0) * Kpad + c4 * 8;

        float acc[2][4][4];
        #pragma unroll
        for (int i = 0; i < 2; i++)
            #pragma unroll
            for (int j = 0; j < 4; j++)
                #pragma unroll
                for (int q = 0; q < 4; q++) acc[i][j][q] = 0.f;

        __syncthreads();   // all warps done with previous nb's smem

        LOAD_CHUNK1(sdst, 0);
        CP_COMMIT();

        int cur = 0;
        for (int kc = 0; kc < nit; kc++) {
            CP_WAIT0();
            __syncthreads();

            if (kc + 1 < nit) {
                LOAD_CHUNK1(sdst + (cur ^ 1) * BUFSET1, (kc + 1) * 64);
                CP_COMMIT();
            }

            uint32_t aBase  = aBase0  + cur * BUFSET1;
            uint32_t bhBase = bhBase0 + cur * BUFSET1;
            #pragma unroll
            for (int s = 0; s < 4; s++) {
                uint32_t af[2][4], bh2[2][4];
                #pragma unroll
                for (int i = 0; i < 2; i++)
                    ldm_x4(af[i], aBase + i * 16 * TPAD + s * 32);
                #pragma unroll
                for (int jj = 0; jj < 2; jj++)
                    ldm_x4(bh2[jj], bhBase + jj * 16 * TPAD + s * 32);
                #pragma unroll
                for (int i = 0; i < 2; i++)
                    #pragma unroll
                    for (int j = 0; j < 4; j++)
                        mma16816(acc[i][j], af[i], &bh2[j >> 1][(j & 1) * 2]);
            }
            cur ^= 1;
        }

        #pragma unroll
        for (int i = 0; i < 2; i++) {
            #pragma unroll
            for (int j = 0; j < 4; j++) {
                int gc = n0 + wn * 32 + j * 8 + qcol;
                #pragma unroll
                for (int half = 0; half < 2; half++) {
                    if (gc < Nact)
                        sacc[i][half] += tanhf(acc[i][j][half * 2 + 0] + bias[gc]) * proj[gc];
                    if (gc + 1 < Nact)
                        sacc[i][half] += tanhf(acc[i][j][half * 2 + 1] + bias[gc + 1]) * proj[gc + 1];
                }
            }
        }
    }

    #pragma unroll
    for (int i = 0; i < 2; i++)
        #pragma unroll
        for (int half = 0; half < 2; half++) {
            float v = sacc[i][half];
            v += __shfl_xor_sync(0xffffffffu, v, 1);
            v += __shfl_xor_sync(0xffffffffu, v, 2);
            sacc[i][half] = v;
        }

    __syncthreads();
    float* sred = (float*)sm;
    if ((lane & 3) == 0) {
        #pragma unroll
        for (int i = 0; i < 2; i++)
            #pragma unroll
            for (int half = 0; half < 2; half++) {
                int rl = wm * 32 + i * 16 + half * 8 + qrow;
                sred[rl * 4 + wn] = sacc[i][half];
            }
    }
    __syncthreads();
    if (tid < 128) {
        float s = sred[tid * 4] + sred[tid * 4 + 1] + sred[tid * 4 + 2] + sred[tid * 4 + 3];
        score[m0 + tid] = s;
    }
}

// ---------------- conversion / prep kernels ----------------
__device__ __forceinline__ void split_f16(float v, __half* H, __half* L, size_t i) {
    __half h = __float2half(v);
    H[i] = h;
    L[i] = __float2half(v - __half2float(h));
}

__global__ void k_zero(float* p, long long n) {
    long long i = (long long)blockIdx.x * blockDim.x + threadIdx.x;
    if (i < n) p[i] = 0.f;
}
__global__ void k_zero_h2(uint32_t* a, uint32_t* b, int nw) {
    int i = blockIdx.x * 256 + threadIdx.x;
    if (i < nw) { a[i] = 0u; b[i] = 0u; }
}

__global__ void k_conv_wih(const float* __restrict__ Wf, const float* __restrict__ Wr) {
    int idx = blockIdx.x * 256 + threadIdx.x;
    if (idx >= NIH * IND) return;
    int n = idx / IND, k = idx % IND;
    float v = (n < H3) ? Wf[(size_t)n * IND + k] : Wr[(size_t)(n - H3) * IND + k];
    g_WihH[(size_t)n * KPAD_IN + k] = __float2half(v);
}

constexpr int CW_WHH = 2 * H3 * HID;
constexpr int CW_WW  = H2 * H2;
constexpr int CW_TOT = CW_WHH + 2 * CW_WW + NIH + 2 * H3;
__global__ void k_conv_rest(const float* __restrict__ Whf, const float* __restrict__ Whr,
                            const float* __restrict__ Ww, const float* __restrict__ Ws,
                            const float* __restrict__ bif, const float* __restrict__ bir,
                            const float* __restrict__ bhf, const float* __restrict__ bhr) {
    int idx = blockIdx.x * 256 + threadIdx.x;
    if (idx < CW_WHH) {
        int d = idx / (H3 * HID), r = idx % (H3 * HID);
        int n = r / HID, k = r % HID;       // n = gate*HID + kk
        int gate = n / HID;                  // 0,1,2
        int kk = n % HID;
        int c = (kk >> 3) * 32 + gate * 8 + (kk & 7);   // interleaved row
        const float* W = d ? Whr : Whf;
        split_f16(W[(size_t)n * HID + k], g_WhhIH, g_WhhIL,
                  ((size_t)d * NI_GRU + c) * KPAD_H + k);
        return;
    }
    idx -= CW_WHH;
    if (idx < CW_WW) {
        int n = idx / H2, k = idx % H2;
        g_WwordH[(size_t)n * KPAD_W + k] = __float2half(Ww[(size_t)k * H2 + n]);
        return;
    }
    idx -= CW_WW;
    if (idx < CW_WW) {
        int n = idx / H2, k = idx % H2;
        g_WsentH[(size_t)n * KPAD_W + k] = __float2half(Ws[(size_t)k * H2 + n]);
        return;
    }
    idx -= CW_WW;
    if (idx < NIH) { g_bias_ih[idx] = (idx < H3) ? bif[idx] : bir[idx - H3]; return; }
    idx -= NIH;
    if (idx < 2 * H3) g_bias_hh[idx] = (idx < H3) ? bhf[idx] : bhr[idx - H3];
}

__global__ void k_conv_bag(const float* __restrict__ bag) {
    size_t idx = (size_t)blockIdx.x * 256 + threadIdx.x;   // over MM * 90 (float4 groups)
    if (idx >= (size_t)MM * (IND / 4)) return;
    int j = (int)(idx % (IND / 4));
    size_t m = idx / (IND / 4);
    int tt = (int)(m >> 12), b = (int)(m & 4095);
    float4 v = *(const float4*)(bag + ((size_t)b * TSTEPS + tt) * IND + 4 * j);
    __half2 h0; h0.x = __float2half(v.x); h0.y = __float2half(v.y);
    __half2 h1; h1.x = __float2half(v.z); h1.y = __float2half(v.w);
    size_t o = m * KPAD_IN + 4 * j;
    *(__half2*)(g_bagF + o)     = h0;
    *(__half2*)(g_bagF + o + 2) = h1;
}

// ---------------- fused softmax-over-t + word_vec ----------------
__global__ void k_word_attn() {
    int b = blockIdx.x;
    int tid = threadIdx.x;
    __shared__ float sh[TSTEPS];
    __shared__ float al[TSTEPS];
    if (tid < TSTEPS) {
        float v = g_score[tid * BB + b];
        al[tid] = v; sh[tid] = v;
    }
    __syncthreads();
    #pragma unroll
    for (int o = 32; o; o >>= 1) {
        if (tid < o) sh[tid] = fmaxf(sh[tid], sh[tid + o]);
        __syncthreads();
    }
    float mx = sh[0];
    __syncthreads();
    if (tid < TSTEPS) {
        float e = __expf(al[tid] - mx);
        al[tid] = e; sh[tid] = e;
    }
    __syncthreads();
    #pragma unroll
    for (int o = 32; o; o >>= 1) {
        if (tid < o) sh[tid] += sh[tid + o];
        __syncthreads();
    }
    float inv = 1.f / sh[0];
    __syncthreads();
    if (tid < TSTEPS) al[tid] *= inv;
    __syncthreads();

    for (int h = tid; h < H2; h += blockDim.x) {
        float acc = 0.f;
        #pragma unroll 8
        for (int t = 0; t < TSTEPS; t++)
            acc += al[t] * __half2float(g_OUTF[((size_t)t * BB + b) * KPAD_W + h]);
        g_wv[(size_t)b * H2 + h] = acc;
        g_wvF[(size_t)b * KPAD_W + h] = __float2half(acc);
    }
}

// ---------------- sentence softmax + weighted sum + FC + scatter ----------------
__global__ void k_sent(const float* __restrict__ fcW, const float* __restrict__ fcb,
                       const int* __restrict__ pairs, float* __restrict__ out) {
    int nb = blockIdx.x;
    __shared__ float beta[MSENT];
    __shared__ float sv[H2];
    if (threadIdx.x == 0) {
        float v[MSENT], mx = -1e30f;
        #pragma unroll
        for (int s = 0; s < MSENT; s++) { v[s] = g_score2[nb * MSENT + s]; mx = fmaxf(mx, v[s]); }
        float sum = 0.f;
        #pragma unroll
        for (int s = 0; s < MSENT; s++) { v[s] = expf(v[s] - mx); sum += v[s]; }
        #pragma unroll
        for (int s = 0; s < MSENT; s++) beta[s] = v[s] / sum;
    }
    __syncthreads();
    for (int h = threadIdx.x; h < H2; h += blockDim.x) {
        float acc = 0.f;
        #pragma unroll
        for (int s = 0; s < MSENT; s++)
            acc += beta[s] * g_wv[((size_t)(nb * MSENT + s)) * H2 + h];
        sv[h] = acc;
    }
    __syncthreads();
    const int* p = pairs + nb * 3;
    int base = ((p[0] * ENT + p[1]) * ENT + p[2]) * OUTD;
    for (int o = threadIdx.x; o < OUTD; o += blockDim.x) {
        float acc = fcb[o];
        for (int h = 0; h < H2; h++) acc += sv[h] * fcW[(size_t)o * H2 + h];
        out[base + o] = acc;
    }
}

// ---------------- launcher ----------------
extern "C" void kernel_launch(void* const* d_in, const int* in_sizes, int n_in,
                              void* d_out, int out_size) {
    const float* bag       = (const float*)d_in[0];
    const float* W_ih_f    = (const float*)d_in[1];
    const float* W_hh_f    = (const float*)d_in[2];
    const float* b_ih_f    = (const float*)d_in[3];
    const float* b_hh_f    = (const float*)d_in[4];
    const float* W_ih_r    = (const float*)d_in[5];
    const float* W_hh_r    = (const float*)d_in[6];
    const float* b_ih_r    = (const float*)d_in[7];
    const float* b_hh_r    = (const float*)d_in[8];
    const float* W_word    = (const float*)d_in[9];
    const float* b_word    = (const float*)d_in[10];
    const float* proj_word = (const float*)d_in[11];
    const float* W_sent    = (const float*)d_in[12];
    const float* b_sent    = (const float*)d_in[13];
    const float* proj_sent = (const float*)d_in[14];
    const float* fc_W      = (const float*)d_in[15];
    const float* fc_b      = (const float*)d_in[16];
    const int*   pairs     = (const int*)d_in[17];
    float* out = (float*)d_out;

    static bool attr_set = false;
    if (!attr_set) {
        cudaFuncSetAttribute(gemm_f16s, cudaFuncAttributeMaxDynamicSharedMemorySize, SMEM_GEMM1);
        cudaFuncSetAttribute(gemm_gru, cudaFuncAttributeMaxDynamicSharedMemorySize, SMEM_GEMM);
        cudaFuncSetAttribute(gemm_score, cudaFuncAttributeMaxDynamicSharedMemorySize, SMEM_GEMM1);
        attr_set = true;
    }

    #define SYMA(p, s) void* p; cudaGetSymbolAddress(&p, s)
    SYMA(pXG, g_XGh);
    SYMA(pScore, g_score);
    SYMA(pWv, g_wv);
    SYMA(pScore2, g_score2);
    SYMA(pBih, g_bias_ih); SYMA(pBhh, g_bias_hh);
    SYMA(pBagF, g_bagF);
    SYMA(pWihH, g_WihH);
    SYMA(pWhhIH, g_WhhIH); SYMA(pWhhIL, g_WhhIL);
    SYMA(pWwH, g_WwordH);
    SYMA(pWsH, g_WsentH);
    SYMA(pOF, g_OUTF);
    SYMA(phA, g_hA); SYMA(phB, g_hB);
    SYMA(pwvF, g_wvF);
    #undef SYMA

    // ---- prep (3 launches), then input GEMM as launch #4 (ncu capture slot) ----
    k_conv_wih<<<(NIH * IND + 255) / 256, 256>>>(W_ih_f, W_ih_r);                       // 1
    k_conv_rest<<<(CW_TOT + 255) / 256, 256>>>(W_hh_f, W_hh_r, W_word, W_sent,          // 2
                                               b_ih_f, b_ih_r, b_hh_f, b_hh_r);
    {
        long long n = MM * (IND / 4);                                                   // 3
        k_conv_bag<<<(unsigned)((n + 255) / 256), 256>>>(bag);
    }
    {
        dim3 g(NPAD_IH / 128, (unsigned)(MM / 128), 1);                                 // 4
        gemm_f16s<<<g, 512, SMEM_GEMM1>>>(
            (const __half*)pBagF, (const __half*)pWihH,
            (const float*)pBih, (__half*)pXG,
            NIH, NIH, KPAD_IN, KPAD_IN / 64);
    }
    {
        int nw = 2 * BB * KPAD_H / 2;                                                   // 5
        k_zero_h2<<<(nw + 255) / 256, 256>>>((uint32_t*)phA, (uint32_t*)phB, nw);
    }
    k_zero<<<(out_size + 255) / 256, 256>>>(out, (long long)out_size);                  // 6

    // ---- GRU recurrence: one fused launch per step ----
    {
        dim3 g(NI_GRU / 128, BB / 128, 2);   // (8, 32, 2) = 512 blocks
        const __half* hbuf[2] = {(const __half*)phA, (const __half*)phB};
        for (int s = 0; s < TSTEPS; s++) {
            gemm_gru<<<g, 512, SMEM_GEMM>>>(
                hbuf[s & 1],
                (const __half*)pWhhIH, (const __half*)pWhhIL,
                (const float*)pBhh,
                (__half*)(s & 1 ? phA : phB), s);
        }
    }

    // ---- word attention: fused GEMM + tanh.proj score, fused softmax+wv ----
    gemm_score<<<(unsigned)(MM / 128), 512, SMEM_GEMM1>>>(
        (const __half*)pOF, (const __half*)pWwH,
        b_word, proj_word, (float*)pScore, H2, KPAD_W, KPAD_W / 64, NPAD_W / 128);
    k_word_attn<<<BB, 256>>>();

    // ---- sentence attention: fused GEMM + score, then softmax+FC+scatter ----
    gemm_score<<<BB / 128, 512, SMEM_GEMM1>>>(
        (const __half*)pwvF, (const __half*)pWsH,
        b_sent, proj_sent, (float*)pScore2, H2, KPAD_W, KPAD_W / 64, NPAD_W / 128);
    k_sent<<<NBAG, 256>>>(fc_W, fc_b, pairs, out);
}